// round 3
// baseline (speedup 1.0000x reference)
#include <cuda_runtime.h>
#include <math.h>

#define LTOT   1360
#define BATCH  4
#define NROWS  (BATCH*LTOT)          // 5440
#define L2SZ   ((size_t)LTOT*LTOT)

// ---------------- static device scratch (no allocs allowed) ----------------
__device__ float g_t0[BATCH*1024*512];
__device__ float g_c1[BATCH*256*512];
__device__ float g_c2[BATCH*64*512];
__device__ float g_c3[BATCH*16*512];
__device__ float g_pc[BATCH*336*512];
__device__ float g_pyr[BATCH*336*512];
__device__ float g_x[NROWS*512];
__device__ float g_q[NROWS*512];
__device__ float g_k[NROWS*512];
__device__ float g_v[NROWS*512];
__device__ float g_o[NROWS*512];
__device__ float g_fc[NROWS*512];
__device__ float g_tout[NROWS*512];
__device__ float g_sout[NROWS*512];
__device__ float g_xn[NROWS*512];
__device__ float g_h[NROWS*512];
__device__ float g_wc[3*2048*512];
__device__ unsigned char g_tm[L2SZ];
__device__ unsigned char g_sm[(size_t)BATCH*LTOT*LTOT];

// ---------------- temporal mask (1 = masked) ----------------
__global__ void k_build_tmask(unsigned char* tm) {
    int idx = blockIdx.x*blockDim.x + threadIdx.x;
    if (idx >= LTOT*LTOT) return;
    int i = idx / LTOT, j = idx % LTOT;
    const int starts[4] = {0,1024,1280,1344};
    const int sizes[4]  = {1024,256,64,16};
    int li = (i<1024)?0:(i<1280)?1:(i<1344)?2:3;
    int lj = (j<1024)?0:(j<1280)?1:(j<1344)?2:3;
    bool m = false;
    if (li == lj) {
        int d = i - j; if (d >= -2 && d <= 2) m = true;
    } else if (li == lj + 1) {
        int st = starts[li];
        int ls = starts[lj] + (i - st)*4;
        int rs = (i == st + sizes[li] - 1) ? st : starts[lj] + (i - st + 1)*4;
        if (j >= ls && j < rs) m = true;
    } else if (lj == li + 1) {
        int st = starts[lj];
        int ls = starts[li] + (j - st)*4;
        int rs = (j == st + sizes[lj] - 1) ? st : starts[li] + (j - st + 1)*4;
        if (i >= ls && i < rs) m = true;
    }
    tm[idx] = m ? 0 : 1;
}

// ---------------- conv weight re-layout: Wm[l][t*512+ci][co] = W[l][co][ci][t] ----------------
__global__ void k_convw(const float* __restrict__ w, float* __restrict__ wm) {
    int idx = blockIdx.x*blockDim.x + threadIdx.x;
    if (idx >= 3*2048*512) return;
    int l  = idx / (2048*512);
    int r  = idx - l*2048*512;
    int kk = r >> 9, co = r & 511;
    int t  = kk >> 9, ci = kk & 511;
    wm[idx] = w[(((size_t)(l*512 + co))*512 + ci)*4 + t];
}

// ---------------- tiled SGEMM C[M,N]=A[M,K]@B[K,N] (+bias, epilogue) ----------------
// mode: 0 none, 1 relu, 2 scale+elu
__global__ void __launch_bounds__(256) k_sgemm(
        const float* __restrict__ A, const float* __restrict__ Bm,
        float* __restrict__ C, const float* __restrict__ bias,
        int M, int N, int K, int mode) {
    __shared__ float As[64][17];
    __shared__ float Bs[16][64];
    int tid = threadIdx.x;
    int tx = tid & 15, ty = tid >> 4;
    int row0 = blockIdx.y << 6, col0 = blockIdx.x << 6;
    float acc[4][4] = {};
    for (int k0 = 0; k0 < K; k0 += 16) {
        #pragma unroll
        for (int e = tid; e < 1024; e += 256) {
            int m = e >> 4, k = e & 15;
            int r = row0 + m;
            As[m][k] = (r < M) ? A[(size_t)r*K + k0 + k] : 0.f;
        }
        #pragma unroll
        for (int e = tid; e < 1024; e += 256) {
            int k = e >> 6, n = e & 63;
            Bs[k][n] = Bm[(size_t)(k0 + k)*N + col0 + n];
        }
        __syncthreads();
        #pragma unroll
        for (int k = 0; k < 16; k++) {
            float4 b4 = *(const float4*)&Bs[k][tx << 2];
            #pragma unroll
            for (int i = 0; i < 4; i++) {
                float av = As[(ty << 2) + i][k];
                acc[i][0] += av*b4.x; acc[i][1] += av*b4.y;
                acc[i][2] += av*b4.z; acc[i][3] += av*b4.w;
            }
        }
        __syncthreads();
    }
    #pragma unroll
    for (int i = 0; i < 4; i++) {
        int r = row0 + (ty << 2) + i;
        if (r >= M) break;
        float* cp = C + (size_t)r*N + col0 + (tx << 2);
        #pragma unroll
        for (int j = 0; j < 4; j++) {
            float v = acc[i][j];
            if (bias) v += bias[col0 + (tx << 2) + j];
            if (mode == 1) v = fmaxf(v, 0.f);
            else if (mode == 2) {
                v *= 0.9999950000374997f;
                if (v <= 0.f) v = expm1f(v);
            }
            cp[j] = v;
        }
    }
}

// ---------------- block reduce (256 thr) ----------------
__device__ __forceinline__ float block_sum256(float v) {
    __shared__ float red[8];
    int lane = threadIdx.x & 31, w = threadIdx.x >> 5;
    #pragma unroll
    for (int o = 16; o; o >>= 1) v += __shfl_xor_sync(0xffffffffu, v, o);
    if (lane == 0) red[w] = v;
    __syncthreads();
    if (w == 0) {
        float t = (lane < 8) ? red[lane] : 0.f;
        #pragma unroll
        for (int o = 4; o; o >>= 1) t += __shfl_xor_sync(0xffffffffu, t, o);
        if (lane == 0) red[0] = t;
    }
    __syncthreads();
    float r = red[0];
    __syncthreads();
    return r;
}

// ---------------- concat(x_enc, pyr) + LN(eps=1e-5) ----------------
__global__ void __launch_bounds__(256) k_concat_ln(
        const float* __restrict__ xe, const float* __restrict__ pyr,
        const float* __restrict__ g, const float* __restrict__ bt,
        float* __restrict__ out) {
    int row = blockIdx.x;
    int b = row / LTOT, i = row % LTOT;
    const float* src = (i < 1024) ? xe + ((size_t)(b*1024 + i))*512
                                  : pyr + ((size_t)(b*336 + (i - 1024)))*512;
    int t = threadIdx.x;
    float v0 = src[t], v1 = src[t + 256];
    float mu = block_sum256(v0 + v1) * (1.f/512.f);
    float d0 = v0 - mu, d1 = v1 - mu;
    float var = block_sum256(d0*d0 + d1*d1) * (1.f/512.f);
    float rs = rsqrtf(var + 1e-5f);
    float* o = out + (size_t)row*512;
    o[t]       = d0*rs*g[t]       + bt[t];
    o[t + 256] = d1*rs*g[t + 256] + bt[t + 256];
}

// ---------------- (a + res) -> LN ----------------
__global__ void __launch_bounds__(256) k_add_ln(
        const float* __restrict__ a, const float* __restrict__ res,
        const float* __restrict__ g, const float* __restrict__ bt,
        float* __restrict__ out, float eps) {
    int row = blockIdx.x, t = threadIdx.x;
    const float* pa = a + (size_t)row*512;
    const float* pr = res + (size_t)row*512;
    float v0 = pa[t] + pr[t], v1 = pa[t + 256] + pr[t + 256];
    float mu = block_sum256(v0 + v1) * (1.f/512.f);
    float d0 = v0 - mu, d1 = v1 - mu;
    float var = block_sum256(d0*d0 + d1*d1) * (1.f/512.f);
    float rs = rsqrtf(var + eps);
    float* o = out + (size_t)row*512;
    o[t]       = d0*rs*g[t]       + bt[t];
    o[t + 256] = d1*rs*g[t + 256] + bt[t + 256];
}

// ---------------- row L2 normalize ----------------
__global__ void __launch_bounds__(256) k_rownorm(
        const float* __restrict__ x, float* __restrict__ xn) {
    int row = blockIdx.x, t = threadIdx.x;
    const float* p = x + (size_t)row*512;
    float v0 = p[t], v1 = p[t + 256];
    float ss = block_sum256(v0*v0 + v1*v1);
    float inv = 1.f / fmaxf(sqrtf(ss), 1e-8f);
    float* o = xn + (size_t)row*512;
    o[t] = v0*inv; o[t + 256] = v1*inv;
}

__global__ void k_zero16(unsigned char* p, long n16) {
    long i = blockIdx.x*(long)blockDim.x + threadIdx.x;
    if (i < n16) ((int4*)p)[i] = make_int4(0,0,0,0);
}

// ---------------- semantic top-k mask: write 1 (=masked) at top-k positions ----------------
__global__ void __launch_bounds__(256) k_topk(
        const float* __restrict__ xn, unsigned char* __restrict__ smask) {
    int i = blockIdx.x, b = blockIdx.y, tid = threadIdx.x;
    const int starts[4] = {0,1024,1280,1344};
    const int sizes[4]  = {1024,256,64,16};
    int lev = (i<1024)?0:(i<1280)?1:(i<1344)?2:3;
    int st = starts[lev], n = sizes[lev];
    int kk = n < 32 ? n : 32;
    __shared__ float sims[1024];
    __shared__ float qrow[512];
    __shared__ float wv[8]; __shared__ int wi[8];
    const float* xb = xn + (size_t)b*LTOT*512;
    for (int d = tid; d < 512; d += 256) qrow[d] = xb[(size_t)i*512 + d];
    __syncthreads();
    int w = tid >> 5, lane = tid & 31;
    for (int j = w; j < n; j += 8) {
        const float* rj = xb + (size_t)(st + j)*512;
        float p = 0.f;
        #pragma unroll 4
        for (int d = lane; d < 512; d += 32) p += qrow[d]*rj[d];
        #pragma unroll
        for (int o = 16; o; o >>= 1) p += __shfl_xor_sync(0xffffffffu, p, o);
        if (lane == 0) sims[j] = p;
    }
    __syncthreads();
    unsigned char* mrow = smask + ((size_t)b*LTOT + i)*LTOT + st;
    for (int it = 0; it < kk; it++) {
        float bv = -3.f; int bi = n;
        for (int j = tid; j < n; j += 256) {
            float v = sims[j];
            if (v > bv) { bv = v; bi = j; }
        }
        #pragma unroll
        for (int o = 16; o; o >>= 1) {
            float ov = __shfl_xor_sync(0xffffffffu, bv, o);
            int   oi = __shfl_xor_sync(0xffffffffu, bi, o);
            if (ov > bv || (ov == bv && oi < bi)) { bv = ov; bi = oi; }
        }
        if (lane == 0) { wv[w] = bv; wi[w] = bi; }
        __syncthreads();
        if (tid == 0) {
            float fv = wv[0]; int fi = wi[0];
            #pragma unroll
            for (int z = 1; z < 8; z++)
                if (wv[z] > fv || (wv[z] == fv && wi[z] < fi)) { fv = wv[z]; fi = wi[z]; }
            mrow[fi] = 1;
            sims[fi] = -3.f;
        }
        __syncthreads();
    }
}

// ---------------- fused masked attention: 16 queries x 1 head per block ----------------
// mask byte: nonzero = masked (-inf); zero = attend. Applies to BOTH branches.
#define ATT_SMEM ((16*68 + 16*1361 + 64*68)*4)
__global__ void __launch_bounds__(256) k_attn(
        const float* __restrict__ Q, const float* __restrict__ K,
        const float* __restrict__ V, const unsigned char* __restrict__ mask,
        size_t mbstride, float* __restrict__ O) {
    extern __shared__ float smem[];
    float* Qs = smem;                      // [16][68]
    float* Ss = smem + 16*68;              // [16][1361]
    float* Ts = smem + 16*68 + 16*1361;    // [64][68]
    __shared__ float rsum[16];
    int tid = threadIdx.x;
    int b = blockIdx.z, h = blockIdx.y, q0 = blockIdx.x << 4;
    size_t rb = (size_t)b * LTOT;
    const float* Qb = Q + rb*512 + h*64;
    const float* Kb = K + rb*512 + h*64;
    const float* Vb = V + rb*512 + h*64;
    const unsigned char* mb = mask + mbstride*b;
    for (int e = tid; e < 1024; e += 256) {
        int qq = e >> 6, d = e & 63;
        Qs[qq*68 + d] = Qb[(size_t)(q0+qq)*512 + d];
    }
    int a = tid & 7, jj = tid >> 3;
    for (int jt = 0; jt < 22; jt++) {
        int jb = jt*64, jc = min(64, LTOT - jb);
        __syncthreads();
        for (int e = tid; e < (jc << 6); e += 256) {
            int j = e >> 6, d = e & 63;
            Ts[j*68 + d] = Kb[(size_t)(jb+j)*512 + d];
        }
        __syncthreads();
        float s00=0,s01=0,s10=0,s11=0;
        const float *qa = Qs + a*68, *qc = Qs + (a+8)*68;
        const float *ka = Ts + jj*68, *kc = Ts + (jj+32)*68;
        #pragma unroll
        for (int d = 0; d < 64; d += 4) {
            float4 x0 = *(const float4*)(qa+d), x1 = *(const float4*)(qc+d);
            float4 y0 = *(const float4*)(ka+d), y1 = *(const float4*)(kc+d);
            s00 += x0.x*y0.x+x0.y*y0.y+x0.z*y0.z+x0.w*y0.w;
            s01 += x0.x*y1.x+x0.y*y1.y+x0.z*y1.z+x0.w*y1.w;
            s10 += x1.x*y0.x+x1.y*y0.y+x1.z*y0.z+x1.w*y0.w;
            s11 += x1.x*y1.x+x1.y*y1.y+x1.z*y1.z+x1.w*y1.w;
        }
        if (jj < jc) {
            int jg = jb + jj;
            Ss[a*1361+jg]     = mb[(size_t)(q0+a)*LTOT+jg]   ? -1e30f : s00*0.125f;
            Ss[(a+8)*1361+jg] = mb[(size_t)(q0+a+8)*LTOT+jg] ? -1e30f : s10*0.125f;
        }
        if (jj + 32 < jc) {
            int jg = jb + jj + 32;
            Ss[a*1361+jg]     = mb[(size_t)(q0+a)*LTOT+jg]   ? -1e30f : s01*0.125f;
            Ss[(a+8)*1361+jg] = mb[(size_t)(q0+a+8)*LTOT+jg] ? -1e30f : s11*0.125f;
        }
    }
    __syncthreads();
    int w = tid >> 5, lane = tid & 31;
    for (int r = w; r < 16; r += 8) {
        float* row = Ss + r*1361;
        float mx = -1e30f;
        for (int j = lane; j < LTOT; j += 32) mx = fmaxf(mx, row[j]);
        #pragma unroll
        for (int o = 16; o; o >>= 1) mx = fmaxf(mx, __shfl_xor_sync(0xffffffffu, mx, o));
        float sum = 0.f;
        for (int j = lane; j < LTOT; j += 32) {
            float e = expf(row[j] - mx);
            row[j] = e; sum += e;
        }
        #pragma unroll
        for (int o = 16; o; o >>= 1) sum += __shfl_xor_sync(0xffffffffu, sum, o);
        if (lane == 0) rsum[r] = sum;
    }
    __syncthreads();
    int q = tid >> 4, d0 = (tid & 15) << 2;
    float4 acc = make_float4(0,0,0,0);
    for (int jt = 0; jt < 22; jt++) {
        int jb = jt*64, jc = min(64, LTOT - jb);
        __syncthreads();
        for (int e = tid; e < (jc << 6); e += 256) {
            int j = e >> 6, d = e & 63;
            Ts[j*68 + d] = Vb[(size_t)(jb+j)*512 + d];
        }
        __syncthreads();
        const float* prow = Ss + q*1361 + jb;
        for (int j = 0; j < jc; j++) {
            float p = prow[j];
            float4 v4 = *(const float4*)(Ts + j*68 + d0);
            acc.x += p*v4.x; acc.y += p*v4.y; acc.z += p*v4.z; acc.w += p*v4.w;
        }
    }
    float inv = 1.f / rsum[q];
    float4 o4 = make_float4(acc.x*inv, acc.y*inv, acc.z*inv, acc.w*inv);
    *(float4*)(O + (rb + q0 + q)*512 + h*64 + d0) = o4;
}

// ---------------- pyramid concat + combine ----------------
__global__ void k_pyrcat(const float* __restrict__ c1, const float* __restrict__ c2,
                         const float* __restrict__ c3, float* __restrict__ out) {
    int idx = blockIdx.x*blockDim.x + threadIdx.x;
    if (idx >= BATCH*336*512) return;
    int d = idx & 511, r = idx >> 9;
    int b = r / 336, p = r % 336;
    float v;
    if (p < 256) v = c1[((size_t)(b*256 + p) << 9) | d];
    else if (p < 320) v = c2[((size_t)(b*64 + p - 256) << 9) | d];
    else v = c3[((size_t)(b*16 + p - 320) << 9) | d];
    out[idx] = v;
}

__global__ void k_comb(const float* __restrict__ t, const float* __restrict__ s,
                       float* __restrict__ x, int n) {
    int i = blockIdx.x*blockDim.x + threadIdx.x;
    if (i < n) x[i] = (t[i] + s[i] + x[i]) * (1.f/3.f);
}

// ---------------- orchestration ----------------
static void gemm(const float* A, const float* B, float* C, const float* bias,
                 int M, int N, int K, int mode) {
    dim3 g(N/64, (M + 63)/64);
    k_sgemm<<<g, 256>>>(A, B, C, bias, M, N, K, mode);
}

extern "C" void kernel_launch(void* const* d_in, const int* in_sizes, int n_in,
                              void* d_out, int out_size) {
    const float* x_enc  = (const float*)d_in[0];
    const float* down_W = (const float*)d_in[1];
    const float* down_b = (const float*)d_in[2];
    const float* conv_W = (const float*)d_in[3];
    const float* conv_b = (const float*)d_in[4];
    const float* up_W   = (const float*)d_in[5];
    const float* up_b   = (const float*)d_in[6];
    const float* bc_g   = (const float*)d_in[7];
    const float* bc_b   = (const float*)d_in[8];
    const float* Wq     = (const float*)d_in[9];
    const float* Wk     = (const float*)d_in[10];
    const float* Wv     = (const float*)d_in[11];
    const float* fcW    = (const float*)d_in[12];
    const float* fcb    = (const float*)d_in[13];
    const float* aln_g  = (const float*)d_in[14];
    const float* aln_b  = (const float*)d_in[15];
    const float* W1     = (const float*)d_in[16];
    const float* b1     = (const float*)d_in[17];
    const float* W2     = (const float*)d_in[18];
    const float* b2     = (const float*)d_in[19];
    const float* fln_g  = (const float*)d_in[20];
    const float* fln_b  = (const float*)d_in[21];
    float* out = (float*)d_out;

    float *t0,*c1,*c2,*c3,*pc,*pyr,*x,*q,*k,*v,*o,*fc,*tout,*sout,*xn,*h,*wc;
    unsigned char *tm,*smk;
    cudaGetSymbolAddress((void**)&t0,  g_t0);
    cudaGetSymbolAddress((void**)&c1,  g_c1);
    cudaGetSymbolAddress((void**)&c2,  g_c2);
    cudaGetSymbolAddress((void**)&c3,  g_c3);
    cudaGetSymbolAddress((void**)&pc,  g_pc);
    cudaGetSymbolAddress((void**)&pyr, g_pyr);
    cudaGetSymbolAddress((void**)&x,   g_x);
    cudaGetSymbolAddress((void**)&q,   g_q);
    cudaGetSymbolAddress((void**)&k,   g_k);
    cudaGetSymbolAddress((void**)&v,   g_v);
    cudaGetSymbolAddress((void**)&o,   g_o);
    cudaGetSymbolAddress((void**)&fc,  g_fc);
    cudaGetSymbolAddress((void**)&tout,g_tout);
    cudaGetSymbolAddress((void**)&sout,g_sout);
    cudaGetSymbolAddress((void**)&xn,  g_xn);
    cudaGetSymbolAddress((void**)&h,   g_h);
    cudaGetSymbolAddress((void**)&wc,  g_wc);
    cudaGetSymbolAddress((void**)&tm,  g_tm);
    cudaGetSymbolAddress((void**)&smk, g_sm);

    cudaFuncSetAttribute(k_attn, cudaFuncAttributeMaxDynamicSharedMemorySize, ATT_SMEM);

    k_build_tmask<<<(LTOT*LTOT + 255)/256, 256>>>(tm);
    k_convw<<<(3*2048*512 + 255)/256, 256>>>(conv_W, wc);

    // bottleneck
    gemm(x_enc, down_W, t0, down_b, BATCH*1024, 512, 512, 0);
    gemm(t0, wc,              c1, conv_b,        BATCH*256, 512, 2048, 2);
    gemm(c1, wc + 2048*512,   c2, conv_b + 512,  BATCH*64,  512, 2048, 2);
    gemm(c2, wc + 2*2048*512, c3, conv_b + 1024, BATCH*16,  512, 2048, 2);
    k_pyrcat<<<(BATCH*336*512 + 255)/256, 256>>>(c1, c2, c3, pc);
    gemm(pc, up_W, pyr, up_b, BATCH*336, 512, 512, 0);
    k_concat_ln<<<NROWS, 256>>>(x_enc, pyr, bc_g, bc_b, x);

    for (int l = 0; l < 2; l++) {
        // semantic mask from layer-input x
        k_rownorm<<<NROWS, 256>>>(x, xn);
        long n16 = (long)BATCH*LTOT*LTOT/16;
        k_zero16<<<(unsigned)((n16 + 255)/256), 256>>>(smk, n16);
        dim3 tg(LTOT, BATCH);
        k_topk<<<tg, 256>>>(xn, smk);

        for (int s = 0; s < 2; s++) {
            size_t wo = ((size_t)l*2 + s)*512*512;
            size_t lo = ((size_t)l*2 + s)*512;
            gemm(x, Wq + wo, q, nullptr, NROWS, 512, 512, 0);
            gemm(x, Wk + wo, k, nullptr, NROWS, 512, 512, 0);
            gemm(x, Wv + wo, v, nullptr, NROWS, 512, 512, 0);
            dim3 ag(LTOT/16, 8, BATCH);
            if (s == 0) k_attn<<<ag, 256, ATT_SMEM>>>(q, k, v, tm, 0, o);
            else        k_attn<<<ag, 256, ATT_SMEM>>>(q, k, v, smk, L2SZ, o);
            gemm(o, fcW + wo, fc, fcb + lo, NROWS, 512, 512, 0);
            k_add_ln<<<NROWS, 256>>>(fc, x, aln_g + lo, aln_b + lo,
                                     s == 0 ? tout : sout, 1e-6f);
        }
        k_comb<<<(NROWS*512 + 255)/256, 256>>>(tout, sout, x, NROWS*512);

        size_t fo = (size_t)l*512*512, fb = (size_t)l*512;
        gemm(x, W1 + fo, h, b1 + fb, NROWS, 512, 512, 1);
        gemm(h, W2 + fo, fc, b2 + fb, NROWS, 512, 512, 0);
        k_add_ln<<<NROWS, 256>>>(fc, x, fln_g + fb, fln_b + fb,
                                 (l == 0) ? x : out, 1e-6f);
    }
}

// round 4
// speedup vs baseline: 1.6348x; 1.6348x over previous
#include <cuda_runtime.h>
#include <math.h>

#define LTOT   1360
#define BATCH  4
#define NROWS  (BATCH*LTOT)          // 5440
#define L2SZ   ((size_t)LTOT*LTOT)

// ---------------- static device scratch ----------------
__device__ float g_t0[BATCH*1024*512];
__device__ float g_c1[BATCH*256*512];
__device__ float g_c2[BATCH*64*512];
__device__ float g_c3[BATCH*16*512];
__device__ float g_pc[BATCH*336*512];
__device__ float g_pyr[BATCH*336*512];
__device__ float g_x[NROWS*512];
__device__ float g_q[NROWS*512];
__device__ float g_k[NROWS*512];
__device__ float g_v[NROWS*512];
__device__ float g_o[NROWS*512];
__device__ float g_fc[NROWS*512];
__device__ float g_tout[NROWS*512];
__device__ float g_sout[NROWS*512];
__device__ float g_xn[NROWS*512];
__device__ float g_h[NROWS*512];
__device__ float g_wc[3*2048*512];
__device__ unsigned char g_sm[(size_t)BATCH*LTOT*LTOT];

// ---------------- conv weight re-layout ----------------
__global__ void k_convw(const float* __restrict__ w, float* __restrict__ wm) {
    int idx = blockIdx.x*blockDim.x + threadIdx.x;
    if (idx >= 3*2048*512) return;
    int l  = idx / (2048*512);
    int r  = idx - l*2048*512;
    int kk = r >> 9, co = r & 511;
    int t  = kk >> 9, ci = kk & 511;
    wm[idx] = w[(((size_t)(l*512 + co))*512 + ci)*4 + t];
}

// ---------------- SGEMM: 128x64 tile, 8x4 per thread ----------------
// mode: 0 none, 1 relu, 2 scale+elu
__global__ void __launch_bounds__(256) k_sgemm(
        const float* __restrict__ A, const float* __restrict__ Bm,
        float* __restrict__ C, const float* __restrict__ bias,
        int M, int N, int K, int mode) {
    __shared__ float As[16*136];   // k-major: As[k][r], pitch 136
    __shared__ float Bs[16*64];    // Bs[k][n]
    int tid = threadIdx.x;
    int tx = tid & 15, ty = tid >> 4;
    int row0 = blockIdx.y << 7, col0 = blockIdx.x << 6;
    float acc[8][4] = {};
    for (int k0 = 0; k0 < K; k0 += 16) {
        #pragma unroll
        for (int s = 0; s < 2; s++) {
            int slot = tid*2 + s;
            int r = slot >> 2, kq = (slot & 3) << 2;
            int gr = row0 + r;
            float4 av = make_float4(0.f,0.f,0.f,0.f);
            if (gr < M) av = *(const float4*)&A[(size_t)gr*K + k0 + kq];
            As[(kq+0)*136 + r] = av.x;
            As[(kq+1)*136 + r] = av.y;
            As[(kq+2)*136 + r] = av.z;
            As[(kq+3)*136 + r] = av.w;
        }
        {
            int kb = tid >> 4, nq = (tid & 15) << 2;
            *(float4*)&Bs[kb*64 + nq] =
                *(const float4*)&Bm[(size_t)(k0 + kb)*N + col0 + nq];
        }
        __syncthreads();
        #pragma unroll
        for (int kk = 0; kk < 16; kk++) {
            float4 b4 = *(const float4*)&Bs[kk*64 + (tx<<2)];
            float4 a0 = *(const float4*)&As[kk*136 + (ty<<3)];
            float4 a1 = *(const float4*)&As[kk*136 + (ty<<3) + 4];
            acc[0][0]+=a0.x*b4.x; acc[0][1]+=a0.x*b4.y; acc[0][2]+=a0.x*b4.z; acc[0][3]+=a0.x*b4.w;
            acc[1][0]+=a0.y*b4.x; acc[1][1]+=a0.y*b4.y; acc[1][2]+=a0.y*b4.z; acc[1][3]+=a0.y*b4.w;
            acc[2][0]+=a0.z*b4.x; acc[2][1]+=a0.z*b4.y; acc[2][2]+=a0.z*b4.z; acc[2][3]+=a0.z*b4.w;
            acc[3][0]+=a0.w*b4.x; acc[3][1]+=a0.w*b4.y; acc[3][2]+=a0.w*b4.z; acc[3][3]+=a0.w*b4.w;
            acc[4][0]+=a1.x*b4.x; acc[4][1]+=a1.x*b4.y; acc[4][2]+=a1.x*b4.z; acc[4][3]+=a1.x*b4.w;
            acc[5][0]+=a1.y*b4.x; acc[5][1]+=a1.y*b4.y; acc[5][2]+=a1.y*b4.z; acc[5][3]+=a1.y*b4.w;
            acc[6][0]+=a1.z*b4.x; acc[6][1]+=a1.z*b4.y; acc[6][2]+=a1.z*b4.z; acc[6][3]+=a1.z*b4.w;
            acc[7][0]+=a1.w*b4.x; acc[7][1]+=a1.w*b4.y; acc[7][2]+=a1.w*b4.z; acc[7][3]+=a1.w*b4.w;
        }
        __syncthreads();
    }
    float4 bv = make_float4(0.f,0.f,0.f,0.f);
    if (bias) bv = *(const float4*)&bias[col0 + (tx<<2)];
    #pragma unroll
    for (int ii = 0; ii < 8; ii++) {
        int r = row0 + (ty<<3) + ii;
        if (r >= M) break;
        float v[4] = {acc[ii][0]+bv.x, acc[ii][1]+bv.y, acc[ii][2]+bv.z, acc[ii][3]+bv.w};
        #pragma unroll
        for (int j = 0; j < 4; j++) {
            if (mode == 1) v[j] = fmaxf(v[j], 0.f);
            else if (mode == 2) {
                v[j] *= 0.9999950000374997f;
                if (v[j] <= 0.f) v[j] = expm1f(v[j]);
            }
        }
        *(float4*)&C[(size_t)r*N + col0 + (tx<<2)] = make_float4(v[0],v[1],v[2],v[3]);
    }
}

// ---------------- block reduce (256 thr) ----------------
__device__ __forceinline__ float block_sum256(float v) {
    __shared__ float red[8];
    int lane = threadIdx.x & 31, w = threadIdx.x >> 5;
    #pragma unroll
    for (int o = 16; o; o >>= 1) v += __shfl_xor_sync(0xffffffffu, v, o);
    if (lane == 0) red[w] = v;
    __syncthreads();
    if (w == 0) {
        float t = (lane < 8) ? red[lane] : 0.f;
        #pragma unroll
        for (int o = 4; o; o >>= 1) t += __shfl_xor_sync(0xffffffffu, t, o);
        if (lane == 0) red[0] = t;
    }
    __syncthreads();
    float r = red[0];
    __syncthreads();
    return r;
}

// ---------------- concat(x_enc, pyr) + LN(1e-5) ----------------
__global__ void __launch_bounds__(256) k_concat_ln(
        const float* __restrict__ xe, const float* __restrict__ pyr,
        const float* __restrict__ g, const float* __restrict__ bt,
        float* __restrict__ out) {
    int row = blockIdx.x;
    int b = row / LTOT, i = row % LTOT;
    const float* src = (i < 1024) ? xe + ((size_t)(b*1024 + i))*512
                                  : pyr + ((size_t)(b*336 + (i - 1024)))*512;
    int t = threadIdx.x;
    float v0 = src[t], v1 = src[t + 256];
    float mu = block_sum256(v0 + v1) * (1.f/512.f);
    float d0 = v0 - mu, d1 = v1 - mu;
    float var = block_sum256(d0*d0 + d1*d1) * (1.f/512.f);
    float rs = rsqrtf(var + 1e-5f);
    float* o = out + (size_t)row*512;
    o[t]       = d0*rs*g[t]       + bt[t];
    o[t + 256] = d1*rs*g[t + 256] + bt[t + 256];
}

// ---------------- (a + res) -> LN ----------------
__global__ void __launch_bounds__(256) k_add_ln(
        const float* __restrict__ a, const float* __restrict__ res,
        const float* __restrict__ g, const float* __restrict__ bt,
        float* __restrict__ out, float eps) {
    int row = blockIdx.x, t = threadIdx.x;
    const float* pa = a + (size_t)row*512;
    const float* pr = res + (size_t)row*512;
    float v0 = pa[t] + pr[t], v1 = pa[t + 256] + pr[t + 256];
    float mu = block_sum256(v0 + v1) * (1.f/512.f);
    float d0 = v0 - mu, d1 = v1 - mu;
    float var = block_sum256(d0*d0 + d1*d1) * (1.f/512.f);
    float rs = rsqrtf(var + eps);
    float* o = out + (size_t)row*512;
    o[t]       = d0*rs*g[t]       + bt[t];
    o[t + 256] = d1*rs*g[t + 256] + bt[t + 256];
}

// ---------------- row L2 normalize ----------------
__global__ void __launch_bounds__(256) k_rownorm(
        const float* __restrict__ x, float* __restrict__ xn) {
    int row = blockIdx.x, t = threadIdx.x;
    const float* p = x + (size_t)row*512;
    float v0 = p[t], v1 = p[t + 256];
    float ss = block_sum256(v0*v0 + v1*v1);
    float inv = 1.f / fmaxf(sqrtf(ss), 1e-8f);
    float* o = xn + (size_t)row*512;
    o[t] = v0*inv; o[t + 256] = v1*inv;
}

__global__ void k_zero16(unsigned char* p, long n16) {
    long i = blockIdx.x*(long)blockDim.x + threadIdx.x;
    if (i < n16) ((int4*)p)[i] = make_int4(0,0,0,0);
}

// ---------------- semantic top-k mask: 1 (=masked) at top-k positions ----------------
__global__ void __launch_bounds__(256) k_topk(
        const float* __restrict__ xn, unsigned char* __restrict__ smask) {
    int i = blockIdx.x, b = blockIdx.y, tid = threadIdx.x;
    const int starts[4] = {0,1024,1280,1344};
    const int sizes[4]  = {1024,256,64,16};
    int lev = (i<1024)?0:(i<1280)?1:(i<1344)?2:3;
    int st = starts[lev], n = sizes[lev];
    int kk = n < 32 ? n : 32;
    __shared__ float sims[1024];
    __shared__ float qrow[512];
    __shared__ float wv[8]; __shared__ int wi[8];
    const float* xb = xn + (size_t)b*LTOT*512;
    for (int d = tid; d < 512; d += 256) qrow[d] = xb[(size_t)i*512 + d];
    __syncthreads();
    int w = tid >> 5, lane = tid & 31;
    for (int j = w; j < n; j += 8) {
        const float* rj = xb + (size_t)(st + j)*512;
        float p = 0.f;
        #pragma unroll 4
        for (int d = lane; d < 512; d += 32) p += qrow[d]*rj[d];
        #pragma unroll
        for (int o = 16; o; o >>= 1) p += __shfl_xor_sync(0xffffffffu, p, o);
        if (lane == 0) sims[j] = p;
    }
    __syncthreads();
    unsigned char* mrow = smask + ((size_t)b*LTOT + i)*LTOT + st;
    for (int it = 0; it < kk; it++) {
        float bv = -3.f; int bi = n;
        for (int j = tid; j < n; j += 256) {
            float v = sims[j];
            if (v > bv) { bv = v; bi = j; }
        }
        #pragma unroll
        for (int o = 16; o; o >>= 1) {
            float ov = __shfl_xor_sync(0xffffffffu, bv, o);
            int   oi = __shfl_xor_sync(0xffffffffu, bi, o);
            if (ov > bv || (ov == bv && oi < bi)) { bv = ov; bi = oi; }
        }
        if (lane == 0) { wv[w] = bv; wi[w] = bi; }
        __syncthreads();
        if (tid == 0) {
            float fv = wv[0]; int fi = wi[0];
            #pragma unroll
            for (int z = 1; z < 8; z++)
                if (wv[z] > fv || (wv[z] == fv && wi[z] < fi)) { fv = wv[z]; fi = wi[z]; }
            mrow[fi] = 1;
            sims[fi] = -3.f;
        }
        __syncthreads();
    }
}

// ---------------- SPARSE temporal attention: block per (query, batch) ----------------
// tmask attends only where m==1: same-level window +-2, 4 children, 1 parent (<=10 keys)
__global__ void __launch_bounds__(256) k_tattn(
        const float* __restrict__ Q, const float* __restrict__ K,
        const float* __restrict__ V, float* __restrict__ O) {
    int i = blockIdx.x, b = blockIdx.y;
    int h = threadIdx.x >> 5, lane = threadIdx.x & 31;
    const int starts[4] = {0,1024,1280,1344};
    const int sizes[4]  = {1024,256,64,16};
    int lev = (i<1024)?0:(i<1280)?1:(i<1344)?2:3;
    int st = starts[lev], n = sizes[lev];
    int nb[10]; int cnt = 0;
    int lo = (i-2 < st) ? st : i-2;
    int hi = (i+2 > st+n-1) ? st+n-1 : i+2;
    for (int j = lo; j <= hi; j++) nb[cnt++] = j;
    if (lev > 0) {
        int c0 = starts[lev-1] + (i - st)*4;
        nb[cnt++] = c0; nb[cnt++] = c0+1; nb[cnt++] = c0+2; nb[cnt++] = c0+3;
    }
    if (lev < 3) nb[cnt++] = starts[lev+1] + (i - st)/4;

    size_t rowb = (size_t)(b*LTOT);
    const float2 qv = *(const float2*)(Q + (rowb + i)*512 + h*64 + lane*2);
    float sc[10];
    #pragma unroll
    for (int t = 0; t < 10; t++) {
        if (t < cnt) {
            float2 kv = *(const float2*)(K + (rowb + nb[t])*512 + h*64 + lane*2);
            float p = qv.x*kv.x + qv.y*kv.y;
            #pragma unroll
            for (int o = 16; o; o >>= 1) p += __shfl_xor_sync(0xffffffffu, p, o);
            sc[t] = p * 0.125f;
        } else sc[t] = -1e30f;
    }
    float mx = -1e30f;
    #pragma unroll
    for (int t = 0; t < 10; t++) mx = fmaxf(mx, sc[t]);
    float ssum = 0.f;
    #pragma unroll
    for (int t = 0; t < 10; t++) {
        sc[t] = (t < cnt) ? expf(sc[t] - mx) : 0.f;
        ssum += sc[t];
    }
    float inv = 1.f / ssum;
    float ax = 0.f, ay = 0.f;
    #pragma unroll
    for (int t = 0; t < 10; t++) {
        if (t < cnt) {
            float2 vv = *(const float2*)(V + (rowb + nb[t])*512 + h*64 + lane*2);
            ax += sc[t]*vv.x; ay += sc[t]*vv.y;
        }
    }
    *(float2*)(O + (rowb + i)*512 + h*64 + lane*2) = make_float2(ax*inv, ay*inv);
}

// ---------------- DENSE semantic attention: 16 q x 1 head per block ----------------
// smem: Qs[16][68] | Ss[16][1361] | Ts (shared by TsK[64][268] and TsV[256][68])
#define TSK_PITCH 268
#define ATT_SMEM ((16*68 + 16*1361 + 256*68)*4)   // 161,088 B
__global__ void __launch_bounds__(256) k_sattn(
        const float* __restrict__ Q, const float* __restrict__ K,
        const float* __restrict__ V, const unsigned char* __restrict__ mask,
        float* __restrict__ O) {
    extern __shared__ float smem[];
    float* Qs = smem;                      // [16][68]
    float* Ss = smem + 16*68;              // [16][1361]
    float* Ts = smem + 16*68 + 16*1361;    // scratch region
    __shared__ float rsum[16];
    int tid = threadIdx.x;
    int b = blockIdx.z, h = blockIdx.y, q0 = blockIdx.x << 4;
    size_t rb = (size_t)b * LTOT;
    const float* Qb = Q + rb*512 + h*64;
    const float* Kb = K + rb*512 + h*64;
    const float* Vb = V + rb*512 + h*64;
    const unsigned char* mb = mask + L2SZ*b;

    {   // Qs load: 256 float4 slots
        int qq = tid >> 4, d4 = (tid & 15) << 2;
        *(float4*)&Qs[qq*68 + d4] = *(const float4*)&Qb[(size_t)(q0+qq)*512 + d4];
    }
    // ---- pass 1: scores (tiles of 256 keys, K staged d-major) ----
    int qt = tid & 3, kt = tid >> 2;   // 4 q each, 4 k each
    for (int jt = 0; jt < 6; jt++) {
        int jb = jt << 8;
        int jc = LTOT - jb; if (jc > 256) jc = 256;
        __syncthreads();
        for (int slot = tid; slot < (jc << 4); slot += 256) {
            int j = slot >> 4, d4 = (slot & 15) << 2;
            float4 kv = *(const float4*)&Kb[(size_t)(jb+j)*512 + d4];
            Ts[(d4+0)*TSK_PITCH + j] = kv.x;
            Ts[(d4+1)*TSK_PITCH + j] = kv.y;
            Ts[(d4+2)*TSK_PITCH + j] = kv.z;
            Ts[(d4+3)*TSK_PITCH + j] = kv.w;
        }
        __syncthreads();
        float s[4][4] = {};
        #pragma unroll 8
        for (int d = 0; d < 64; d++) {
            float4 kv = *(const float4*)&Ts[d*TSK_PITCH + (kt<<2)];
            float q0v = Qs[(qt*4+0)*68 + d];
            float q1v = Qs[(qt*4+1)*68 + d];
            float q2v = Qs[(qt*4+2)*68 + d];
            float q3v = Qs[(qt*4+3)*68 + d];
            s[0][0]+=q0v*kv.x; s[0][1]+=q0v*kv.y; s[0][2]+=q0v*kv.z; s[0][3]+=q0v*kv.w;
            s[1][0]+=q1v*kv.x; s[1][1]+=q1v*kv.y; s[1][2]+=q1v*kv.z; s[1][3]+=q1v*kv.w;
            s[2][0]+=q2v*kv.x; s[2][1]+=q2v*kv.y; s[2][2]+=q2v*kv.z; s[2][3]+=q2v*kv.w;
            s[3][0]+=q3v*kv.x; s[3][1]+=q3v*kv.y; s[3][2]+=q3v*kv.z; s[3][3]+=q3v*kv.w;
        }
        #pragma unroll
        for (int u = 0; u < 4; u++) {
            int q = qt*4 + u;
            const unsigned char* mrow = mb + (size_t)(q0+q)*LTOT;
            float* srow = Ss + q*1361;
            #pragma unroll
            for (int w = 0; w < 4; w++) {
                int jl = (kt<<2) + w;
                if (jl < jc) {
                    int jg = jb + jl;
                    srow[jg] = mrow[jg] ? -1e30f : s[u][w]*0.125f;
                }
            }
        }
    }
    __syncthreads();
    // ---- softmax (unnormalized exp; sums in rsum) ----
    {
        int w = tid >> 5, lane = tid & 31;
        for (int r = w; r < 16; r += 8) {
            float* row = Ss + r*1361;
            float mx = -1e30f;
            for (int j = lane; j < LTOT; j += 32) mx = fmaxf(mx, row[j]);
            #pragma unroll
            for (int o = 16; o; o >>= 1) mx = fmaxf(mx, __shfl_xor_sync(0xffffffffu, mx, o));
            float sum = 0.f;
            for (int j = lane; j < LTOT; j += 32) {
                float e = expf(row[j] - mx);
                row[j] = e; sum += e;
            }
            #pragma unroll
            for (int o = 16; o; o >>= 1) sum += __shfl_xor_sync(0xffffffffu, sum, o);
            if (lane == 0) rsum[r] = sum;
        }
    }
    // ---- pass 2: PV, 4-way j-split, V staged j-major ----
    int rep = tid >> 6;           // 0..3
    int qt2 = (tid >> 4) & 3;     // q = qt2*4+u
    int dt  = tid & 15;           // d4 = dt*4
    float4 acc[4] = {};
    for (int jt = 0; jt < 6; jt++) {
        int jb = jt << 8;
        int jc = LTOT - jb; if (jc > 256) jc = 256;
        __syncthreads();
        for (int slot = tid; slot < (jc << 4); slot += 256) {
            int j = slot >> 4, d4 = (slot & 15) << 2;
            *(float4*)&Ts[j*68 + d4] = *(const float4*)&Vb[(size_t)(jb+j)*512 + d4];
        }
        __syncthreads();
        int j0 = rep << 6;
        int j1 = j0 + 64; if (j1 > jc) j1 = jc;
        const float* p0r = Ss + (qt2*4+0)*1361 + jb;
        const float* p1r = Ss + (qt2*4+1)*1361 + jb;
        const float* p2r = Ss + (qt2*4+2)*1361 + jb;
        const float* p3r = Ss + (qt2*4+3)*1361 + jb;
        for (int j = j0; j < j1; j++) {
            float4 v4 = *(const float4*)&Ts[j*68 + (dt<<2)];
            float p0 = p0r[j], p1 = p1r[j], p2 = p2r[j], p3 = p3r[j];
            acc[0].x+=p0*v4.x; acc[0].y+=p0*v4.y; acc[0].z+=p0*v4.z; acc[0].w+=p0*v4.w;
            acc[1].x+=p1*v4.x; acc[1].y+=p1*v4.y; acc[1].z+=p1*v4.z; acc[1].w+=p1*v4.w;
            acc[2].x+=p2*v4.x; acc[2].y+=p2*v4.y; acc[2].z+=p2*v4.z; acc[2].w+=p2*v4.w;
            acc[3].x+=p3*v4.x; acc[3].y+=p3*v4.y; acc[3].z+=p3*v4.z; acc[3].w+=p3*v4.w;
        }
    }
    __syncthreads();
    #pragma unroll
    for (int u = 0; u < 4; u++) {
        int q = qt2*4 + u;
        *(float4*)&Ts[((rep*16 + q)*64) + (dt<<2)] = acc[u];
    }
    __syncthreads();
    {
        int q = tid >> 4, d4 = (tid & 15) << 2;
        float4 r0 = *(const float4*)&Ts[(0*16+q)*64 + d4];
        float4 r1 = *(const float4*)&Ts[(1*16+q)*64 + d4];
        float4 r2 = *(const float4*)&Ts[(2*16+q)*64 + d4];
        float4 r3 = *(const float4*)&Ts[(3*16+q)*64 + d4];
        float inv = 1.f / rsum[q];
        float4 o4 = make_float4((r0.x+r1.x+r2.x+r3.x)*inv, (r0.y+r1.y+r2.y+r3.y)*inv,
                                (r0.z+r1.z+r2.z+r3.z)*inv, (r0.w+r1.w+r2.w+r3.w)*inv);
        *(float4*)(O + (rb + q0 + q)*512 + h*64 + d4) = o4;
    }
}

// ---------------- pyramid concat + combine ----------------
__global__ void k_pyrcat(const float* __restrict__ c1, const float* __restrict__ c2,
                         const float* __restrict__ c3, float* __restrict__ out) {
    int idx = blockIdx.x*blockDim.x + threadIdx.x;
    if (idx >= BATCH*336*512) return;
    int d = idx & 511, r = idx >> 9;
    int b = r / 336, p = r % 336;
    float v;
    if (p < 256) v = c1[((size_t)(b*256 + p) << 9) | d];
    else if (p < 320) v = c2[((size_t)(b*64 + p - 256) << 9) | d];
    else v = c3[((size_t)(b*16 + p - 320) << 9) | d];
    out[idx] = v;
}

__global__ void k_comb(const float* __restrict__ t, const float* __restrict__ s,
                       float* __restrict__ x, int n) {
    int i = blockIdx.x*blockDim.x + threadIdx.x;
    if (i < n) x[i] = (t[i] + s[i] + x[i]) * (1.f/3.f);
}

// ---------------- orchestration ----------------
static void gemm(const float* A, const float* B, float* C, const float* bias,
                 int M, int N, int K, int mode) {
    dim3 g(N/64, (M + 127)/128);
    k_sgemm<<<g, 256>>>(A, B, C, bias, M, N, K, mode);
}

extern "C" void kernel_launch(void* const* d_in, const int* in_sizes, int n_in,
                              void* d_out, int out_size) {
    const float* x_enc  = (const float*)d_in[0];
    const float* down_W = (const float*)d_in[1];
    const float* down_b = (const float*)d_in[2];
    const float* conv_W = (const float*)d_in[3];
    const float* conv_b = (const float*)d_in[4];
    const float* up_W   = (const float*)d_in[5];
    const float* up_b   = (const float*)d_in[6];
    const float* bc_g   = (const float*)d_in[7];
    const float* bc_b   = (const float*)d_in[8];
    const float* Wq     = (const float*)d_in[9];
    const float* Wk     = (const float*)d_in[10];
    const float* Wv     = (const float*)d_in[11];
    const float* fcW    = (const float*)d_in[12];
    const float* fcb    = (const float*)d_in[13];
    const float* aln_g  = (const float*)d_in[14];
    const float* aln_b  = (const float*)d_in[15];
    const float* W1     = (const float*)d_in[16];
    const float* b1     = (const float*)d_in[17];
    const float* W2     = (const float*)d_in[18];
    const float* b2     = (const float*)d_in[19];
    const float* fln_g  = (const float*)d_in[20];
    const float* fln_b  = (const float*)d_in[21];
    float* out = (float*)d_out;

    float *t0,*c1,*c2,*c3,*pc,*pyr,*x,*q,*k,*v,*o,*fc,*tout,*sout,*xn,*h,*wc;
    unsigned char *smk;
    cudaGetSymbolAddress((void**)&t0,  g_t0);
    cudaGetSymbolAddress((void**)&c1,  g_c1);
    cudaGetSymbolAddress((void**)&c2,  g_c2);
    cudaGetSymbolAddress((void**)&c3,  g_c3);
    cudaGetSymbolAddress((void**)&pc,  g_pc);
    cudaGetSymbolAddress((void**)&pyr, g_pyr);
    cudaGetSymbolAddress((void**)&x,   g_x);
    cudaGetSymbolAddress((void**)&q,   g_q);
    cudaGetSymbolAddress((void**)&k,   g_k);
    cudaGetSymbolAddress((void**)&v,   g_v);
    cudaGetSymbolAddress((void**)&o,   g_o);
    cudaGetSymbolAddress((void**)&fc,  g_fc);
    cudaGetSymbolAddress((void**)&tout,g_tout);
    cudaGetSymbolAddress((void**)&sout,g_sout);
    cudaGetSymbolAddress((void**)&xn,  g_xn);
    cudaGetSymbolAddress((void**)&h,   g_h);
    cudaGetSymbolAddress((void**)&wc,  g_wc);
    cudaGetSymbolAddress((void**)&smk, g_sm);

    cudaFuncSetAttribute(k_sattn, cudaFuncAttributeMaxDynamicSharedMemorySize, ATT_SMEM);

    k_convw<<<(3*2048*512 + 255)/256, 256>>>(conv_W, wc);

    // bottleneck
    gemm(x_enc, down_W, t0, down_b, BATCH*1024, 512, 512, 0);
    gemm(t0, wc,              c1, conv_b,        BATCH*256, 512, 2048, 2);
    gemm(c1, wc + 2048*512,   c2, conv_b + 512,  BATCH*64,  512, 2048, 2);
    gemm(c2, wc + 2*2048*512, c3, conv_b + 1024, BATCH*16,  512, 2048, 2);
    k_pyrcat<<<(BATCH*336*512 + 255)/256, 256>>>(c1, c2, c3, pc);
    gemm(pc, up_W, pyr, up_b, BATCH*336, 512, 512, 0);
    k_concat_ln<<<NROWS, 256>>>(x_enc, pyr, bc_g, bc_b, x);

    for (int l = 0; l < 2; l++) {
        // semantic mask from layer-input x
        k_rownorm<<<NROWS, 256>>>(x, xn);
        long n16 = (long)BATCH*LTOT*LTOT/16;
        k_zero16<<<(unsigned)((n16 + 255)/256), 256>>>(smk, n16);
        dim3 tg(LTOT, BATCH);
        k_topk<<<tg, 256>>>(xn, smk);

        for (int s = 0; s < 2; s++) {
            size_t wo = ((size_t)l*2 + s)*512*512;
            size_t lo = ((size_t)l*2 + s)*512;
            gemm(x, Wq + wo, q, nullptr, NROWS, 512, 512, 0);
            gemm(x, Wk + wo, k, nullptr, NROWS, 512, 512, 0);
            gemm(x, Wv + wo, v, nullptr, NROWS, 512, 512, 0);
            if (s == 0) {
                dim3 sg(LTOT, BATCH);
                k_tattn<<<sg, 256>>>(q, k, v, o);
            } else {
                dim3 ag(LTOT/16, 8, BATCH);
                k_sattn<<<ag, 256, ATT_SMEM>>>(q, k, v, smk, o);
            }
            gemm(o, fcW + wo, fc, fcb + lo, NROWS, 512, 512, 0);
            k_add_ln<<<NROWS, 256>>>(fc, x, aln_g + lo, aln_b + lo,
                                     s == 0 ? tout : sout, 1e-6f);
        }
        k_comb<<<(NROWS*512 + 255)/256, 256>>>(tout, sout, x, NROWS*512);

        size_t fo = (size_t)l*512*512, fb = (size_t)l*512;
        gemm(x, W1 + fo, h, b1 + fb, NROWS, 512, 512, 1);
        gemm(h, W2 + fo, fc, b2 + fb, NROWS, 512, 512, 0);
        k_add_ln<<<NROWS, 256>>>(fc, x, fln_g + fb, fln_b + fb,
                                 (l == 0) ? x : out, 1e-6f);
    }
}

// round 5
// speedup vs baseline: 1.8133x; 1.1092x over previous
#include <cuda_runtime.h>
#include <math.h>

#define LTOT   1360
#define BATCH  4
#define NROWS  (BATCH*LTOT)          // 5440
#define L2SZ   ((size_t)LTOT*LTOT)

// ---------------- static device scratch ----------------
__device__ float g_t0[BATCH*1024*512];
__device__ float g_c1[BATCH*256*512];
__device__ float g_c2[BATCH*64*512];
__device__ float g_c3[BATCH*16*512];
__device__ float g_pc[BATCH*336*512];
__device__ float g_pyr[BATCH*336*512];
__device__ float g_x[NROWS*512];
__device__ float g_q[NROWS*512];
__device__ float g_k[NROWS*512];
__device__ float g_v[NROWS*512];
__device__ float g_o[NROWS*512];
__device__ float g_fc[NROWS*512];
__device__ float g_tout[NROWS*512];
__device__ float g_sout[NROWS*512];
__device__ float g_xn[NROWS*512];
__device__ float g_h[NROWS*512];
__device__ float g_wc[3*2048*512];
__device__ float g_part[4*1024*512];     // split-K partials (max M=1024)
__device__ unsigned char g_sm[(size_t)BATCH*LTOT*LTOT];

// ---------------- conv weight re-layout ----------------
__global__ void k_convw(const float* __restrict__ w, float* __restrict__ wm) {
    int idx = blockIdx.x*blockDim.x + threadIdx.x;
    if (idx >= 3*2048*512) return;
    int l  = idx / (2048*512);
    int r  = idx - l*2048*512;
    int kk = r >> 9, co = r & 511;
    int t  = kk >> 9, ci = kk & 511;
    wm[idx] = w[(((size_t)(l*512 + co))*512 + ci)*4 + t];
}

// ---------------- double-buffered SGEMM body: 128x64 tile, 8x4/thread ----------------
// mode: 0 none, 1 relu, 2 scale+elu
__device__ __forceinline__ void sgemm_body(
        const float* __restrict__ A, const float* __restrict__ Bm,
        float* __restrict__ C, const float* __restrict__ bias,
        int M, int N, int K, int lda, int mode) {
    __shared__ float As[2][16*136];   // k-major: As[k][r]
    __shared__ float Bs[2][16*64];
    int tid = threadIdx.x;
    int tx = tid & 15, ty = tid >> 4;
    int row0 = blockIdx.y << 7, col0 = blockIdx.x << 6;
    int lr = tid >> 1;                 // A loader row (0..127)
    int lk = (tid & 1) << 3;           // A loader k offset (0 or 8)
    int bk = tid >> 4, bn = (tid & 15) << 2;  // B loader
    int KT = K >> 4;
    float acc[8][4] = {};
    float4 a0, a1, bb;
    {   // preload tile 0
        int gr = row0 + lr;
        a0 = make_float4(0.f,0.f,0.f,0.f); a1 = a0;
        if (gr < M) {
            const float* p = &A[(size_t)gr*lda + lk];
            a0 = *(const float4*)p; a1 = *(const float4*)(p+4);
        }
        bb = *(const float4*)&Bm[(size_t)bk*N + col0 + bn];
        As[0][(lk+0)*136+lr]=a0.x; As[0][(lk+1)*136+lr]=a0.y;
        As[0][(lk+2)*136+lr]=a0.z; As[0][(lk+3)*136+lr]=a0.w;
        As[0][(lk+4)*136+lr]=a1.x; As[0][(lk+5)*136+lr]=a1.y;
        As[0][(lk+6)*136+lr]=a1.z; As[0][(lk+7)*136+lr]=a1.w;
        *(float4*)&Bs[0][bk*64 + bn] = bb;
    }
    __syncthreads();
    int buf = 0;
    for (int kt = 0; kt < KT; kt++) {
        bool more = (kt + 1 < KT);
        if (more) {
            int gr = row0 + lr;
            a0 = make_float4(0.f,0.f,0.f,0.f); a1 = a0;
            if (gr < M) {
                const float* p = &A[(size_t)gr*lda + ((kt+1)<<4) + lk];
                a0 = *(const float4*)p; a1 = *(const float4*)(p+4);
            }
            bb = *(const float4*)&Bm[(size_t)(((kt+1)<<4) + bk)*N + col0 + bn];
        }
        const float* Ab = As[buf];
        const float* Bb = Bs[buf];
        #pragma unroll
        for (int kk = 0; kk < 16; kk++) {
            float4 b4 = *(const float4*)&Bb[kk*64 + (tx<<2)];
            float4 r0 = *(const float4*)&Ab[kk*136 + (ty<<3)];
            float4 r1 = *(const float4*)&Ab[kk*136 + (ty<<3) + 4];
            acc[0][0]+=r0.x*b4.x; acc[0][1]+=r0.x*b4.y; acc[0][2]+=r0.x*b4.z; acc[0][3]+=r0.x*b4.w;
            acc[1][0]+=r0.y*b4.x; acc[1][1]+=r0.y*b4.y; acc[1][2]+=r0.y*b4.z; acc[1][3]+=r0.y*b4.w;
            acc[2][0]+=r0.z*b4.x; acc[2][1]+=r0.z*b4.y; acc[2][2]+=r0.z*b4.z; acc[2][3]+=r0.z*b4.w;
            acc[3][0]+=r0.w*b4.x; acc[3][1]+=r0.w*b4.y; acc[3][2]+=r0.w*b4.z; acc[3][3]+=r0.w*b4.w;
            acc[4][0]+=r1.x*b4.x; acc[4][1]+=r1.x*b4.y; acc[4][2]+=r1.x*b4.z; acc[4][3]+=r1.x*b4.w;
            acc[5][0]+=r1.y*b4.x; acc[5][1]+=r1.y*b4.y; acc[5][2]+=r1.y*b4.z; acc[5][3]+=r1.y*b4.w;
            acc[6][0]+=r1.z*b4.x; acc[6][1]+=r1.z*b4.y; acc[6][2]+=r1.z*b4.z; acc[6][3]+=r1.z*b4.w;
            acc[7][0]+=r1.w*b4.x; acc[7][1]+=r1.w*b4.y; acc[7][2]+=r1.w*b4.z; acc[7][3]+=r1.w*b4.w;
        }
        if (more) {
            int nb = buf ^ 1;
            As[nb][(lk+0)*136+lr]=a0.x; As[nb][(lk+1)*136+lr]=a0.y;
            As[nb][(lk+2)*136+lr]=a0.z; As[nb][(lk+3)*136+lr]=a0.w;
            As[nb][(lk+4)*136+lr]=a1.x; As[nb][(lk+5)*136+lr]=a1.y;
            As[nb][(lk+6)*136+lr]=a1.z; As[nb][(lk+7)*136+lr]=a1.w;
            *(float4*)&Bs[nb][bk*64 + bn] = bb;
            buf = nb;
            __syncthreads();
        }
    }
    float4 bv = make_float4(0.f,0.f,0.f,0.f);
    if (bias) bv = *(const float4*)&bias[col0 + (tx<<2)];
    #pragma unroll
    for (int ii = 0; ii < 8; ii++) {
        int r = row0 + (ty<<3) + ii;
        if (r >= M) break;
        float v[4] = {acc[ii][0]+bv.x, acc[ii][1]+bv.y, acc[ii][2]+bv.z, acc[ii][3]+bv.w};
        #pragma unroll
        for (int j = 0; j < 4; j++) {
            if (mode == 1) v[j] = fmaxf(v[j], 0.f);
            else if (mode == 2) {
                v[j] *= 0.9999950000374997f;
                if (v[j] <= 0.f) v[j] = expm1f(v[j]);
            }
        }
        *(float4*)&C[(size_t)r*N + col0 + (tx<<2)] = make_float4(v[0],v[1],v[2],v[3]);
    }
}

__global__ void __launch_bounds__(256,3) k_sgemm(
        const float* __restrict__ A, const float* __restrict__ Bm,
        float* __restrict__ C, const float* __restrict__ bias,
        int M, int N, int K, int mode) {
    sgemm_body(A, Bm, C, bias, M, N, K, K, mode);
}

// QKV: one launch, grid.z selects weight/output
__global__ void __launch_bounds__(256,3) k_sgemm_qkv(
        const float* __restrict__ A,
        const float* __restrict__ B0, const float* __restrict__ B1, const float* __restrict__ B2,
        float* __restrict__ C0, float* __restrict__ C1, float* __restrict__ C2,
        int M, int N, int K) {
    const float* Bm = (blockIdx.z == 0) ? B0 : (blockIdx.z == 1) ? B1 : B2;
    float* C = (blockIdx.z == 0) ? C0 : (blockIdx.z == 1) ? C1 : C2;
    sgemm_body(A, Bm, C, nullptr, M, N, K, K, 0);
}

// split-K: grid.z = k-chunk; raw partials
__global__ void __launch_bounds__(256,3) k_sgemm_splitk(
        const float* __restrict__ A, const float* __restrict__ Bm,
        float* __restrict__ Cpart, int M, int N, int K, int kc) {
    int z = blockIdx.z;
    sgemm_body(A + (size_t)z*kc, Bm + (size_t)z*kc*N,
               Cpart + (size_t)z*M*N, nullptr, M, N, kc, K, 0);
}

// reduce 4 partials + bias + scale + elu
__global__ void k_convred(const float* __restrict__ part, const float* __restrict__ bias,
                          float* __restrict__ out, int M) {
    int idx = blockIdx.x*blockDim.x + threadIdx.x;
    int n = M*512;
    if (idx >= n) return;
    size_t stride = (size_t)M*512;
    float v = part[idx] + part[idx+stride] + part[idx+2*stride] + part[idx+3*stride]
            + bias[idx & 511];
    v *= 0.9999950000374997f;
    if (v <= 0.f) v = expm1f(v);
    out[idx] = v;
}

// ---------------- block reduce (256 thr) ----------------
__device__ __forceinline__ float block_sum256(float v) {
    __shared__ float red[8];
    int lane = threadIdx.x & 31, w = threadIdx.x >> 5;
    #pragma unroll
    for (int o = 16; o; o >>= 1) v += __shfl_xor_sync(0xffffffffu, v, o);
    if (lane == 0) red[w] = v;
    __syncthreads();
    if (w == 0) {
        float t = (lane < 8) ? red[lane] : 0.f;
        #pragma unroll
        for (int o = 4; o; o >>= 1) t += __shfl_xor_sync(0xffffffffu, t, o);
        if (lane == 0) red[0] = t;
    }
    __syncthreads();
    float r = red[0];
    __syncthreads();
    return r;
}

// ---------------- concat(x_enc, pyr) + LN(1e-5) ----------------
__global__ void __launch_bounds__(256) k_concat_ln(
        const float* __restrict__ xe, const float* __restrict__ pyr,
        const float* __restrict__ g, const float* __restrict__ bt,
        float* __restrict__ out) {
    int row = blockIdx.x;
    int b = row / LTOT, i = row % LTOT;
    const float* src = (i < 1024) ? xe + ((size_t)(b*1024 + i))*512
                                  : pyr + ((size_t)(b*336 + (i - 1024)))*512;
    int t = threadIdx.x;
    float v0 = src[t], v1 = src[t + 256];
    float mu = block_sum256(v0 + v1) * (1.f/512.f);
    float d0 = v0 - mu, d1 = v1 - mu;
    float var = block_sum256(d0*d0 + d1*d1) * (1.f/512.f);
    float rs = rsqrtf(var + 1e-5f);
    float* o = out + (size_t)row*512;
    o[t]       = d0*rs*g[t]       + bt[t];
    o[t + 256] = d1*rs*g[t + 256] + bt[t + 256];
}

// ---------------- (a + res) -> LN ----------------
__global__ void __launch_bounds__(256) k_add_ln(
        const float* __restrict__ a, const float* __restrict__ res,
        const float* __restrict__ g, const float* __restrict__ bt,
        float* __restrict__ out, float eps) {
    int row = blockIdx.x, t = threadIdx.x;
    const float* pa = a + (size_t)row*512;
    const float* pr = res + (size_t)row*512;
    float v0 = pa[t] + pr[t], v1 = pa[t + 256] + pr[t + 256];
    float mu = block_sum256(v0 + v1) * (1.f/512.f);
    float d0 = v0 - mu, d1 = v1 - mu;
    float var = block_sum256(d0*d0 + d1*d1) * (1.f/512.f);
    float rs = rsqrtf(var + eps);
    float* o = out + (size_t)row*512;
    o[t]       = d0*rs*g[t]       + bt[t];
    o[t + 256] = d1*rs*g[t + 256] + bt[t + 256];
}

// ---------------- row L2 normalize ----------------
__global__ void __launch_bounds__(256) k_rownorm(
        const float* __restrict__ x, float* __restrict__ xn) {
    int row = blockIdx.x, t = threadIdx.x;
    const float* p = x + (size_t)row*512;
    float v0 = p[t], v1 = p[t + 256];
    float ss = block_sum256(v0*v0 + v1*v1);
    float inv = 1.f / fmaxf(sqrtf(ss), 1e-8f);
    float* o = xn + (size_t)row*512;
    o[t] = v0*inv; o[t + 256] = v1*inv;
}

// ---------------- semantic top-k mask (self-clearing) ----------------
__global__ void __launch_bounds__(256) k_topk(
        const float* __restrict__ xn, unsigned char* __restrict__ smask) {
    int i = blockIdx.x, b = blockIdx.y, tid = threadIdx.x;
    const int starts[4] = {0,1024,1280,1344};
    const int sizes[4]  = {1024,256,64,16};
    int lev = (i<1024)?0:(i<1280)?1:(i<1344)?2:3;
    int st = starts[lev], n = sizes[lev];
    int kk = n < 32 ? n : 32;
    __shared__ float sims[1024];
    __shared__ float qrow[512];
    __shared__ float wv[8]; __shared__ int wi[8];
    const float* xb = xn + (size_t)b*LTOT*512;
    unsigned char* mrow = smask + ((size_t)b*LTOT + i)*LTOT + st;
    for (int j = tid; j < n; j += 256) mrow[j] = 0;   // clear own segment
    for (int d = tid; d < 512; d += 256) qrow[d] = xb[(size_t)i*512 + d];
    __syncthreads();
    int w = tid >> 5, lane = tid & 31;
    for (int j = w; j < n; j += 8) {
        const float* rj = xb + (size_t)(st + j)*512;
        float p = 0.f;
        #pragma unroll 4
        for (int d = lane; d < 512; d += 32) p += qrow[d]*rj[d];
        #pragma unroll
        for (int o = 16; o; o >>= 1) p += __shfl_xor_sync(0xffffffffu, p, o);
        if (lane == 0) sims[j] = p;
    }
    __syncthreads();
    for (int it = 0; it < kk; it++) {
        float bv = -3.f; int bi = n;
        for (int j = tid; j < n; j += 256) {
            float v = sims[j];
            if (v > bv) { bv = v; bi = j; }
        }
        #pragma unroll
        for (int o = 16; o; o >>= 1) {
            float ov = __shfl_xor_sync(0xffffffffu, bv, o);
            int   oi = __shfl_xor_sync(0xffffffffu, bi, o);
            if (ov > bv || (ov == bv && oi < bi)) { bv = ov; bi = oi; }
        }
        if (lane == 0) { wv[w] = bv; wi[w] = bi; }
        __syncthreads();
        if (tid == 0) {
            float fv = wv[0]; int fi = wi[0];
            #pragma unroll
            for (int z = 1; z < 8; z++)
                if (wv[z] > fv || (wv[z] == fv && wi[z] < fi)) { fv = wv[z]; fi = wi[z]; }
            mrow[fi] = 1;
            sims[fi] = -3.f;
        }
        __syncthreads();
    }
}

// ---------------- SPARSE temporal attention ----------------
__global__ void __launch_bounds__(256) k_tattn(
        const float* __restrict__ Q, const float* __restrict__ K,
        const float* __restrict__ V, float* __restrict__ O) {
    int i = blockIdx.x, b = blockIdx.y;
    int h = threadIdx.x >> 5, lane = threadIdx.x & 31;
    const int starts[4] = {0,1024,1280,1344};
    const int sizes[4]  = {1024,256,64,16};
    int lev = (i<1024)?0:(i<1280)?1:(i<1344)?2:3;
    int st = starts[lev], n = sizes[lev];
    int nb[10]; int cnt = 0;
    int lo = (i-2 < st) ? st : i-2;
    int hi = (i+2 > st+n-1) ? st+n-1 : i+2;
    for (int j = lo; j <= hi; j++) nb[cnt++] = j;
    if (lev > 0) {
        int c0 = starts[lev-1] + (i - st)*4;
        nb[cnt++] = c0; nb[cnt++] = c0+1; nb[cnt++] = c0+2; nb[cnt++] = c0+3;
    }
    if (lev < 3) nb[cnt++] = starts[lev+1] + (i - st)/4;

    size_t rowb = (size_t)(b*LTOT);
    const float2 qv = *(const float2*)(Q + (rowb + i)*512 + h*64 + lane*2);
    float sc[10];
    #pragma unroll
    for (int t = 0; t < 10; t++) {
        if (t < cnt) {
            float2 kv = *(const float2*)(K + (rowb + nb[t])*512 + h*64 + lane*2);
            float p = qv.x*kv.x + qv.y*kv.y;
            #pragma unroll
            for (int o = 16; o; o >>= 1) p += __shfl_xor_sync(0xffffffffu, p, o);
            sc[t] = p * 0.125f;
        } else sc[t] = -1e30f;
    }
    float mx = -1e30f;
    #pragma unroll
    for (int t = 0; t < 10; t++) mx = fmaxf(mx, sc[t]);
    float ssum = 0.f;
    #pragma unroll
    for (int t = 0; t < 10; t++) {
        sc[t] = (t < cnt) ? expf(sc[t] - mx) : 0.f;
        ssum += sc[t];
    }
    float inv = 1.f / ssum;
    float ax = 0.f, ay = 0.f;
    #pragma unroll
    for (int t = 0; t < 10; t++) {
        if (t < cnt) {
            float2 vv = *(const float2*)(V + (rowb + nb[t])*512 + h*64 + lane*2);
            ax += sc[t]*vv.x; ay += sc[t]*vv.y;
        }
    }
    *(float2*)(O + (rowb + i)*512 + h*64 + lane*2) = make_float2(ax*inv, ay*inv);
}

// ---------------- DENSE semantic attention: 16 q x 1 head per block ----------------
#define TSK_PITCH 268
#define ATT_SMEM ((16*68 + 16*1361 + 256*68)*4)   // 161,088 B
__global__ void __launch_bounds__(256) k_sattn(
        const float* __restrict__ Q, const float* __restrict__ K,
        const float* __restrict__ V, const unsigned char* __restrict__ mask,
        float* __restrict__ O) {
    extern __shared__ float smem[];
    float* Qs = smem;                      // [16][68]
    float* Ss = smem + 16*68;              // [16][1361]
    float* Ts = smem + 16*68 + 16*1361;    // scratch
    __shared__ float rsum[16];
    int tid = threadIdx.x;
    int b = blockIdx.z, h = blockIdx.y, q0 = blockIdx.x << 4;
    size_t rb = (size_t)b * LTOT;
    const float* Qb = Q + rb*512 + h*64;
    const float* Kb = K + rb*512 + h*64;
    const float* Vb = V + rb*512 + h*64;
    const unsigned char* mb = mask + L2SZ*b;

    {
        int qq = tid >> 4, d4 = (tid & 15) << 2;
        *(float4*)&Qs[qq*68 + d4] = *(const float4*)&Qb[(size_t)(q0+qq)*512 + d4];
    }
    int qt = tid & 3, kt = tid >> 2;
    for (int jt = 0; jt < 6; jt++) {
        int jb = jt << 8;
        int jc = LTOT - jb; if (jc > 256) jc = 256;
        __syncthreads();
        for (int slot = tid; slot < (jc << 4); slot += 256) {
            int j = slot >> 4, d4 = (slot & 15) << 2;
            float4 kv = *(const float4*)&Kb[(size_t)(jb+j)*512 + d4];
            Ts[(d4+0)*TSK_PITCH + j] = kv.x;
            Ts[(d4+1)*TSK_PITCH + j] = kv.y;
            Ts[(d4+2)*TSK_PITCH + j] = kv.z;
            Ts[(d4+3)*TSK_PITCH + j] = kv.w;
        }
        __syncthreads();
        float s[4][4] = {};
        #pragma unroll 8
        for (int d = 0; d < 64; d++) {
            float4 kv = *(const float4*)&Ts[d*TSK_PITCH + (kt<<2)];
            float q0v = Qs[(qt*4+0)*68 + d];
            float q1v = Qs[(qt*4+1)*68 + d];
            float q2v = Qs[(qt*4+2)*68 + d];
            float q3v = Qs[(qt*4+3)*68 + d];
            s[0][0]+=q0v*kv.x; s[0][1]+=q0v*kv.y; s[0][2]+=q0v*kv.z; s[0][3]+=q0v*kv.w;
            s[1][0]+=q1v*kv.x; s[1][1]+=q1v*kv.y; s[1][2]+=q1v*kv.z; s[1][3]+=q1v*kv.w;
            s[2][0]+=q2v*kv.x; s[2][1]+=q2v*kv.y; s[2][2]+=q2v*kv.z; s[2][3]+=q2v*kv.w;
            s[3][0]+=q3v*kv.x; s[3][1]+=q3v*kv.y; s[3][2]+=q3v*kv.z; s[3][3]+=q3v*kv.w;
        }
        #pragma unroll
        for (int u = 0; u < 4; u++) {
            int q = qt*4 + u;
            const unsigned char* mrow = mb + (size_t)(q0+q)*LTOT;
            float* srow = Ss + q*1361;
            #pragma unroll
            for (int w = 0; w < 4; w++) {
                int jl = (kt<<2) + w;
                if (jl < jc) {
                    int jg = jb + jl;
                    srow[jg] = mrow[jg] ? -1e30f : s[u][w]*0.125f;
                }
            }
        }
    }
    __syncthreads();
    {
        int w = tid >> 5, lane = tid & 31;
        for (int r = w; r < 16; r += 8) {
            float* row = Ss + r*1361;
            float mx = -1e30f;
            for (int j = lane; j < LTOT; j += 32) mx = fmaxf(mx, row[j]);
            #pragma unroll
            for (int o = 16; o; o >>= 1) mx = fmaxf(mx, __shfl_xor_sync(0xffffffffu, mx, o));
            float sum = 0.f;
            for (int j = lane; j < LTOT; j += 32) {
                float e = expf(row[j] - mx);
                row[j] = e; sum += e;
            }
            #pragma unroll
            for (int o = 16; o; o >>= 1) sum += __shfl_xor_sync(0xffffffffu, sum, o);
            if (lane == 0) rsum[r] = sum;
        }
    }
    int rep = tid >> 6;
    int qt2 = (tid >> 4) & 3;
    int dt  = tid & 15;
    float4 acc[4] = {};
    for (int jt = 0; jt < 6; jt++) {
        int jb = jt << 8;
        int jc = LTOT - jb; if (jc > 256) jc = 256;
        __syncthreads();
        for (int slot = tid; slot < (jc << 4); slot += 256) {
            int j = slot >> 4, d4 = (slot & 15) << 2;
            *(float4*)&Ts[j*68 + d4] = *(const float4*)&Vb[(size_t)(jb+j)*512 + d4];
        }
        __syncthreads();
        int j0 = rep << 6;
        int j1 = j0 + 64; if (j1 > jc) j1 = jc;
        const float* p0r = Ss + (qt2*4+0)*1361 + jb;
        const float* p1r = Ss + (qt2*4+1)*1361 + jb;
        const float* p2r = Ss + (qt2*4+2)*1361 + jb;
        const float* p3r = Ss + (qt2*4+3)*1361 + jb;
        for (int j = j0; j < j1; j++) {
            float4 v4 = *(const float4*)&Ts[j*68 + (dt<<2)];
            float p0 = p0r[j], p1 = p1r[j], p2 = p2r[j], p3 = p3r[j];
            acc[0].x+=p0*v4.x; acc[0].y+=p0*v4.y; acc[0].z+=p0*v4.z; acc[0].w+=p0*v4.w;
            acc[1].x+=p1*v4.x; acc[1].y+=p1*v4.y; acc[1].z+=p1*v4.z; acc[1].w+=p1*v4.w;
            acc[2].x+=p2*v4.x; acc[2].y+=p2*v4.y; acc[2].z+=p2*v4.z; acc[2].w+=p2*v4.w;
            acc[3].x+=p3*v4.x; acc[3].y+=p3*v4.y; acc[3].z+=p3*v4.z; acc[3].w+=p3*v4.w;
        }
    }
    __syncthreads();
    #pragma unroll
    for (int u = 0; u < 4; u++) {
        int q = qt2*4 + u;
        *(float4*)&Ts[((rep*16 + q)*64) + (dt<<2)] = acc[u];
    }
    __syncthreads();
    {
        int q = tid >> 4, d4 = (tid & 15) << 2;
        float4 r0 = *(const float4*)&Ts[(0*16+q)*64 + d4];
        float4 r1 = *(const float4*)&Ts[(1*16+q)*64 + d4];
        float4 r2 = *(const float4*)&Ts[(2*16+q)*64 + d4];
        float4 r3 = *(const float4*)&Ts[(3*16+q)*64 + d4];
        float inv = 1.f / rsum[q];
        float4 o4 = make_float4((r0.x+r1.x+r2.x+r3.x)*inv, (r0.y+r1.y+r2.y+r3.y)*inv,
                                (r0.z+r1.z+r2.z+r3.z)*inv, (r0.w+r1.w+r2.w+r3.w)*inv);
        *(float4*)(O + (rb + q0 + q)*512 + h*64 + d4) = o4;
    }
}

// ---------------- pyramid concat + combine ----------------
__global__ void k_pyrcat(const float* __restrict__ c1, const float* __restrict__ c2,
                         const float* __restrict__ c3, float* __restrict__ out) {
    int idx = blockIdx.x*blockDim.x + threadIdx.x;
    if (idx >= BATCH*336*512) return;
    int d = idx & 511, r = idx >> 9;
    int b = r / 336, p = r % 336;
    float v;
    if (p < 256) v = c1[((size_t)(b*256 + p) << 9) | d];
    else if (p < 320) v = c2[((size_t)(b*64 + p - 256) << 9) | d];
    else v = c3[((size_t)(b*16 + p - 320) << 9) | d];
    out[idx] = v;
}

__global__ void k_comb(const float* __restrict__ t, const float* __restrict__ s,
                       float* __restrict__ x, int n) {
    int i = blockIdx.x*blockDim.x + threadIdx.x;
    if (i < n) x[i] = (t[i] + s[i] + x[i]) * (1.f/3.f);
}

// ---------------- orchestration ----------------
static void gemm(const float* A, const float* B, float* C, const float* bias,
                 int M, int N, int K, int mode) {
    dim3 g(N/64, (M + 127)/128);
    k_sgemm<<<g, 256>>>(A, B, C, bias, M, N, K, mode);
}

static void conv_gemm(const float* A, const float* B, float* part, const float* bias,
                      float* out, int M) {
    dim3 g(8, (M + 127)/128, 4);
    k_sgemm_splitk<<<g, 256>>>(A, B, part, M, 512, 2048, 512);
    k_convred<<<(M*512 + 255)/256, 256>>>(part, bias, out, M);
}

extern "C" void kernel_launch(void* const* d_in, const int* in_sizes, int n_in,
                              void* d_out, int out_size) {
    const float* x_enc  = (const float*)d_in[0];
    const float* down_W = (const float*)d_in[1];
    const float* down_b = (const float*)d_in[2];
    const float* conv_W = (const float*)d_in[3];
    const float* conv_b = (const float*)d_in[4];
    const float* up_W   = (const float*)d_in[5];
    const float* up_b   = (const float*)d_in[6];
    const float* bc_g   = (const float*)d_in[7];
    const float* bc_b   = (const float*)d_in[8];
    const float* Wq     = (const float*)d_in[9];
    const float* Wk     = (const float*)d_in[10];
    const float* Wv     = (const float*)d_in[11];
    const float* fcW    = (const float*)d_in[12];
    const float* fcb    = (const float*)d_in[13];
    const float* aln_g  = (const float*)d_in[14];
    const float* aln_b  = (const float*)d_in[15];
    const float* W1     = (const float*)d_in[16];
    const float* b1     = (const float*)d_in[17];
    const float* W2     = (const float*)d_in[18];
    const float* b2     = (const float*)d_in[19];
    const float* fln_g  = (const float*)d_in[20];
    const float* fln_b  = (const float*)d_in[21];
    float* out = (float*)d_out;

    float *t0,*c1,*c2,*c3,*pc,*pyr,*x,*q,*k,*v,*o,*fc,*tout,*sout,*xn,*h,*wc,*part;
    unsigned char *smk;
    cudaGetSymbolAddress((void**)&t0,  g_t0);
    cudaGetSymbolAddress((void**)&c1,  g_c1);
    cudaGetSymbolAddress((void**)&c2,  g_c2);
    cudaGetSymbolAddress((void**)&c3,  g_c3);
    cudaGetSymbolAddress((void**)&pc,  g_pc);
    cudaGetSymbolAddress((void**)&pyr, g_pyr);
    cudaGetSymbolAddress((void**)&x,   g_x);
    cudaGetSymbolAddress((void**)&q,   g_q);
    cudaGetSymbolAddress((void**)&k,   g_k);
    cudaGetSymbolAddress((void**)&v,   g_v);
    cudaGetSymbolAddress((void**)&o,   g_o);
    cudaGetSymbolAddress((void**)&fc,  g_fc);
    cudaGetSymbolAddress((void**)&tout,g_tout);
    cudaGetSymbolAddress((void**)&sout,g_sout);
    cudaGetSymbolAddress((void**)&xn,  g_xn);
    cudaGetSymbolAddress((void**)&h,   g_h);
    cudaGetSymbolAddress((void**)&wc,  g_wc);
    cudaGetSymbolAddress((void**)&part,g_part);
    cudaGetSymbolAddress((void**)&smk, g_sm);

    cudaFuncSetAttribute(k_sattn, cudaFuncAttributeMaxDynamicSharedMemorySize, ATT_SMEM);

    k_convw<<<(3*2048*512 + 255)/256, 256>>>(conv_W, wc);

    // bottleneck
    gemm(x_enc, down_W, t0, down_b, BATCH*1024, 512, 512, 0);
    conv_gemm(t0, wc,              part, conv_b,        c1, BATCH*256);
    conv_gemm(c1, wc + 2048*512,   part, conv_b + 512,  c2, BATCH*64);
    conv_gemm(c2, wc + 2*2048*512, part, conv_b + 1024, c3, BATCH*16);
    k_pyrcat<<<(BATCH*336*512 + 255)/256, 256>>>(c1, c2, c3, pc);
    gemm(pc, up_W, pyr, up_b, BATCH*336, 512, 512, 0);
    k_concat_ln<<<NROWS, 256>>>(x_enc, pyr, bc_g, bc_b, x);

    for (int l = 0; l < 2; l++) {
        k_rownorm<<<NROWS, 256>>>(x, xn);
        dim3 tg(LTOT, BATCH);
        k_topk<<<tg, 256>>>(xn, smk);

        for (int s = 0; s < 2; s++) {
            size_t wo = ((size_t)l*2 + s)*512*512;
            size_t lo = ((size_t)l*2 + s)*512;
            dim3 qg(8, (NROWS + 127)/128, 3);
            k_sgemm_qkv<<<qg, 256>>>(x, Wq + wo, Wk + wo, Wv + wo,
                                     q, k, v, NROWS, 512, 512);
            if (s == 0) {
                dim3 sg(LTOT, BATCH);
                k_tattn<<<sg, 256>>>(q, k, v, o);
            } else {
                dim3 ag(LTOT/16, 8, BATCH);
                k_sattn<<<ag, 256, ATT_SMEM>>>(q, k, v, smk, o);
            }
            gemm(o, fcW + wo, fc, fcb + lo, NROWS, 512, 512, 0);
            k_add_ln<<<NROWS, 256>>>(fc, x, aln_g + lo, aln_b + lo,
                                     s == 0 ? tout : sout, 1e-6f);
        }
        k_comb<<<(NROWS*512 + 255)/256, 256>>>(tout, sout, x, NROWS*512);

        size_t fo = (size_t)l*512*512, fb = (size_t)l*512;
        gemm(x, W1 + fo, h, b1 + fb, NROWS, 512, 512, 1);
        gemm(h, W2 + fo, fc, b2 + fb, NROWS, 512, 512, 0);
        k_add_ln<<<NROWS, 256>>>(fc, x, fln_g + fb, fln_b + fb,
                                 (l == 0) ? x : out, 1e-6f);
    }
}

// round 7
// speedup vs baseline: 1.9957x; 1.1006x over previous
#include <cuda_runtime.h>
#include <cuda_bf16.h>
#include <math.h>
#include <stdint.h>

#define LTOT   1360
#define BATCH  4
#define NROWS  (BATCH*LTOT)          // 5440
#define L2SZ   ((size_t)LTOT*LTOT)

typedef __nv_bfloat16 bf16;
typedef unsigned int u32;

// ---------------- static device scratch ----------------
__device__ float g_t0[BATCH*1024*512];
__device__ float g_c1[BATCH*256*512];
__device__ float g_c2[BATCH*64*512];
__device__ float g_c3[BATCH*16*512];
__device__ float g_pc[BATCH*336*512];
__device__ float g_pyr[BATCH*336*512];
__device__ float g_x[NROWS*512];
__device__ float g_q[NROWS*512];
__device__ float g_k[NROWS*512];
__device__ float g_v[NROWS*512];
__device__ float g_q2[NROWS*512];
__device__ float g_k2[NROWS*512];
__device__ float g_v2[NROWS*512];
__device__ float g_o[NROWS*512];
__device__ float g_o2[NROWS*512];
__device__ float g_fc[NROWS*512];
__device__ float g_fc2[NROWS*512];
__device__ float g_tout[NROWS*512];
__device__ float g_sout[NROWS*512];
__device__ float g_xn[NROWS*512];
__device__ float g_h[NROWS*512];
__device__ float g_wc[3*2048*512];
__device__ bf16 g_ahi[2*NROWS*512];
__device__ bf16 g_alo[2*NROWS*512];
__device__ bf16 g_bhi[6*512*512];
__device__ bf16 g_blo[6*512*512];
__device__ unsigned char g_sm[(size_t)BATCH*LTOT*LTOT];

// ---------------- fp32 -> bf16 hi/lo (flat) ----------------
__global__ void k_cvtA(const float* __restrict__ s, bf16* __restrict__ hi,
                       bf16* __restrict__ lo, int n4) {
    int i = blockIdx.x*blockDim.x + threadIdx.x;
    if (i >= n4) return;
    float4 v = ((const float4*)s)[i];
    bf16 h0=__float2bfloat16(v.x), h1=__float2bfloat16(v.y),
         h2=__float2bfloat16(v.z), h3=__float2bfloat16(v.w);
    bf16 l0=__float2bfloat16(v.x-__bfloat162float(h0)),
         l1=__float2bfloat16(v.y-__bfloat162float(h1)),
         l2=__float2bfloat16(v.z-__bfloat162float(h2)),
         l3=__float2bfloat16(v.w-__bfloat162float(h3));
    uint2 hp = make_uint2((u32)__bfloat16_as_ushort(h0) | ((u32)__bfloat16_as_ushort(h1)<<16),
                          (u32)__bfloat16_as_ushort(h2) | ((u32)__bfloat16_as_ushort(h3)<<16));
    uint2 lp = make_uint2((u32)__bfloat16_as_ushort(l0) | ((u32)__bfloat16_as_ushort(l1)<<16),
                          (u32)__bfloat16_as_ushort(l2) | ((u32)__bfloat16_as_ushort(l3)<<16));
    ((uint2*)hi)[i] = hp;
    ((uint2*)lo)[i] = lp;
}

// ---------------- fp32 [K][N] -> bf16 hi/lo transposed [N][K] ----------------
__device__ __forceinline__ void cvtB_body(const float* __restrict__ src,
        bf16* __restrict__ hi, bf16* __restrict__ lo, int K, int N) {
    __shared__ float t[32][33];
    int tx = threadIdx.x, ty = threadIdx.y;
    int n0 = blockIdx.x*32, k0 = blockIdx.y*32;
    #pragma unroll
    for (int i = 0; i < 4; i++)
        t[ty + i*8][tx] = src[(size_t)(k0 + ty + i*8)*N + n0 + tx];
    __syncthreads();
    #pragma unroll
    for (int i = 0; i < 4; i++) {
        float v = t[tx][ty + i*8];
        int n = n0 + ty + i*8, kk = k0 + tx;
        bf16 h = __float2bfloat16(v);
        bf16 l = __float2bfloat16(v - __bfloat162float(h));
        hi[(size_t)n*K + kk] = h;
        lo[(size_t)n*K + kk] = l;
    }
}
__global__ void k_cvtB(const float* __restrict__ src, bf16* hi, bf16* lo, int K, int N) {
    cvtB_body(src, hi, lo, K, N);
}
__global__ void k_cvtB_qkv(const float* __restrict__ Wq, const float* __restrict__ Wk,
                           const float* __restrict__ Wv, size_t wo_t, size_t wo_s,
                           bf16* hi, bf16* lo) {
    int z = blockIdx.z;
    const float* base = ((z%3 == 0) ? Wq : (z%3 == 1) ? Wk : Wv) + ((z/3) ? wo_s : wo_t);
    cvtB_body(base, hi + (size_t)z*512*512, lo + (size_t)z*512*512, 512, 512);
}

// ---------------- bf16x3 MMA GEMM: 128x64 tile, 8 warps ----------------
__device__ __forceinline__ void mma16816(float* d, const u32* a, const u32* b) {
    asm volatile(
        "mma.sync.aligned.m16n8k16.row.col.f32.bf16.bf16.f32 "
        "{%0,%1,%2,%3}, {%4,%5,%6,%7}, {%8,%9}, {%0,%1,%2,%3};"
        : "+f"(d[0]), "+f"(d[1]), "+f"(d[2]), "+f"(d[3])
        : "r"(a[0]), "r"(a[1]), "r"(a[2]), "r"(a[3]), "r"(b[0]), "r"(b[1]));
}
#define AP 40
// mode: 0 none, 1 relu, 2 scale+elu
__device__ void mg_body(const bf16* __restrict__ Ahi, const bf16* __restrict__ Alo,
                        const bf16* __restrict__ Bhi, const bf16* __restrict__ Blo,
                        float* __restrict__ C, const float* __restrict__ bias,
                        int M, int N, int K, int mode) {
    __shared__ bf16 As[2][128*AP];
    __shared__ bf16 Bs[2][64*AP];
    int tid = threadIdx.x, wid = tid >> 5, lane = tid & 31;
    int wm = wid >> 1, wn = wid & 1, g = lane >> 2, qp = lane & 3;
    int row0 = blockIdx.y << 7, col0 = blockIdx.x << 6;
    float acc[2][4][4] = {};
    for (int kc = 0; kc < K; kc += 32) {
        #pragma unroll
        for (int s = tid; s < 512; s += 256) {
            int r = s >> 2, k8 = (s & 3) << 3;
            int gr = row0 + r;
            float4 vh = make_float4(0,0,0,0), vl = vh;
            if (gr < M) {
                vh = *(const float4*)(Ahi + (size_t)gr*K + kc + k8);
                vl = *(const float4*)(Alo + (size_t)gr*K + kc + k8);
            }
            *(float4*)&As[0][r*AP + k8] = vh;
            *(float4*)&As[1][r*AP + k8] = vl;
        }
        if (tid < 256) {
            int s = tid;
            int r = s >> 2, k8 = (s & 3) << 3;
            int gn = col0 + r;
            float4 vh = *(const float4*)(Bhi + (size_t)gn*K + kc + k8);
            float4 vl = *(const float4*)(Blo + (size_t)gn*K + kc + k8);
            *(float4*)&Bs[0][r*AP + k8] = vh;
            *(float4*)&Bs[1][r*AP + k8] = vl;
        }
        __syncthreads();
        #pragma unroll
        for (int ks = 0; ks < 32; ks += 16) {
            u32 ah[2][4], al[2][4], bh[4][2], bl[4][2];
            #pragma unroll
            for (int mt = 0; mt < 2; mt++) {
                int ar = (wm*32 + mt*16 + g)*AP + ks + qp*2;
                int ar8 = ar + 8*AP;
                ah[mt][0] = *(u32*)&As[0][ar];     ah[mt][1] = *(u32*)&As[0][ar8];
                ah[mt][2] = *(u32*)&As[0][ar + 8]; ah[mt][3] = *(u32*)&As[0][ar8 + 8];
                al[mt][0] = *(u32*)&As[1][ar];     al[mt][1] = *(u32*)&As[1][ar8];
                al[mt][2] = *(u32*)&As[1][ar + 8]; al[mt][3] = *(u32*)&As[1][ar8 + 8];
            }
            #pragma unroll
            for (int nt = 0; nt < 4; nt++) {
                int br = (wn*32 + nt*8 + g)*AP + ks + qp*2;
                bh[nt][0] = *(u32*)&Bs[0][br]; bh[nt][1] = *(u32*)&Bs[0][br + 8];
                bl[nt][0] = *(u32*)&Bs[1][br]; bl[nt][1] = *(u32*)&Bs[1][br + 8];
            }
            #pragma unroll
            for (int mt = 0; mt < 2; mt++)
                #pragma unroll
                for (int nt = 0; nt < 4; nt++) {
                    mma16816(acc[mt][nt], ah[mt], bh[nt]);
                    mma16816(acc[mt][nt], ah[mt], bl[nt]);
                    mma16816(acc[mt][nt], al[mt], bh[nt]);
                }
        }
        __syncthreads();
    }
    #pragma unroll
    for (int mt = 0; mt < 2; mt++) {
        int r0 = row0 + wm*32 + mt*16 + g;
        #pragma unroll
        for (int half = 0; half < 2; half++) {
            int r = r0 + half*8;
            if (r >= M) continue;
            #pragma unroll
            for (int nt = 0; nt < 4; nt++) {
                int cl = col0 + wn*32 + nt*8 + qp*2;
                float v0 = acc[mt][nt][half*2 + 0], v1 = acc[mt][nt][half*2 + 1];
                if (bias) { v0 += bias[cl]; v1 += bias[cl + 1]; }
                if (mode == 1) { v0 = fmaxf(v0, 0.f); v1 = fmaxf(v1, 0.f); }
                else if (mode == 2) {
                    v0 *= 0.9999950000374997f; if (v0 <= 0.f) v0 = expm1f(v0);
                    v1 *= 0.9999950000374997f; if (v1 <= 0.f) v1 = expm1f(v1);
                }
                *(float2*)&C[(size_t)r*N + cl] = make_float2(v0, v1);
            }
        }
    }
}

__global__ void __launch_bounds__(256) k_mgemm(
        const bf16* Ahi, const bf16* Alo, const bf16* Bhi, const bf16* Blo,
        float* C, const float* bias, int M, int N, int K, int mode) {
    mg_body(Ahi, Alo, Bhi, Blo, C, bias, M, N, K, mode);
}
__global__ void __launch_bounds__(256) k_mgemm_qkv(
        const bf16* Ahi, const bf16* Alo, const bf16* Bhi, const bf16* Blo,
        float* q, float* k, float* v, float* q2, float* k2, float* v2,
        int M, int N, int K) {
    int z = blockIdx.z;
    size_t bo = (size_t)z*512*512;
    float* C = (z==0)?q:(z==1)?k:(z==2)?v:(z==3)?q2:(z==4)?k2:v2;
    mg_body(Ahi, Alo, Bhi + bo, Blo + bo, C, nullptr, M, N, K, 0);
}
__global__ void __launch_bounds__(256) k_mgemm_fc(
        const bf16* Ahi, const bf16* Alo, const bf16* Bhi, const bf16* Blo,
        const float* fcb, size_t lo_t, size_t lo_s,
        float* ft, float* fs, int M, int N, int K) {
    int z = blockIdx.z;
    size_t ao = (size_t)z*NROWS*512, bo = (size_t)z*512*512;
    mg_body(Ahi + ao, Alo + ao, Bhi + bo, Blo + bo, z ? fs : ft,
            fcb + (z ? lo_s : lo_t), M, N, K, 0);
}

// ---------------- conv weight re-layout ----------------
__global__ void k_convw(const float* __restrict__ w, float* __restrict__ wm) {
    int idx = blockIdx.x*blockDim.x + threadIdx.x;
    if (idx >= 3*2048*512) return;
    int l  = idx / (2048*512);
    int r  = idx - l*2048*512;
    int kk = r >> 9, co = r & 511;
    int t  = kk >> 9, ci = kk & 511;
    wm[idx] = w[(((size_t)(l*512 + co))*512 + ci)*4 + t];
}

// ---------------- block reduce (256 thr) ----------------
__device__ __forceinline__ float block_sum256(float v) {
    __shared__ float red[8];
    int lane = threadIdx.x & 31, w = threadIdx.x >> 5;
    #pragma unroll
    for (int o = 16; o; o >>= 1) v += __shfl_xor_sync(0xffffffffu, v, o);
    if (lane == 0) red[w] = v;
    __syncthreads();
    if (w == 0) {
        float t = (lane < 8) ? red[lane] : 0.f;
        #pragma unroll
        for (int o = 4; o; o >>= 1) t += __shfl_xor_sync(0xffffffffu, t, o);
        if (lane == 0) red[0] = t;
    }
    __syncthreads();
    float r = red[0];
    __syncthreads();
    return r;
}

// ---------------- concat + LN(1e-5) ----------------
__global__ void __launch_bounds__(256) k_concat_ln(
        const float* __restrict__ xe, const float* __restrict__ pyr,
        const float* __restrict__ g, const float* __restrict__ bt,
        float* __restrict__ out) {
    int row = blockIdx.x;
    int b = row / LTOT, i = row % LTOT;
    const float* src = (i < 1024) ? xe + ((size_t)(b*1024 + i))*512
                                  : pyr + ((size_t)(b*336 + (i - 1024)))*512;
    int t = threadIdx.x;
    float v0 = src[t], v1 = src[t + 256];
    float mu = block_sum256(v0 + v1) * (1.f/512.f);
    float d0 = v0 - mu, d1 = v1 - mu;
    float var = block_sum256(d0*d0 + d1*d1) * (1.f/512.f);
    float rs = rsqrtf(var + 1e-5f);
    float* o = out + (size_t)row*512;
    o[t]       = d0*rs*g[t]       + bt[t];
    o[t + 256] = d1*rs*g[t + 256] + bt[t + 256];
}

// ---------------- (a+res) -> LN ----------------
__global__ void __launch_bounds__(256) k_add_ln(
        const float* __restrict__ a, const float* __restrict__ res,
        const float* __restrict__ g, const float* __restrict__ bt,
        float* __restrict__ out, float eps) {
    int row = blockIdx.x, t = threadIdx.x;
    const float* pa = a + (size_t)row*512;
    const float* pr = res + (size_t)row*512;
    float v0 = pa[t] + pr[t], v1 = pa[t + 256] + pr[t + 256];
    float mu = block_sum256(v0 + v1) * (1.f/512.f);
    float d0 = v0 - mu, d1 = v1 - mu;
    float var = block_sum256(d0*d0 + d1*d1) * (1.f/512.f);
    float rs = rsqrtf(var + eps);
    float* o = out + (size_t)row*512;
    o[t]       = d0*rs*g[t]       + bt[t];
    o[t + 256] = d1*rs*g[t + 256] + bt[t + 256];
}

// two-branch add_ln
__global__ void __launch_bounds__(256) k_add_ln2(
        const float* __restrict__ at, const float* __restrict__ as_,
        const float* __restrict__ res,
        const float* __restrict__ g, const float* __restrict__ bt,
        size_t lo_t, size_t lo_s,
        float* __restrict__ ot, float* __restrict__ os_) {
    int s = blockIdx.y;
    const float* a = s ? as_ : at;
    const float* gg = g + (s ? lo_s : lo_t);
    const float* bb = bt + (s ? lo_s : lo_t);
    float* out = s ? os_ : ot;
    int row = blockIdx.x, t = threadIdx.x;
    const float* pa = a + (size_t)row*512;
    const float* pr = res + (size_t)row*512;
    float v0 = pa[t] + pr[t], v1 = pa[t + 256] + pr[t + 256];
    float mu = block_sum256(v0 + v1) * (1.f/512.f);
    float d0 = v0 - mu, d1 = v1 - mu;
    float var = block_sum256(d0*d0 + d1*d1) * (1.f/512.f);
    float rs = rsqrtf(var + 1e-6f);
    float* o = out + (size_t)row*512;
    o[t]       = d0*rs*gg[t]       + bb[t];
    o[t + 256] = d1*rs*gg[t + 256] + bb[t + 256];
}

// ---------------- row L2 normalize ----------------
__global__ void __launch_bounds__(256) k_rownorm(
        const float* __restrict__ x, float* __restrict__ xn) {
    int row = blockIdx.x, t = threadIdx.x;
    const float* p = x + (size_t)row*512;
    float v0 = p[t], v1 = p[t + 256];
    float ss = block_sum256(v0*v0 + v1*v1);
    float inv = 1.f / fmaxf(sqrtf(ss), 1e-8f);
    float* o = xn + (size_t)row*512;
    o[t] = v0*inv; o[t + 256] = v1*inv;
}

// ---------------- semantic top-k mask (self-clearing) ----------------
__global__ void __launch_bounds__(256) k_topk(
        const float* __restrict__ xn, unsigned char* __restrict__ smask) {
    int i = blockIdx.x, b = blockIdx.y, tid = threadIdx.x;
    const int starts[4] = {0,1024,1280,1344};
    const int sizes[4]  = {1024,256,64,16};
    int lev = (i<1024)?0:(i<1280)?1:(i<1344)?2:3;
    int st = starts[lev], n = sizes[lev];
    int kk = n < 32 ? n : 32;
    __shared__ float sims[1024];
    __shared__ float qrow[512];
    __shared__ float wv[8]; __shared__ int wi[8];
    const float* xb = xn + (size_t)b*LTOT*512;
    unsigned char* mrow = smask + ((size_t)b*LTOT + i)*LTOT + st;
    for (int j = tid; j < n; j += 256) mrow[j] = 0;
    for (int d = tid; d < 512; d += 256) qrow[d] = xb[(size_t)i*512 + d];
    __syncthreads();
    int w = tid >> 5, lane = tid & 31;
    for (int j = w; j < n; j += 8) {
        const float* rj = xb + (size_t)(st + j)*512;
        float p = 0.f;
        #pragma unroll 4
        for (int d = lane; d < 512; d += 32) p += qrow[d]*rj[d];
        #pragma unroll
        for (int o = 16; o; o >>= 1) p += __shfl_xor_sync(0xffffffffu, p, o);
        if (lane == 0) sims[j] = p;
    }
    __syncthreads();
    for (int it = 0; it < kk; it++) {
        float bv = -3.f; int bi = n;
        for (int j = tid; j < n; j += 256) {
            float v = sims[j];
            if (v > bv) { bv = v; bi = j; }
        }
        #pragma unroll
        for (int o = 16; o; o >>= 1) {
            float ov = __shfl_xor_sync(0xffffffffu, bv, o);
            int   oi = __shfl_xor_sync(0xffffffffu, bi, o);
            if (ov > bv || (ov == bv && oi < bi)) { bv = ov; bi = oi; }
        }
        if (lane == 0) { wv[w] = bv; wi[w] = bi; }
        __syncthreads();
        if (tid == 0) {
            float fv = wv[0]; int fi = wi[0];
            #pragma unroll
            for (int z = 1; z < 8; z++)
                if (wv[z] > fv || (wv[z] == fv && wi[z] < fi)) { fv = wv[z]; fi = wi[z]; }
            mrow[fi] = 1;
            sims[fi] = -3.f;
        }
        __syncthreads();
    }
}

// ---------------- SPARSE temporal attention ----------------
__global__ void __launch_bounds__(256) k_tattn(
        const float* __restrict__ Q, const float* __restrict__ K,
        const float* __restrict__ V, float* __restrict__ O) {
    int i = blockIdx.x, b = blockIdx.y;
    int h = threadIdx.x >> 5, lane = threadIdx.x & 31;
    const int starts[4] = {0,1024,1280,1344};
    const int sizes[4]  = {1024,256,64,16};
    int lev = (i<1024)?0:(i<1280)?1:(i<1344)?2:3;
    int st = starts[lev], n = sizes[lev];
    int nb[10]; int cnt = 0;
    int lo = (i-2 < st) ? st : i-2;
    int hi = (i+2 > st+n-1) ? st+n-1 : i+2;
    for (int j = lo; j <= hi; j++) nb[cnt++] = j;
    if (lev > 0) {
        int c0 = starts[lev-1] + (i - st)*4;
        nb[cnt++] = c0; nb[cnt++] = c0+1; nb[cnt++] = c0+2; nb[cnt++] = c0+3;
    }
    if (lev < 3) nb[cnt++] = starts[lev+1] + (i - st)/4;

    size_t rowb = (size_t)(b*LTOT);
    const float2 qv = *(const float2*)(Q + (rowb + i)*512 + h*64 + lane*2);
    float sc[10];
    #pragma unroll
    for (int t = 0; t < 10; t++) {
        if (t < cnt) {
            float2 kv = *(const float2*)(K + (rowb + nb[t])*512 + h*64 + lane*2);
            float p = qv.x*kv.x + qv.y*kv.y;
            #pragma unroll
            for (int o = 16; o; o >>= 1) p += __shfl_xor_sync(0xffffffffu, p, o);
            sc[t] = p * 0.125f;
        } else sc[t] = -1e30f;
    }
    float mx = -1e30f;
    #pragma unroll
    for (int t = 0; t < 10; t++) mx = fmaxf(mx, sc[t]);
    float ssum = 0.f;
    #pragma unroll
    for (int t = 0; t < 10; t++) {
        sc[t] = (t < cnt) ? expf(sc[t] - mx) : 0.f;
        ssum += sc[t];
    }
    float inv = 1.f / ssum;
    float ax = 0.f, ay = 0.f;
    #pragma unroll
    for (int t = 0; t < 10; t++) {
        if (t < cnt) {
            float2 vv = *(const float2*)(V + (rowb + nb[t])*512 + h*64 + lane*2);
            ax += sc[t]*vv.x; ay += sc[t]*vv.y;
        }
    }
    *(float2*)(O + (rowb + i)*512 + h*64 + lane*2) = make_float2(ax*inv, ay*inv);
}

// ---------------- DENSE semantic attention ----------------
#define TSK_PITCH 268
#define ATT_SMEM ((16*68 + 16*1361 + 256*68)*4)
__global__ void __launch_bounds__(256) k_sattn(
        const float* __restrict__ Q, const float* __restrict__ K,
        const float* __restrict__ V, const unsigned char* __restrict__ mask,
        float* __restrict__ O) {
    extern __shared__ float smem[];
    float* Qs = smem;
    float* Ss = smem + 16*68;
    float* Ts = smem + 16*68 + 16*1361;
    __shared__ float rsum[16];
    int tid = threadIdx.x;
    int b = blockIdx.z, h = blockIdx.y, q0 = blockIdx.x << 4;
    size_t rb = (size_t)b * LTOT;
    const float* Qb = Q + rb*512 + h*64;
    const float* Kb = K + rb*512 + h*64;
    const float* Vb = V + rb*512 + h*64;
    const unsigned char* mb = mask + L2SZ*b;
    {
        int qq = tid >> 4, d4 = (tid & 15) << 2;
        *(float4*)&Qs[qq*68 + d4] = *(const float4*)&Qb[(size_t)(q0+qq)*512 + d4];
    }
    int qt = tid & 3, kt = tid >> 2;
    for (int jt = 0; jt < 6; jt++) {
        int jb = jt << 8;
        int jc = LTOT - jb; if (jc > 256) jc = 256;
        __syncthreads();
        for (int slot = tid; slot < (jc << 4); slot += 256) {
            int j = slot >> 4, d4 = (slot & 15) << 2;
            float4 kv = *(const float4*)&Kb[(size_t)(jb+j)*512 + d4];
            Ts[(d4+0)*TSK_PITCH + j] = kv.x;
            Ts[(d4+1)*TSK_PITCH + j] = kv.y;
            Ts[(d4+2)*TSK_PITCH + j] = kv.z;
            Ts[(d4+3)*TSK_PITCH + j] = kv.w;
        }
        __syncthreads();
        float s[4][4] = {};
        #pragma unroll 8
        for (int d = 0; d < 64; d++) {
            float4 kv = *(const float4*)&Ts[d*TSK_PITCH + (kt<<2)];
            float q0v = Qs[(qt*4+0)*68 + d];
            float q1v = Qs[(qt*4+1)*68 + d];
            float q2v = Qs[(qt*4+2)*68 + d];
            float q3v = Qs[(qt*4+3)*68 + d];
            s[0][0]+=q0v*kv.x; s[0][1]+=q0v*kv.y; s[0][2]+=q0v*kv.z; s[0][3]+=q0v*kv.w;
            s[1][0]+=q1v*kv.x; s[1][1]+=q1v*kv.y; s[1][2]+=q1v*kv.z; s[1][3]+=q1v*kv.w;
            s[2][0]+=q2v*kv.x; s[2][1]+=q2v*kv.y; s[2][2]+=q2v*kv.z; s[2][3]+=q2v*kv.w;
            s[3][0]+=q3v*kv.x; s[3][1]+=q3v*kv.y; s[3][2]+=q3v*kv.z; s[3][3]+=q3v*kv.w;
        }
        #pragma unroll
        for (int u = 0; u < 4; u++) {
            int q = qt*4 + u;
            const unsigned char* mrow = mb + (size_t)(q0+q)*LTOT;
            float* srow = Ss + q*1361;
            #pragma unroll
            for (int w = 0; w < 4; w++) {
                int jl = (kt<<2) + w;
                if (jl < jc) {
                    int jg = jb + jl;
                    srow[jg] = mrow[jg] ? -1e30f : s[u][w]*0.125f;
                }
            }
        }
    }
    __syncthreads();
    {
        int w = tid >> 5, lane = tid & 31;
        for (int r = w; r < 16; r += 8) {
            float* row = Ss + r*1361;
            float mx = -1e30f;
            for (int j = lane; j < LTOT; j += 32) mx = fmaxf(mx, row[j]);
            #pragma unroll
            for (int o = 16; o; o >>= 1) mx = fmaxf(mx, __shfl_xor_sync(0xffffffffu, mx, o));
            float sum = 0.f;
            for (int j = lane; j < LTOT; j += 32) {
                float e = expf(row[j] - mx);
                row[j] = e; sum += e;
            }
            #pragma unroll
            for (int o = 16; o; o >>= 1) sum += __shfl_xor_sync(0xffffffffu, sum, o);
            if (lane == 0) rsum[r] = sum;
        }
    }
    int rep = tid >> 6;
    int qt2 = (tid >> 4) & 3;
    int dt  = tid & 15;
    float4 acc[4] = {};
    for (int jt = 0; jt < 6; jt++) {
        int jb = jt << 8;
        int jc = LTOT - jb; if (jc > 256) jc = 256;
        __syncthreads();
        for (int slot = tid; slot < (jc << 4); slot += 256) {
            int j = slot >> 4, d4 = (slot & 15) << 2;
            *(float4*)&Ts[j*68 + d4] = *(const float4*)&Vb[(size_t)(jb+j)*512 + d4];
        }
        __syncthreads();
        int j0 = rep << 6;
        int j1 = j0 + 64; if (j1 > jc) j1 = jc;
        const float* p0r = Ss + (qt2*4+0)*1361 + jb;
        const float* p1r = Ss + (qt2*4+1)*1361 + jb;
        const float* p2r = Ss + (qt2*4+2)*1361 + jb;
        const float* p3r = Ss + (qt2*4+3)*1361 + jb;
        for (int j = j0; j < j1; j++) {
            float4 v4 = *(const float4*)&Ts[j*68 + (dt<<2)];
            float p0 = p0r[j], p1 = p1r[j], p2 = p2r[j], p3 = p3r[j];
            acc[0].x+=p0*v4.x; acc[0].y+=p0*v4.y; acc[0].z+=p0*v4.z; acc[0].w+=p0*v4.w;
            acc[1].x+=p1*v4.x; acc[1].y+=p1*v4.y; acc[1].z+=p1*v4.z; acc[1].w+=p1*v4.w;
            acc[2].x+=p2*v4.x; acc[2].y+=p2*v4.y; acc[2].z+=p2*v4.z; acc[2].w+=p2*v4.w;
            acc[3].x+=p3*v4.x; acc[3].y+=p3*v4.y; acc[3].z+=p3*v4.z; acc[3].w+=p3*v4.w;
        }
    }
    __syncthreads();
    #pragma unroll
    for (int u = 0; u < 4; u++) {
        int q = qt2*4 + u;
        *(float4*)&Ts[((rep*16 + q)*64) + (dt<<2)] = acc[u];
    }
    __syncthreads();
    {
        int q = tid >> 4, d4 = (tid & 15) << 2;
        float4 r0 = *(const float4*)&Ts[(0*16+q)*64 + d4];
        float4 r1 = *(const float4*)&Ts[(1*16+q)*64 + d4];
        float4 r2 = *(const float4*)&Ts[(2*16+q)*64 + d4];
        float4 r3 = *(const float4*)&Ts[(3*16+q)*64 + d4];
        float inv = 1.f / rsum[q];
        float4 o4 = make_float4((r0.x+r1.x+r2.x+r3.x)*inv, (r0.y+r1.y+r2.y+r3.y)*inv,
                                (r0.z+r1.z+r2.z+r3.z)*inv, (r0.w+r1.w+r2.w+r3.w)*inv);
        *(float4*)(O + (rb + q0 + q)*512 + h*64 + d4) = o4;
    }
}

// ---------------- pyramid concat + combine ----------------
__global__ void k_pyrcat(const float* __restrict__ c1, const float* __restrict__ c2,
                         const float* __restrict__ c3, float* __restrict__ out) {
    int idx = blockIdx.x*blockDim.x + threadIdx.x;
    if (idx >= BATCH*336*512) return;
    int d = idx & 511, r = idx >> 9;
    int b = r / 336, p = r % 336;
    float v;
    if (p < 256) v = c1[((size_t)(b*256 + p) << 9) | d];
    else if (p < 320) v = c2[((size_t)(b*64 + p - 256) << 9) | d];
    else v = c3[((size_t)(b*16 + p - 320) << 9) | d];
    out[idx] = v;
}

__global__ void k_comb(const float* __restrict__ t, const float* __restrict__ s,
                       float* __restrict__ x, int n) {
    int i = blockIdx.x*blockDim.x + threadIdx.x;
    if (i < n) x[i] = (t[i] + s[i] + x[i]) * (1.f/3.f);
}

// ---------------- orchestration ----------------
static bf16 *s_ahi, *s_alo, *s_bhi, *s_blo;

static void mgemm(const float* A, const float* B, float* C, const float* bias,
                  int M, int N, int K, int mode) {
    int n4 = M*K/4;
    k_cvtA<<<(n4 + 255)/256, 256>>>(A, s_ahi, s_alo, n4);
    k_cvtB<<<dim3(N/32, K/32), dim3(32, 8)>>>(B, s_bhi, s_blo, K, N);
    dim3 g(N/64, (M + 127)/128);
    k_mgemm<<<g, 256>>>(s_ahi, s_alo, s_bhi, s_blo, C, bias, M, N, K, mode);
}

extern "C" void kernel_launch(void* const* d_in, const int* in_sizes, int n_in,
                              void* d_out, int out_size) {
    const float* x_enc  = (const float*)d_in[0];
    const float* down_W = (const float*)d_in[1];
    const float* down_b = (const float*)d_in[2];
    const float* conv_W = (const float*)d_in[3];
    const float* conv_b = (const float*)d_in[4];
    const float* up_W   = (const float*)d_in[5];
    const float* up_b   = (const float*)d_in[6];
    const float* bc_g   = (const float*)d_in[7];
    const float* bc_b   = (const float*)d_in[8];
    const float* Wq     = (const float*)d_in[9];
    const float* Wk     = (const float*)d_in[10];
    const float* Wv     = (const float*)d_in[11];
    const float* fcW    = (const float*)d_in[12];
    const float* fcb    = (const float*)d_in[13];
    const float* aln_g  = (const float*)d_in[14];
    const float* aln_b  = (const float*)d_in[15];
    const float* W1     = (const float*)d_in[16];
    const float* b1     = (const float*)d_in[17];
    const float* W2     = (const float*)d_in[18];
    const float* b2     = (const float*)d_in[19];
    const float* fln_g  = (const float*)d_in[20];
    const float* fln_b  = (const float*)d_in[21];
    float* out = (float*)d_out;

    float *t0,*c1,*c2,*c3,*pc,*pyr,*x,*q,*k,*v,*q2,*k2,*v2,*o,*o2,*fc,*fc2,
          *tout,*sout,*xn,*h,*wc;
    unsigned char *smk;
    cudaGetSymbolAddress((void**)&t0,  g_t0);
    cudaGetSymbolAddress((void**)&c1,  g_c1);
    cudaGetSymbolAddress((void**)&c2,  g_c2);
    cudaGetSymbolAddress((void**)&c3,  g_c3);
    cudaGetSymbolAddress((void**)&pc,  g_pc);
    cudaGetSymbolAddress((void**)&pyr, g_pyr);
    cudaGetSymbolAddress((void**)&x,   g_x);
    cudaGetSymbolAddress((void**)&q,   g_q);
    cudaGetSymbolAddress((void**)&k,   g_k);
    cudaGetSymbolAddress((void**)&v,   g_v);
    cudaGetSymbolAddress((void**)&q2,  g_q2);
    cudaGetSymbolAddress((void**)&k2,  g_k2);
    cudaGetSymbolAddress((void**)&v2,  g_v2);
    cudaGetSymbolAddress((void**)&o,   g_o);
    cudaGetSymbolAddress((void**)&o2,  g_o2);
    cudaGetSymbolAddress((void**)&fc,  g_fc);
    cudaGetSymbolAddress((void**)&fc2, g_fc2);
    cudaGetSymbolAddress((void**)&tout,g_tout);
    cudaGetSymbolAddress((void**)&sout,g_sout);
    cudaGetSymbolAddress((void**)&xn,  g_xn);
    cudaGetSymbolAddress((void**)&h,   g_h);
    cudaGetSymbolAddress((void**)&wc,  g_wc);
    cudaGetSymbolAddress((void**)&smk, g_sm);
    cudaGetSymbolAddress((void**)&s_ahi, g_ahi);
    cudaGetSymbolAddress((void**)&s_alo, g_alo);
    cudaGetSymbolAddress((void**)&s_bhi, g_bhi);
    cudaGetSymbolAddress((void**)&s_blo, g_blo);

    cudaFuncSetAttribute(k_sattn, cudaFuncAttributeMaxDynamicSharedMemorySize, ATT_SMEM);

    k_convw<<<(3*2048*512 + 255)/256, 256>>>(conv_W, wc);

    // bottleneck
    mgemm(x_enc, down_W, t0, down_b, BATCH*1024, 512, 512, 0);
    mgemm(t0, wc,              c1, conv_b,        BATCH*256, 512, 2048, 2);
    mgemm(c1, wc + 2048*512,   c2, conv_b + 512,  BATCH*64,  512, 2048, 2);
    mgemm(c2, wc + 2*2048*512, c3, conv_b + 1024, BATCH*16,  512, 2048, 2);
    k_pyrcat<<<(BATCH*336*512 + 255)/256, 256>>>(c1, c2, c3, pc);
    mgemm(pc, up_W, pyr, up_b, BATCH*336, 512, 512, 0);
    k_concat_ln<<<NROWS, 256>>>(x_enc, pyr, bc_g, bc_b, x);

    for (int l = 0; l < 2; l++) {
        k_rownorm<<<NROWS, 256>>>(x, xn);
        dim3 tg(LTOT, BATCH);
        k_topk<<<tg, 256>>>(xn, smk);

        size_t wo_t = ((size_t)l*2 + 0)*512*512, wo_s = ((size_t)l*2 + 1)*512*512;
        size_t lo_t = ((size_t)l*2 + 0)*512,     lo_s = ((size_t)l*2 + 1)*512;

        // QKV x6 fused
        {
            int n4 = NROWS*512/4;
            k_cvtA<<<(n4 + 255)/256, 256>>>(x, s_ahi, s_alo, n4);
            k_cvtB_qkv<<<dim3(16, 16, 6), dim3(32, 8)>>>(Wq, Wk, Wv, wo_t, wo_s,
                                                         s_bhi, s_blo);
            dim3 qg(8, (NROWS + 127)/128, 6);
            k_mgemm_qkv<<<qg, 256>>>(s_ahi, s_alo, s_bhi, s_blo,
                                     q, k, v, q2, k2, v2, NROWS, 512, 512);
        }
        dim3 sg(LTOT, BATCH);
        k_tattn<<<sg, 256>>>(q, k, v, o);
        dim3 ag(LTOT/16, 8, BATCH);
        k_sattn<<<ag, 256, ATT_SMEM>>>(q2, k2, v2, smk, o2);

        // fc x2 fused
        {
            int n4 = NROWS*512/4;
            k_cvtA<<<(n4 + 255)/256, 256>>>(o,  s_ahi, s_alo, n4);
            k_cvtA<<<(n4 + 255)/256, 256>>>(o2, s_ahi + (size_t)NROWS*512,
                                                s_alo + (size_t)NROWS*512, n4);
            k_cvtB<<<dim3(16, 16), dim3(32, 8)>>>(fcW + wo_t, s_bhi, s_blo, 512, 512);
            k_cvtB<<<dim3(16, 16), dim3(32, 8)>>>(fcW + wo_s, s_bhi + (size_t)512*512,
                                                  s_blo + (size_t)512*512, 512, 512);
            dim3 fg(8, (NROWS + 127)/128, 2);
            k_mgemm_fc<<<fg, 256>>>(s_ahi, s_alo, s_bhi, s_blo,
                                    fcb, lo_t, lo_s, fc, fc2, NROWS, 512, 512);
        }
        dim3 lg(NROWS, 2);
        k_add_ln2<<<lg, 256>>>(fc, fc2, x, aln_g, aln_b, lo_t, lo_s, tout, sout);
        k_comb<<<(NROWS*512 + 255)/256, 256>>>(tout, sout, x, NROWS*512);

        size_t fo = (size_t)l*512*512, fb = (size_t)l*512;
        mgemm(x, W1 + fo, h, b1 + fb, NROWS, 512, 512, 1);
        mgemm(h, W2 + fo, fc, b2 + fb, NROWS, 512, 512, 0);
        k_add_ln<<<NROWS, 256>>>(fc, x, fln_g + fb, fln_b + fb,
                                 (l == 0) ? x : out, 1e-6f);
    }
}

// round 8
// speedup vs baseline: 2.5274x; 1.2664x over previous
#include <cuda_runtime.h>
#include <cuda_bf16.h>
#include <math.h>
#include <stdint.h>

#define LTOT   1360
#define BATCH  4
#define NROWS  (BATCH*LTOT)          // 5440
#define L2SZ   ((size_t)LTOT*LTOT)
#define SIMB   (1048576 + 65536)     // per-batch sim storage (lvl0 + lvl1)

typedef __nv_bfloat16 bf16;
typedef unsigned int u32;

// ---------------- static device scratch ----------------
__device__ float g_t0[BATCH*1024*512];
__device__ float g_c1[BATCH*256*512];
__device__ float g_c2[BATCH*64*512];
__device__ float g_c3[BATCH*16*512];
__device__ float g_pc[BATCH*336*512];
__device__ float g_pyr[BATCH*336*512];
__device__ float g_x[NROWS*512];
__device__ float g_q[NROWS*512];
__device__ float g_k[NROWS*512];
__device__ float g_v[NROWS*512];
__device__ float g_q2[NROWS*512];
__device__ float g_k2[NROWS*512];
__device__ float g_v2[NROWS*512];
__device__ float g_o[NROWS*512];
__device__ float g_o2[NROWS*512];
__device__ float g_fc[NROWS*512];
__device__ float g_fc2[NROWS*512];
__device__ float g_tout[NROWS*512];
__device__ float g_sout[NROWS*512];
__device__ float g_xn[NROWS*512];
__device__ float g_h[NROWS*512];
__device__ float g_wc[3*2048*512];
__device__ bf16 g_ahi[2*NROWS*512];
__device__ bf16 g_alo[2*NROWS*512];
__device__ bf16 g_bhi[6*512*512];
__device__ bf16 g_blo[6*512*512];
__device__ float g_sim[(size_t)BATCH*SIMB];
__device__ unsigned char g_sm[(size_t)BATCH*LTOT*LTOT];

// ---------------- fp32 -> bf16 hi/lo (flat) ----------------
__global__ void k_cvtA(const float* __restrict__ s, bf16* __restrict__ hi,
                       bf16* __restrict__ lo, int n4) {
    int i = blockIdx.x*blockDim.x + threadIdx.x;
    if (i >= n4) return;
    float4 v = ((const float4*)s)[i];
    bf16 h0=__float2bfloat16(v.x), h1=__float2bfloat16(v.y),
         h2=__float2bfloat16(v.z), h3=__float2bfloat16(v.w);
    bf16 l0=__float2bfloat16(v.x-__bfloat162float(h0)),
         l1=__float2bfloat16(v.y-__bfloat162float(h1)),
         l2=__float2bfloat16(v.z-__bfloat162float(h2)),
         l3=__float2bfloat16(v.w-__bfloat162float(h3));
    uint2 hp = make_uint2((u32)__bfloat16_as_ushort(h0) | ((u32)__bfloat16_as_ushort(h1)<<16),
                          (u32)__bfloat16_as_ushort(h2) | ((u32)__bfloat16_as_ushort(h3)<<16));
    uint2 lp = make_uint2((u32)__bfloat16_as_ushort(l0) | ((u32)__bfloat16_as_ushort(l1)<<16),
                          (u32)__bfloat16_as_ushort(l2) | ((u32)__bfloat16_as_ushort(l3)<<16));
    ((uint2*)hi)[i] = hp;
    ((uint2*)lo)[i] = lp;
}

// ---------------- fp32 [K][N] -> bf16 hi/lo transposed [N][K] ----------------
__device__ __forceinline__ void cvtB_body(const float* __restrict__ src,
        bf16* __restrict__ hi, bf16* __restrict__ lo, int K, int N) {
    __shared__ float t[32][33];
    int tx = threadIdx.x, ty = threadIdx.y;
    int n0 = blockIdx.x*32, k0 = blockIdx.y*32;
    #pragma unroll
    for (int i = 0; i < 4; i++)
        t[ty + i*8][tx] = src[(size_t)(k0 + ty + i*8)*N + n0 + tx];
    __syncthreads();
    #pragma unroll
    for (int i = 0; i < 4; i++) {
        float v = t[tx][ty + i*8];
        int n = n0 + ty + i*8, kk = k0 + tx;
        bf16 h = __float2bfloat16(v);
        bf16 l = __float2bfloat16(v - __bfloat162float(h));
        hi[(size_t)n*K + kk] = h;
        lo[(size_t)n*K + kk] = l;
    }
}
__global__ void k_cvtB(const float* __restrict__ src, bf16* hi, bf16* lo, int K, int N) {
    cvtB_body(src, hi, lo, K, N);
}
__global__ void k_cvtB_qkv(const float* __restrict__ Wq, const float* __restrict__ Wk,
                           const float* __restrict__ Wv, size_t wo_t, size_t wo_s,
                           bf16* hi, bf16* lo) {
    int z = blockIdx.z;
    const float* base = ((z%3 == 0) ? Wq : (z%3 == 1) ? Wk : Wv) + ((z/3) ? wo_s : wo_t);
    cvtB_body(base, hi + (size_t)z*512*512, lo + (size_t)z*512*512, 512, 512);
}

// ---------------- bf16x3 MMA GEMM: 128x64 tile, 8 warps ----------------
__device__ __forceinline__ void mma16816(float* d, const u32* a, const u32* b) {
    asm volatile(
        "mma.sync.aligned.m16n8k16.row.col.f32.bf16.bf16.f32 "
        "{%0,%1,%2,%3}, {%4,%5,%6,%7}, {%8,%9}, {%0,%1,%2,%3};"
        : "+f"(d[0]), "+f"(d[1]), "+f"(d[2]), "+f"(d[3])
        : "r"(a[0]), "r"(a[1]), "r"(a[2]), "r"(a[3]), "r"(b[0]), "r"(b[1]));
}
#define AP 40
// mode: 0 none, 1 relu, 2 scale+elu
__device__ void mg_body(const bf16* __restrict__ Ahi, const bf16* __restrict__ Alo,
                        const bf16* __restrict__ Bhi, const bf16* __restrict__ Blo,
                        float* __restrict__ C, const float* __restrict__ bias,
                        int M, int N, int K, int mode) {
    __shared__ bf16 As[2][128*AP];
    __shared__ bf16 Bs[2][64*AP];
    int tid = threadIdx.x, wid = tid >> 5, lane = tid & 31;
    int wm = wid >> 1, wn = wid & 1, g = lane >> 2, qp = lane & 3;
    int row0 = blockIdx.y << 7, col0 = blockIdx.x << 6;
    float acc[2][4][4] = {};
    for (int kc = 0; kc < K; kc += 32) {
        #pragma unroll
        for (int s = tid; s < 512; s += 256) {
            int r = s >> 2, k8 = (s & 3) << 3;
            int gr = row0 + r;
            float4 vh = make_float4(0,0,0,0), vl = vh;
            if (gr < M) {
                vh = *(const float4*)(Ahi + (size_t)gr*K + kc + k8);
                vl = *(const float4*)(Alo + (size_t)gr*K + kc + k8);
            }
            *(float4*)&As[0][r*AP + k8] = vh;
            *(float4*)&As[1][r*AP + k8] = vl;
        }
        if (tid < 256) {
            int s = tid;
            int r = s >> 2, k8 = (s & 3) << 3;
            int gn = col0 + r;
            float4 vh = *(const float4*)(Bhi + (size_t)gn*K + kc + k8);
            float4 vl = *(const float4*)(Blo + (size_t)gn*K + kc + k8);
            *(float4*)&Bs[0][r*AP + k8] = vh;
            *(float4*)&Bs[1][r*AP + k8] = vl;
        }
        __syncthreads();
        #pragma unroll
        for (int ks = 0; ks < 32; ks += 16) {
            u32 ah[2][4], al[2][4], bh[4][2], bl[4][2];
            #pragma unroll
            for (int mt = 0; mt < 2; mt++) {
                int ar = (wm*32 + mt*16 + g)*AP + ks + qp*2;
                int ar8 = ar + 8*AP;
                ah[mt][0] = *(u32*)&As[0][ar];     ah[mt][1] = *(u32*)&As[0][ar8];
                ah[mt][2] = *(u32*)&As[0][ar + 8]; ah[mt][3] = *(u32*)&As[0][ar8 + 8];
                al[mt][0] = *(u32*)&As[1][ar];     al[mt][1] = *(u32*)&As[1][ar8];
                al[mt][2] = *(u32*)&As[1][ar + 8]; al[mt][3] = *(u32*)&As[1][ar8 + 8];
            }
            #pragma unroll
            for (int nt = 0; nt < 4; nt++) {
                int br = (wn*32 + nt*8 + g)*AP + ks + qp*2;
                bh[nt][0] = *(u32*)&Bs[0][br]; bh[nt][1] = *(u32*)&Bs[0][br + 8];
                bl[nt][0] = *(u32*)&Bs[1][br]; bl[nt][1] = *(u32*)&Bs[1][br + 8];
            }
            #pragma unroll
            for (int mt = 0; mt < 2; mt++)
                #pragma unroll
                for (int nt = 0; nt < 4; nt++) {
                    mma16816(acc[mt][nt], ah[mt], bh[nt]);
                    mma16816(acc[mt][nt], ah[mt], bl[nt]);
                    mma16816(acc[mt][nt], al[mt], bh[nt]);
                }
        }
        __syncthreads();
    }
    #pragma unroll
    for (int mt = 0; mt < 2; mt++) {
        int r0 = row0 + wm*32 + mt*16 + g;
        #pragma unroll
        for (int half = 0; half < 2; half++) {
            int r = r0 + half*8;
            if (r >= M) continue;
            #pragma unroll
            for (int nt = 0; nt < 4; nt++) {
                int cl = col0 + wn*32 + nt*8 + qp*2;
                float v0 = acc[mt][nt][half*2 + 0], v1 = acc[mt][nt][half*2 + 1];
                if (bias) { v0 += bias[cl]; v1 += bias[cl + 1]; }
                if (mode == 1) { v0 = fmaxf(v0, 0.f); v1 = fmaxf(v1, 0.f); }
                else if (mode == 2) {
                    v0 *= 0.9999950000374997f; if (v0 <= 0.f) v0 = expm1f(v0);
                    v1 *= 0.9999950000374997f; if (v1 <= 0.f) v1 = expm1f(v1);
                }
                *(float2*)&C[(size_t)r*N + cl] = make_float2(v0, v1);
            }
        }
    }
}

__global__ void __launch_bounds__(256) k_mgemm(
        const bf16* Ahi, const bf16* Alo, const bf16* Bhi, const bf16* Blo,
        float* C, const float* bias, int M, int N, int K, int mode) {
    mg_body(Ahi, Alo, Bhi, Blo, C, bias, M, N, K, mode);
}
__global__ void __launch_bounds__(256) k_mgemm_qkv(
        const bf16* Ahi, const bf16* Alo, const bf16* Bhi, const bf16* Blo,
        float* q, float* k, float* v, float* q2, float* k2, float* v2,
        int M, int N, int K) {
    int z = blockIdx.z;
    size_t bo = (size_t)z*512*512;
    float* C = (z==0)?q:(z==1)?k:(z==2)?v:(z==3)?q2:(z==4)?k2:v2;
    mg_body(Ahi, Alo, Bhi + bo, Blo + bo, C, nullptr, M, N, K, 0);
}
__global__ void __launch_bounds__(256) k_mgemm_fc(
        const bf16* Ahi, const bf16* Alo, const bf16* Bhi, const bf16* Blo,
        const float* fcb, size_t lo_t, size_t lo_s,
        float* ft, float* fs, int M, int N, int K) {
    int z = blockIdx.z;
    size_t ao = (size_t)z*NROWS*512, bo = (size_t)z*512*512;
    mg_body(Ahi + ao, Alo + ao, Bhi + bo, Blo + bo, z ? fs : ft,
            fcb + (z ? lo_s : lo_t), M, N, K, 0);
}
// sim Gram GEMM: A and B are the SAME xn rows (k-major), per batch (grid.z)
__global__ void __launch_bounds__(256) k_mgemm_sim(
        const bf16* Ahi, const bf16* Alo, int startRow, int n, size_t lvloff,
        float* simbuf) {
    int b = blockIdx.z;
    size_t ao = ((size_t)(b*LTOT + startRow))*512;
    float* C = simbuf + (size_t)b*SIMB + lvloff;
    mg_body(Ahi + ao, Alo + ao, Ahi + ao, Alo + ao, C, nullptr, n, n, 512, 0);
}

// ---------------- conv weight re-layout ----------------
__global__ void k_convw(const float* __restrict__ w, float* __restrict__ wm) {
    int idx = blockIdx.x*blockDim.x + threadIdx.x;
    if (idx >= 3*2048*512) return;
    int l  = idx / (2048*512);
    int r  = idx - l*2048*512;
    int kk = r >> 9, co = r & 511;
    int t  = kk >> 9, ci = kk & 511;
    wm[idx] = w[(((size_t)(l*512 + co))*512 + ci)*4 + t];
}

// ---------------- block reduce (256 thr) ----------------
__device__ __forceinline__ float block_sum256(float v) {
    __shared__ float red[8];
    int lane = threadIdx.x & 31, w = threadIdx.x >> 5;
    #pragma unroll
    for (int o = 16; o; o >>= 1) v += __shfl_xor_sync(0xffffffffu, v, o);
    if (lane == 0) red[w] = v;
    __syncthreads();
    if (w == 0) {
        float t = (lane < 8) ? red[lane] : 0.f;
        #pragma unroll
        for (int o = 4; o; o >>= 1) t += __shfl_xor_sync(0xffffffffu, t, o);
        if (lane == 0) red[0] = t;
    }
    __syncthreads();
    float r = red[0];
    __syncthreads();
    return r;
}

// ---------------- concat + LN(1e-5) ----------------
__global__ void __launch_bounds__(256) k_concat_ln(
        const float* __restrict__ xe, const float* __restrict__ pyr,
        const float* __restrict__ g, const float* __restrict__ bt,
        float* __restrict__ out) {
    int row = blockIdx.x;
    int b = row / LTOT, i = row % LTOT;
    const float* src = (i < 1024) ? xe + ((size_t)(b*1024 + i))*512
                                  : pyr + ((size_t)(b*336 + (i - 1024)))*512;
    int t = threadIdx.x;
    float v0 = src[t], v1 = src[t + 256];
    float mu = block_sum256(v0 + v1) * (1.f/512.f);
    float d0 = v0 - mu, d1 = v1 - mu;
    float var = block_sum256(d0*d0 + d1*d1) * (1.f/512.f);
    float rs = rsqrtf(var + 1e-5f);
    float* o = out + (size_t)row*512;
    o[t]       = d0*rs*g[t]       + bt[t];
    o[t + 256] = d1*rs*g[t + 256] + bt[t + 256];
}

// ---------------- (a+res) -> LN ----------------
__global__ void __launch_bounds__(256) k_add_ln(
        const float* __restrict__ a, const float* __restrict__ res,
        const float* __restrict__ g, const float* __restrict__ bt,
        float* __restrict__ out, float eps) {
    int row = blockIdx.x, t = threadIdx.x;
    const float* pa = a + (size_t)row*512;
    const float* pr = res + (size_t)row*512;
    float v0 = pa[t] + pr[t], v1 = pa[t + 256] + pr[t + 256];
    float mu = block_sum256(v0 + v1) * (1.f/512.f);
    float d0 = v0 - mu, d1 = v1 - mu;
    float var = block_sum256(d0*d0 + d1*d1) * (1.f/512.f);
    float rs = rsqrtf(var + eps);
    float* o = out + (size_t)row*512;
    o[t]       = d0*rs*g[t]       + bt[t];
    o[t + 256] = d1*rs*g[t + 256] + bt[t + 256];
}

// two-branch add_ln
__global__ void __launch_bounds__(256) k_add_ln2(
        const float* __restrict__ at, const float* __restrict__ as_,
        const float* __restrict__ res,
        const float* __restrict__ g, const float* __restrict__ bt,
        size_t lo_t, size_t lo_s,
        float* __restrict__ ot, float* __restrict__ os_) {
    int s = blockIdx.y;
    const float* a = s ? as_ : at;
    const float* gg = g + (s ? lo_s : lo_t);
    const float* bb = bt + (s ? lo_s : lo_t);
    float* out = s ? os_ : ot;
    int row = blockIdx.x, t = threadIdx.x;
    const float* pa = a + (size_t)row*512;
    const float* pr = res + (size_t)row*512;
    float v0 = pa[t] + pr[t], v1 = pa[t + 256] + pr[t + 256];
    float mu = block_sum256(v0 + v1) * (1.f/512.f);
    float d0 = v0 - mu, d1 = v1 - mu;
    float var = block_sum256(d0*d0 + d1*d1) * (1.f/512.f);
    float rs = rsqrtf(var + 1e-6f);
    float* o = out + (size_t)row*512;
    o[t]       = d0*rs*gg[t]       + bb[t];
    o[t + 256] = d1*rs*gg[t + 256] + bb[t + 256];
}

// ---------------- row L2 normalize ----------------
__global__ void __launch_bounds__(256) k_rownorm(
        const float* __restrict__ x, float* __restrict__ xn) {
    int row = blockIdx.x, t = threadIdx.x;
    const float* p = x + (size_t)row*512;
    float v0 = p[t], v1 = p[t + 256];
    float ss = block_sum256(v0*v0 + v1*v1);
    float inv = 1.f / fmaxf(sqrtf(ss), 1e-8f);
    float* o = xn + (size_t)row*512;
    o[t] = v0*inv; o[t + 256] = v1*inv;
}

// ---------------- top-k select from precomputed sims (lvl<=1) ----------------
__global__ void __launch_bounds__(256) k_topksel(
        const float* __restrict__ xn, const float* __restrict__ simbuf,
        unsigned char* __restrict__ smask) {
    int i = blockIdx.x, b = blockIdx.y, tid = threadIdx.x;
    const int starts[4] = {0,1024,1280,1344};
    const int sizes[4]  = {1024,256,64,16};
    int lev = (i<1024)?0:(i<1280)?1:(i<1344)?2:3;
    int st = starts[lev], n = sizes[lev];
    int kk = n < 32 ? n : 32;
    __shared__ float sims[1024];
    __shared__ float qrow[512];
    __shared__ float wv[8]; __shared__ int wi[8];
    unsigned char* mrow = smask + ((size_t)b*LTOT + i)*LTOT + st;
    for (int j = tid; j < n; j += 256) mrow[j] = 0;
    if (lev <= 1) {
        size_t lvloff = (lev == 0) ? 0 : 1048576;
        const float* srow = simbuf + (size_t)b*SIMB + lvloff + (size_t)(i - st)*n;
        for (int j = tid; j < n; j += 256) sims[j] = srow[j];
        __syncthreads();
    } else {
        const float* xb = xn + (size_t)b*LTOT*512;
        for (int d = tid; d < 512; d += 256) qrow[d] = xb[(size_t)i*512 + d];
        __syncthreads();
        int w = tid >> 5, lane = tid & 31;
        for (int j = w; j < n; j += 8) {
            const float* rj = xb + (size_t)(st + j)*512;
            float p = 0.f;
            #pragma unroll 4
            for (int d = lane; d < 512; d += 32) p += qrow[d]*rj[d];
            #pragma unroll
            for (int o = 16; o; o >>= 1) p += __shfl_xor_sync(0xffffffffu, p, o);
            if (lane == 0) sims[j] = p;
        }
        __syncthreads();
    }
    int w = tid >> 5, lane = tid & 31;
    for (int it = 0; it < kk; it++) {
        float bv = -3.f; int bi = n;
        for (int j = tid; j < n; j += 256) {
            float v = sims[j];
            if (v > bv) { bv = v; bi = j; }
        }
        #pragma unroll
        for (int o = 16; o; o >>= 1) {
            float ov = __shfl_xor_sync(0xffffffffu, bv, o);
            int   oi = __shfl_xor_sync(0xffffffffu, bi, o);
            if (ov > bv || (ov == bv && oi < bi)) { bv = ov; bi = oi; }
        }
        if (lane == 0) { wv[w] = bv; wi[w] = bi; }
        __syncthreads();
        if (tid == 0) {
            float fv = wv[0]; int fi = wi[0];
            #pragma unroll
            for (int z = 1; z < 8; z++)
                if (wv[z] > fv || (wv[z] == fv && wi[z] < fi)) { fv = wv[z]; fi = wi[z]; }
            mrow[fi] = 1;
            sims[fi] = -3.f;
        }
        __syncthreads();
    }
}

// ---------------- SPARSE temporal attention ----------------
__global__ void __launch_bounds__(256) k_tattn(
        const float* __restrict__ Q, const float* __restrict__ K,
        const float* __restrict__ V, float* __restrict__ O) {
    int i = blockIdx.x, b = blockIdx.y;
    int h = threadIdx.x >> 5, lane = threadIdx.x & 31;
    const int starts[4] = {0,1024,1280,1344};
    const int sizes[4]  = {1024,256,64,16};
    int lev = (i<1024)?0:(i<1280)?1:(i<1344)?2:3;
    int st = starts[lev], n = sizes[lev];
    int nb[10]; int cnt = 0;
    int lo = (i-2 < st) ? st : i-2;
    int hi = (i+2 > st+n-1) ? st+n-1 : i+2;
    for (int j = lo; j <= hi; j++) nb[cnt++] = j;
    if (lev > 0) {
        int c0 = starts[lev-1] + (i - st)*4;
        nb[cnt++] = c0; nb[cnt++] = c0+1; nb[cnt++] = c0+2; nb[cnt++] = c0+3;
    }
    if (lev < 3) nb[cnt++] = starts[lev+1] + (i - st)/4;

    size_t rowb = (size_t)(b*LTOT);
    const float2 qv = *(const float2*)(Q + (rowb + i)*512 + h*64 + lane*2);
    float sc[10];
    #pragma unroll
    for (int t = 0; t < 10; t++) {
        if (t < cnt) {
            float2 kv = *(const float2*)(K + (rowb + nb[t])*512 + h*64 + lane*2);
            float p = qv.x*kv.x + qv.y*kv.y;
            #pragma unroll
            for (int o = 16; o; o >>= 1) p += __shfl_xor_sync(0xffffffffu, p, o);
            sc[t] = p * 0.125f;
        } else sc[t] = -1e30f;
    }
    float mx = -1e30f;
    #pragma unroll
    for (int t = 0; t < 10; t++) mx = fmaxf(mx, sc[t]);
    float ssum = 0.f;
    #pragma unroll
    for (int t = 0; t < 10; t++) {
        sc[t] = (t < cnt) ? expf(sc[t] - mx) : 0.f;
        ssum += sc[t];
    }
    float inv = 1.f / ssum;
    float ax = 0.f, ay = 0.f;
    #pragma unroll
    for (int t = 0; t < 10; t++) {
        if (t < cnt) {
            float2 vv = *(const float2*)(V + (rowb + nb[t])*512 + h*64 + lane*2);
            ax += sc[t]*vv.x; ay += sc[t]*vv.y;
        }
    }
    *(float2*)(O + (rowb + i)*512 + h*64 + lane*2) = make_float2(ax*inv, ay*inv);
}

// ---------------- DENSE semantic attention ----------------
#define TSK_PITCH 268
#define ATT_SMEM ((16*68 + 16*1361 + 256*68)*4)
__global__ void __launch_bounds__(256) k_sattn(
        const float* __restrict__ Q, const float* __restrict__ K,
        const float* __restrict__ V, const unsigned char* __restrict__ mask,
        float* __restrict__ O) {
    extern __shared__ float smem[];
    float* Qs = smem;
    float* Ss = smem + 16*68;
    float* Ts = smem + 16*68 + 16*1361;
    __shared__ float rsum[16];
    int tid = threadIdx.x;
    int b = blockIdx.z, h = blockIdx.y, q0 = blockIdx.x << 4;
    size_t rb = (size_t)b * LTOT;
    const float* Qb = Q + rb*512 + h*64;
    const float* Kb = K + rb*512 + h*64;
    const float* Vb = V + rb*512 + h*64;
    const unsigned char* mb = mask + L2SZ*b;
    {
        int qq = tid >> 4, d4 = (tid & 15) << 2;
        *(float4*)&Qs[qq*68 + d4] = *(const float4*)&Qb[(size_t)(q0+qq)*512 + d4];
    }
    int qt = tid & 3, kt = tid >> 2;
    for (int jt = 0; jt < 6; jt++) {
        int jb = jt << 8;
        int jc = LTOT - jb; if (jc > 256) jc = 256;
        __syncthreads();
        for (int slot = tid; slot < (jc << 4); slot += 256) {
            int j = slot >> 4, d4 = (slot & 15) << 2;
            float4 kv = *(const float4*)&Kb[(size_t)(jb+j)*512 + d4];
            Ts[(d4+0)*TSK_PITCH + j] = kv.x;
            Ts[(d4+1)*TSK_PITCH + j] = kv.y;
            Ts[(d4+2)*TSK_PITCH + j] = kv.z;
            Ts[(d4+3)*TSK_PITCH + j] = kv.w;
        }
        __syncthreads();
        float s[4][4] = {};
        #pragma unroll 8
        for (int d = 0; d < 64; d++) {
            float4 kv = *(const float4*)&Ts[d*TSK_PITCH + (kt<<2)];
            float q0v = Qs[(qt*4+0)*68 + d];
            float q1v = Qs[(qt*4+1)*68 + d];
            float q2v = Qs[(qt*4+2)*68 + d];
            float q3v = Qs[(qt*4+3)*68 + d];
            s[0][0]+=q0v*kv.x; s[0][1]+=q0v*kv.y; s[0][2]+=q0v*kv.z; s[0][3]+=q0v*kv.w;
            s[1][0]+=q1v*kv.x; s[1][1]+=q1v*kv.y; s[1][2]+=q1v*kv.z; s[1][3]+=q1v*kv.w;
            s[2][0]+=q2v*kv.x; s[2][1]+=q2v*kv.y; s[2][2]+=q2v*kv.z; s[2][3]+=q2v*kv.w;
            s[3][0]+=q3v*kv.x; s[3][1]+=q3v*kv.y; s[3][2]+=q3v*kv.z; s[3][3]+=q3v*kv.w;
        }
        #pragma unroll
        for (int u = 0; u < 4; u++) {
            int q = qt*4 + u;
            const unsigned char* mrow = mb + (size_t)(q0+q)*LTOT;
            float* srow = Ss + q*1361;
            #pragma unroll
            for (int w = 0; w < 4; w++) {
                int jl = (kt<<2) + w;
                if (jl < jc) {
                    int jg = jb + jl;
                    srow[jg] = mrow[jg] ? -1e30f : s[u][w]*0.125f;
                }
            }
        }
    }
    __syncthreads();
    {
        int w = tid >> 5, lane = tid & 31;
        for (int r = w; r < 16; r += 8) {
            float* row = Ss + r*1361;
            float mx = -1e30f;
            for (int j = lane; j < LTOT; j += 32) mx = fmaxf(mx, row[j]);
            #pragma unroll
            for (int o = 16; o; o >>= 1) mx = fmaxf(mx, __shfl_xor_sync(0xffffffffu, mx, o));
            float sum = 0.f;
            for (int j = lane; j < LTOT; j += 32) {
                float e = expf(row[j] - mx);
                row[j] = e; sum += e;
            }
            #pragma unroll
            for (int o = 16; o; o >>= 1) sum += __shfl_xor_sync(0xffffffffu, sum, o);
            if (lane == 0) rsum[r] = sum;
        }
    }
    int rep = tid >> 6;
    int qt2 = (tid >> 4) & 3;
    int dt  = tid & 15;
    float4 acc[4] = {};
    for (int jt = 0; jt < 6; jt++) {
        int jb = jt << 8;
        int jc = LTOT - jb; if (jc > 256) jc = 256;
        __syncthreads();
        for (int slot = tid; slot < (jc << 4); slot += 256) {
            int j = slot >> 4, d4 = (slot & 15) << 2;
            *(float4*)&Ts[j*68 + d4] = *(const float4*)&Vb[(size_t)(jb+j)*512 + d4];
        }
        __syncthreads();
        int j0 = rep << 6;
        int j1 = j0 + 64; if (j1 > jc) j1 = jc;
        const float* p0r = Ss + (qt2*4+0)*1361 + jb;
        const float* p1r = Ss + (qt2*4+1)*1361 + jb;
        const float* p2r = Ss + (qt2*4+2)*1361 + jb;
        const float* p3r = Ss + (qt2*4+3)*1361 + jb;
        for (int j = j0; j < j1; j++) {
            float4 v4 = *(const float4*)&Ts[j*68 + (dt<<2)];
            float p0 = p0r[j], p1 = p1r[j], p2 = p2r[j], p3 = p3r[j];
            acc[0].x+=p0*v4.x; acc[0].y+=p0*v4.y; acc[0].z+=p0*v4.z; acc[0].w+=p0*v4.w;
            acc[1].x+=p1*v4.x; acc[1].y+=p1*v4.y; acc[1].z+=p1*v4.z; acc[1].w+=p1*v4.w;
            acc[2].x+=p2*v4.x; acc[2].y+=p2*v4.y; acc[2].z+=p2*v4.z; acc[2].w+=p2*v4.w;
            acc[3].x+=p3*v4.x; acc[3].y+=p3*v4.y; acc[3].z+=p3*v4.z; acc[3].w+=p3*v4.w;
        }
    }
    __syncthreads();
    #pragma unroll
    for (int u = 0; u < 4; u++) {
        int q = qt2*4 + u;
        *(float4*)&Ts[((rep*16 + q)*64) + (dt<<2)] = acc[u];
    }
    __syncthreads();
    {
        int q = tid >> 4, d4 = (tid & 15) << 2;
        float4 r0 = *(const float4*)&Ts[(0*16+q)*64 + d4];
        float4 r1 = *(const float4*)&Ts[(1*16+q)*64 + d4];
        float4 r2 = *(const float4*)&Ts[(2*16+q)*64 + d4];
        float4 r3 = *(const float4*)&Ts[(3*16+q)*64 + d4];
        float inv = 1.f / rsum[q];
        float4 o4 = make_float4((r0.x+r1.x+r2.x+r3.x)*inv, (r0.y+r1.y+r2.y+r3.y)*inv,
                                (r0.z+r1.z+r2.z+r3.z)*inv, (r0.w+r1.w+r2.w+r3.w)*inv);
        *(float4*)(O + (rb + q0 + q)*512 + h*64 + d4) = o4;
    }
}

// ---------------- pyramid concat + combine ----------------
__global__ void k_pyrcat(const float* __restrict__ c1, const float* __restrict__ c2,
                         const float* __restrict__ c3, float* __restrict__ out) {
    int idx = blockIdx.x*blockDim.x + threadIdx.x;
    if (idx >= BATCH*336*512) return;
    int d = idx & 511, r = idx >> 9;
    int b = r / 336, p = r % 336;
    float v;
    if (p < 256) v = c1[((size_t)(b*256 + p) << 9) | d];
    else if (p < 320) v = c2[((size_t)(b*64 + p - 256) << 9) | d];
    else v = c3[((size_t)(b*16 + p - 320) << 9) | d];
    out[idx] = v;
}

__global__ void k_comb(const float* __restrict__ t, const float* __restrict__ s,
                       float* __restrict__ x, int n) {
    int i = blockIdx.x*blockDim.x + threadIdx.x;
    if (i < n) x[i] = (t[i] + s[i] + x[i]) * (1.f/3.f);
}

// ---------------- orchestration ----------------
static bf16 *s_ahi, *s_alo, *s_bhi, *s_blo;

static void mgemm(const float* A, const float* B, float* C, const float* bias,
                  int M, int N, int K, int mode) {
    int n4 = M*K/4;
    k_cvtA<<<(n4 + 255)/256, 256>>>(A, s_ahi, s_alo, n4);
    k_cvtB<<<dim3(N/32, K/32), dim3(32, 8)>>>(B, s_bhi, s_blo, K, N);
    dim3 g(N/64, (M + 127)/128);
    k_mgemm<<<g, 256>>>(s_ahi, s_alo, s_bhi, s_blo, C, bias, M, N, K, mode);
}

extern "C" void kernel_launch(void* const* d_in, const int* in_sizes, int n_in,
                              void* d_out, int out_size) {
    const float* x_enc  = (const float*)d_in[0];
    const float* down_W = (const float*)d_in[1];
    const float* down_b = (const float*)d_in[2];
    const float* conv_W = (const float*)d_in[3];
    const float* conv_b = (const float*)d_in[4];
    const float* up_W   = (const float*)d_in[5];
    const float* up_b   = (const float*)d_in[6];
    const float* bc_g   = (const float*)d_in[7];
    const float* bc_b   = (const float*)d_in[8];
    const float* Wq     = (const float*)d_in[9];
    const float* Wk     = (const float*)d_in[10];
    const float* Wv     = (const float*)d_in[11];
    const float* fcW    = (const float*)d_in[12];
    const float* fcb    = (const float*)d_in[13];
    const float* aln_g  = (const float*)d_in[14];
    const float* aln_b  = (const float*)d_in[15];
    const float* W1     = (const float*)d_in[16];
    const float* b1     = (const float*)d_in[17];
    const float* W2     = (const float*)d_in[18];
    const float* b2     = (const float*)d_in[19];
    const float* fln_g  = (const float*)d_in[20];
    const float* fln_b  = (const float*)d_in[21];
    float* out = (float*)d_out;

    float *t0,*c1,*c2,*c3,*pc,*pyr,*x,*q,*k,*v,*q2,*k2,*v2,*o,*o2,*fc,*fc2,
          *tout,*sout,*xn,*h,*wc,*sim;
    unsigned char *smk;
    cudaGetSymbolAddress((void**)&t0,  g_t0);
    cudaGetSymbolAddress((void**)&c1,  g_c1);
    cudaGetSymbolAddress((void**)&c2,  g_c2);
    cudaGetSymbolAddress((void**)&c3,  g_c3);
    cudaGetSymbolAddress((void**)&pc,  g_pc);
    cudaGetSymbolAddress((void**)&pyr, g_pyr);
    cudaGetSymbolAddress((void**)&x,   g_x);
    cudaGetSymbolAddress((void**)&q,   g_q);
    cudaGetSymbolAddress((void**)&k,   g_k);
    cudaGetSymbolAddress((void**)&v,   g_v);
    cudaGetSymbolAddress((void**)&q2,  g_q2);
    cudaGetSymbolAddress((void**)&k2,  g_k2);
    cudaGetSymbolAddress((void**)&v2,  g_v2);
    cudaGetSymbolAddress((void**)&o,   g_o);
    cudaGetSymbolAddress((void**)&o2,  g_o2);
    cudaGetSymbolAddress((void**)&fc,  g_fc);
    cudaGetSymbolAddress((void**)&fc2, g_fc2);
    cudaGetSymbolAddress((void**)&tout,g_tout);
    cudaGetSymbolAddress((void**)&sout,g_sout);
    cudaGetSymbolAddress((void**)&xn,  g_xn);
    cudaGetSymbolAddress((void**)&h,   g_h);
    cudaGetSymbolAddress((void**)&wc,  g_wc);
    cudaGetSymbolAddress((void**)&sim, g_sim);
    cudaGetSymbolAddress((void**)&smk, g_sm);
    cudaGetSymbolAddress((void**)&s_ahi, g_ahi);
    cudaGetSymbolAddress((void**)&s_alo, g_alo);
    cudaGetSymbolAddress((void**)&s_bhi, g_bhi);
    cudaGetSymbolAddress((void**)&s_blo, g_blo);

    cudaFuncSetAttribute(k_sattn, cudaFuncAttributeMaxDynamicSharedMemorySize, ATT_SMEM);

    k_convw<<<(3*2048*512 + 255)/256, 256>>>(conv_W, wc);

    // bottleneck
    mgemm(x_enc, down_W, t0, down_b, BATCH*1024, 512, 512, 0);
    mgemm(t0, wc,              c1, conv_b,        BATCH*256, 512, 2048, 2);
    mgemm(c1, wc + 2048*512,   c2, conv_b + 512,  BATCH*64,  512, 2048, 2);
    mgemm(c2, wc + 2*2048*512, c3, conv_b + 1024, BATCH*16,  512, 2048, 2);
    k_pyrcat<<<(BATCH*336*512 + 255)/256, 256>>>(c1, c2, c3, pc);
    mgemm(pc, up_W, pyr, up_b, BATCH*336, 512, 512, 0);
    k_concat_ln<<<NROWS, 256>>>(x_enc, pyr, bc_g, bc_b, x);

    for (int l = 0; l < 2; l++) {
        // ---- semantic mask: Gram sims via tensor GEMM, then select ----
        k_rownorm<<<NROWS, 256>>>(x, xn);
        {
            int n4 = NROWS*512/4;
            k_cvtA<<<(n4 + 255)/256, 256>>>(xn, s_ahi, s_alo, n4);
            dim3 g0(1024/64, 1024/128, BATCH);
            k_mgemm_sim<<<g0, 256>>>(s_ahi, s_alo, 0,    1024, 0,       sim);
            dim3 g1(256/64, 256/128, BATCH);
            k_mgemm_sim<<<g1, 256>>>(s_ahi, s_alo, 1024, 256,  1048576, sim);
            dim3 tg(LTOT, BATCH);
            k_topksel<<<tg, 256>>>(xn, sim, smk);
        }

        size_t wo_t = ((size_t)l*2 + 0)*512*512, wo_s = ((size_t)l*2 + 1)*512*512;
        size_t lo_t = ((size_t)l*2 + 0)*512,     lo_s = ((size_t)l*2 + 1)*512;

        // QKV x6 fused
        {
            int n4 = NROWS*512/4;
            k_cvtA<<<(n4 + 255)/256, 256>>>(x, s_ahi, s_alo, n4);
            k_cvtB_qkv<<<dim3(16, 16, 6), dim3(32, 8)>>>(Wq, Wk, Wv, wo_t, wo_s,
                                                         s_bhi, s_blo);
            dim3 qg(8, (NROWS + 127)/128, 6);
            k_mgemm_qkv<<<qg, 256>>>(s_ahi, s_alo, s_bhi, s_blo,
                                     q, k, v, q2, k2, v2, NROWS, 512, 512);
        }
        dim3 sg(LTOT, BATCH);
        k_tattn<<<sg, 256>>>(q, k, v, o);
        dim3 ag(LTOT/16, 8, BATCH);
        k_sattn<<<ag, 256, ATT_SMEM>>>(q2, k2, v2, smk, o2);

        // fc x2 fused
        {
            int n4 = NROWS*512/4;
            k_cvtA<<<(n4 + 255)/256, 256>>>(o,  s_ahi, s_alo, n4);
            k_cvtA<<<(n4 + 255)/256, 256>>>(o2, s_ahi + (size_t)NROWS*512,
                                                s_alo + (size_t)NROWS*512, n4);
            k_cvtB<<<dim3(16, 16), dim3(32, 8)>>>(fcW + wo_t, s_bhi, s_blo, 512, 512);
            k_cvtB<<<dim3(16, 16), dim3(32, 8)>>>(fcW + wo_s, s_bhi + (size_t)512*512,
                                                  s_blo + (size_t)512*512, 512, 512);
            dim3 fg(8, (NROWS + 127)/128, 2);
            k_mgemm_fc<<<fg, 256>>>(s_ahi, s_alo, s_bhi, s_blo,
                                    fcb, lo_t, lo_s, fc, fc2, NROWS, 512, 512);
        }
        dim3 lg(NROWS, 2);
        k_add_ln2<<<lg, 256>>>(fc, fc2, x, aln_g, aln_b, lo_t, lo_s, tout, sout);
        k_comb<<<(NROWS*512 + 255)/256, 256>>>(tout, sout, x, NROWS*512);

        size_t fo = (size_t)l*512*512, fb = (size_t)l*512;
        mgemm(x, W1 + fo, h, b1 + fb, NROWS, 512, 512, 1);
        mgemm(h, W2 + fo, fc, b2 + fb, NROWS, 512, 512, 0);
        k_add_ln<<<NROWS, 256>>>(fc, x, fln_g + fb, fln_b + fb,
                                 (l == 0) ? x : out, 1e-6f);
    }
}

// round 9
// speedup vs baseline: 3.6602x; 1.4482x over previous
#include <cuda_runtime.h>
#include <cuda_bf16.h>
#include <math.h>
#include <stdint.h>

#define LTOT   1360
#define BATCH  4
#define NROWS  (BATCH*LTOT)          // 5440
#define L2SZ   ((size_t)LTOT*LTOT)
#define SIMB   (1048576 + 65536)
#define LPAD   1408                  // keys padded to 22*64
#define NBH    (BATCH*8)             // 32 (batch,head) pairs

typedef __nv_bfloat16 bf16;
typedef unsigned int u32;

// ---------------- static device scratch ----------------
__device__ float g_t0[BATCH*1024*512];
__device__ float g_c1[BATCH*256*512];
__device__ float g_c2[BATCH*64*512];
__device__ float g_c3[BATCH*16*512];
__device__ float g_pc[BATCH*336*512];
__device__ float g_pyr[BATCH*336*512];
__device__ float g_x[NROWS*512];
__device__ float g_q[NROWS*512];
__device__ float g_k[NROWS*512];
__device__ float g_v[NROWS*512];
__device__ float g_q2[NROWS*512];
__device__ float g_k2[NROWS*512];
__device__ float g_v2[NROWS*512];
__device__ float g_o[NROWS*512];
__device__ float g_o2[NROWS*512];
__device__ float g_fc[NROWS*512];
__device__ float g_fc2[NROWS*512];
__device__ float g_tout[NROWS*512];
__device__ float g_sout[NROWS*512];
__device__ float g_xn[NROWS*512];
__device__ float g_h[NROWS*512];
__device__ float g_wc[3*2048*512];
__device__ bf16 g_ahi[2*NROWS*512];
__device__ bf16 g_alo[2*NROWS*512];
__device__ bf16 g_bhi[6*512*512];
__device__ bf16 g_blo[6*512*512];
__device__ float g_sim[(size_t)BATCH*SIMB];
__device__ unsigned char g_sm[(size_t)BATCH*LTOT*LTOT];
// attention tensor-core buffers
__device__ bf16 g_QH[(size_t)NBH*LPAD*64];
__device__ bf16 g_QL[(size_t)NBH*LPAD*64];
__device__ bf16 g_KH[(size_t)NBH*LPAD*64];
__device__ bf16 g_KL[(size_t)NBH*LPAD*64];
__device__ bf16 g_VTH[(size_t)NBH*64*LPAD];
__device__ bf16 g_VTL[(size_t)NBH*64*LPAD];
__device__ float g_S[(size_t)NBH*LTOT*LPAD];
__device__ bf16 g_PH[(size_t)NBH*LTOT*LPAD];
__device__ bf16 g_PL[(size_t)NBH*LTOT*LPAD];

// ---------------- fp32 -> bf16 hi/lo (flat) ----------------
__global__ void k_cvtA(const float* __restrict__ s, bf16* __restrict__ hi,
                       bf16* __restrict__ lo, int n4) {
    int i = blockIdx.x*blockDim.x + threadIdx.x;
    if (i >= n4) return;
    float4 v = ((const float4*)s)[i];
    bf16 h0=__float2bfloat16(v.x), h1=__float2bfloat16(v.y),
         h2=__float2bfloat16(v.z), h3=__float2bfloat16(v.w);
    bf16 l0=__float2bfloat16(v.x-__bfloat162float(h0)),
         l1=__float2bfloat16(v.y-__bfloat162float(h1)),
         l2=__float2bfloat16(v.z-__bfloat162float(h2)),
         l3=__float2bfloat16(v.w-__bfloat162float(h3));
    uint2 hp = make_uint2((u32)__bfloat16_as_ushort(h0) | ((u32)__bfloat16_as_ushort(h1)<<16),
                          (u32)__bfloat16_as_ushort(h2) | ((u32)__bfloat16_as_ushort(h3)<<16));
    uint2 lp = make_uint2((u32)__bfloat16_as_ushort(l0) | ((u32)__bfloat16_as_ushort(l1)<<16),
                          (u32)__bfloat16_as_ushort(l2) | ((u32)__bfloat16_as_ushort(l3)<<16));
    ((uint2*)hi)[i] = hp;
    ((uint2*)lo)[i] = lp;
}

// ---------------- fp32 [K][N] -> bf16 hi/lo transposed [N][K] ----------------
__device__ __forceinline__ void cvtB_body(const float* __restrict__ src,
        bf16* __restrict__ hi, bf16* __restrict__ lo, int K, int N) {
    __shared__ float t[32][33];
    int tx = threadIdx.x, ty = threadIdx.y;
    int n0 = blockIdx.x*32, k0 = blockIdx.y*32;
    #pragma unroll
    for (int i = 0; i < 4; i++)
        t[ty + i*8][tx] = src[(size_t)(k0 + ty + i*8)*N + n0 + tx];
    __syncthreads();
    #pragma unroll
    for (int i = 0; i < 4; i++) {
        float v = t[tx][ty + i*8];
        int n = n0 + ty + i*8, kk = k0 + tx;
        bf16 h = __float2bfloat16(v);
        bf16 l = __float2bfloat16(v - __bfloat162float(h));
        hi[(size_t)n*K + kk] = h;
        lo[(size_t)n*K + kk] = l;
    }
}
__global__ void k_cvtB(const float* __restrict__ src, bf16* hi, bf16* lo, int K, int N) {
    cvtB_body(src, hi, lo, K, N);
}
__global__ void k_cvtB_qkv(const float* __restrict__ Wq, const float* __restrict__ Wk,
                           const float* __restrict__ Wv, size_t wo_t, size_t wo_s,
                           bf16* hi, bf16* lo) {
    int z = blockIdx.z;
    const float* base = ((z%3 == 0) ? Wq : (z%3 == 1) ? Wk : Wv) + ((z/3) ? wo_s : wo_t);
    cvtB_body(base, hi + (size_t)z*512*512, lo + (size_t)z*512*512, 512, 512);
}

// ---------------- bf16x3 MMA GEMM body (ldc-aware) ----------------
__device__ __forceinline__ void mma16816(float* d, const u32* a, const u32* b) {
    asm volatile(
        "mma.sync.aligned.m16n8k16.row.col.f32.bf16.bf16.f32 "
        "{%0,%1,%2,%3}, {%4,%5,%6,%7}, {%8,%9}, {%0,%1,%2,%3};"
        : "+f"(d[0]), "+f"(d[1]), "+f"(d[2]), "+f"(d[3])
        : "r"(a[0]), "r"(a[1]), "r"(a[2]), "r"(a[3]), "r"(b[0]), "r"(b[1]));
}
#define AP 40
// mode: 0 none, 1 relu, 2 scale+elu
__device__ void mg_body(const bf16* __restrict__ Ahi, const bf16* __restrict__ Alo,
                        const bf16* __restrict__ Bhi, const bf16* __restrict__ Blo,
                        float* __restrict__ C, const float* __restrict__ bias,
                        int M, int N, int K, int mode, int ldc) {
    __shared__ bf16 As[2][128*AP];
    __shared__ bf16 Bs[2][64*AP];
    int tid = threadIdx.x, wid = tid >> 5, lane = tid & 31;
    int wm = wid >> 1, wn = wid & 1, g = lane >> 2, qp = lane & 3;
    int row0 = blockIdx.y << 7, col0 = blockIdx.x << 6;
    float acc[2][4][4] = {};
    for (int kc = 0; kc < K; kc += 32) {
        #pragma unroll
        for (int s = tid; s < 512; s += 256) {
            int r = s >> 2, k8 = (s & 3) << 3;
            int gr = row0 + r;
            float4 vh = make_float4(0,0,0,0), vl = vh;
            if (gr < M) {
                vh = *(const float4*)(Ahi + (size_t)gr*K + kc + k8);
                vl = *(const float4*)(Alo + (size_t)gr*K + kc + k8);
            }
            *(float4*)&As[0][r*AP + k8] = vh;
            *(float4*)&As[1][r*AP + k8] = vl;
        }
        if (tid < 256) {
            int s = tid;
            int r = s >> 2, k8 = (s & 3) << 3;
            int gn = col0 + r;
            float4 vh = *(const float4*)(Bhi + (size_t)gn*K + kc + k8);
            float4 vl = *(const float4*)(Blo + (size_t)gn*K + kc + k8);
            *(float4*)&Bs[0][r*AP + k8] = vh;
            *(float4*)&Bs[1][r*AP + k8] = vl;
        }
        __syncthreads();
        #pragma unroll
        for (int ks = 0; ks < 32; ks += 16) {
            u32 ah[2][4], al[2][4], bh[4][2], bl[4][2];
            #pragma unroll
            for (int mt = 0; mt < 2; mt++) {
                int ar = (wm*32 + mt*16 + g)*AP + ks + qp*2;
                int ar8 = ar + 8*AP;
                ah[mt][0] = *(u32*)&As[0][ar];     ah[mt][1] = *(u32*)&As[0][ar8];
                ah[mt][2] = *(u32*)&As[0][ar + 8]; ah[mt][3] = *(u32*)&As[0][ar8 + 8];
                al[mt][0] = *(u32*)&As[1][ar];     al[mt][1] = *(u32*)&As[1][ar8];
                al[mt][2] = *(u32*)&As[1][ar + 8]; al[mt][3] = *(u32*)&As[1][ar8 + 8];
            }
            #pragma unroll
            for (int nt = 0; nt < 4; nt++) {
                int br = (wn*32 + nt*8 + g)*AP + ks + qp*2;
                bh[nt][0] = *(u32*)&Bs[0][br]; bh[nt][1] = *(u32*)&Bs[0][br + 8];
                bl[nt][0] = *(u32*)&Bs[1][br]; bl[nt][1] = *(u32*)&Bs[1][br + 8];
            }
            #pragma unroll
            for (int mt = 0; mt < 2; mt++)
                #pragma unroll
                for (int nt = 0; nt < 4; nt++) {
                    mma16816(acc[mt][nt], ah[mt], bh[nt]);
                    mma16816(acc[mt][nt], ah[mt], bl[nt]);
                    mma16816(acc[mt][nt], al[mt], bh[nt]);
                }
        }
        __syncthreads();
    }
    #pragma unroll
    for (int mt = 0; mt < 2; mt++) {
        int r0 = row0 + wm*32 + mt*16 + g;
        #pragma unroll
        for (int half = 0; half < 2; half++) {
            int r = r0 + half*8;
            if (r >= M) continue;
            #pragma unroll
            for (int nt = 0; nt < 4; nt++) {
                int cl = col0 + wn*32 + nt*8 + qp*2;
                float v0 = acc[mt][nt][half*2 + 0], v1 = acc[mt][nt][half*2 + 1];
                if (bias) { v0 += bias[cl]; v1 += bias[cl + 1]; }
                if (mode == 1) { v0 = fmaxf(v0, 0.f); v1 = fmaxf(v1, 0.f); }
                else if (mode == 2) {
                    v0 *= 0.9999950000374997f; if (v0 <= 0.f) v0 = expm1f(v0);
                    v1 *= 0.9999950000374997f; if (v1 <= 0.f) v1 = expm1f(v1);
                }
                *(float2*)&C[(size_t)r*ldc + cl] = make_float2(v0, v1);
            }
        }
    }
}

__global__ void __launch_bounds__(256) k_mgemm(
        const bf16* Ahi, const bf16* Alo, const bf16* Bhi, const bf16* Blo,
        float* C, const float* bias, int M, int N, int K, int mode) {
    mg_body(Ahi, Alo, Bhi, Blo, C, bias, M, N, K, mode, N);
}
__global__ void __launch_bounds__(256) k_mgemm_qkv(
        const bf16* Ahi, const bf16* Alo, const bf16* Bhi, const bf16* Blo,
        float* q, float* k, float* v, float* q2, float* k2, float* v2,
        int M, int N, int K) {
    int z = blockIdx.z;
    size_t bo = (size_t)z*512*512;
    float* C = (z==0)?q:(z==1)?k:(z==2)?v:(z==3)?q2:(z==4)?k2:v2;
    mg_body(Ahi, Alo, Bhi + bo, Blo + bo, C, nullptr, M, N, K, 0, N);
}
__global__ void __launch_bounds__(256) k_mgemm_fc(
        const bf16* Ahi, const bf16* Alo, const bf16* Bhi, const bf16* Blo,
        const float* fcb, size_t lo_t, size_t lo_s,
        float* ft, float* fs, int M, int N, int K) {
    int z = blockIdx.z;
    size_t ao = (size_t)z*NROWS*512, bo = (size_t)z*512*512;
    mg_body(Ahi + ao, Alo + ao, Bhi + bo, Blo + bo, z ? fs : ft,
            fcb + (z ? lo_s : lo_t), M, N, K, 0, N);
}
__global__ void __launch_bounds__(256) k_mgemm_sim(
        const bf16* Ahi, const bf16* Alo, int startRow, int n, size_t lvloff,
        float* simbuf) {
    int b = blockIdx.z;
    size_t ao = ((size_t)(b*LTOT + startRow))*512;
    float* C = simbuf + (size_t)b*SIMB + lvloff;
    mg_body(Ahi + ao, Alo + ao, Ahi + ao, Alo + ao, C, nullptr, n, n, 512, 0, n);
}
// S = Q K^T per (b,h):  [1360 x 1408], K=64
__global__ void __launch_bounds__(256) k_mgemm_att_s(
        const bf16* QH, const bf16* QL, const bf16* KH, const bf16* KL, float* S) {
    int bh = blockIdx.z;
    size_t qo = (size_t)bh*LPAD*64;
    mg_body(QH + qo, QL + qo, KH + qo, KL + qo,
            S + (size_t)bh*LTOT*LPAD, nullptr, LTOT, LPAD, 64, 0, LPAD);
}
// O = P V per (b,h): [1360 x 64], K=1408, written head-interleaved into o2
__global__ void __launch_bounds__(256) k_mgemm_att_pv(
        const bf16* PH, const bf16* PL, const bf16* VTH, const bf16* VTL, float* O) {
    int bh = blockIdx.z, b = bh >> 3, h = bh & 7;
    size_t po = (size_t)bh*LTOT*LPAD, vo = (size_t)bh*64*LPAD;
    mg_body(PH + po, PL + po, VTH + vo, VTL + vo,
            O + ((size_t)b*LTOT)*512 + h*64, nullptr, LTOT, 64, LPAD, 0, 512);
}

// ---------------- attention operand conversion ----------------
// q2,k2 -> head-split padded bf16 hi/lo  [bh][1408][64]
__global__ void k_cvt_qk(const float* __restrict__ q2, const float* __restrict__ k2,
                         bf16* QH, bf16* QL, bf16* KH, bf16* KL) {
    long idx = (long)blockIdx.x*256 + threadIdx.x;
    if (idx >= (long)NBH*LPAD*64) return;
    int d = idx & 63;
    long r_ = idx >> 6;
    int r = (int)(r_ % LPAD);
    int bh = (int)(r_ / LPAD);
    int b = bh >> 3, h = bh & 7;
    float qv = 0.f, kv = 0.f;
    if (r < LTOT) {
        size_t off = ((size_t)(b*LTOT + r))*512 + h*64 + d;
        qv = q2[off]; kv = k2[off];
    }
    bf16 qh = __float2bfloat16(qv);
    bf16 ql = __float2bfloat16(qv - __bfloat162float(qh));
    bf16 kh = __float2bfloat16(kv);
    bf16 kl = __float2bfloat16(kv - __bfloat162float(kh));
    QH[idx] = qh; QL[idx] = ql; KH[idx] = kh; KL[idx] = kl;
}
// v2 -> transposed padded bf16 hi/lo  [bh][64][1408]
__global__ void k_cvt_vt(const float* __restrict__ v2, bf16* VTH, bf16* VTL) {
    __shared__ float t[32][33];
    int bh = blockIdx.z, b = bh >> 3, h = bh & 7;
    int j0 = blockIdx.x*32, d0 = blockIdx.y*32;
    int tx = threadIdx.x, ty = threadIdx.y;
    #pragma unroll
    for (int i = 0; i < 4; i++) {
        int j = j0 + ty + i*8;
        t[ty + i*8][tx] = (j < LTOT)
            ? v2[((size_t)(b*LTOT + j))*512 + h*64 + d0 + tx] : 0.f;
    }
    __syncthreads();
    #pragma unroll
    for (int i = 0; i < 4; i++) {
        int d = d0 + ty + i*8, j = j0 + tx;
        float v = t[tx][ty + i*8];
        bf16 hh = __float2bfloat16(v);
        bf16 ll = __float2bfloat16(v - __bfloat162float(hh));
        size_t off = ((size_t)bh*64 + d)*LPAD + j;
        VTH[off] = hh; VTL[off] = ll;
    }
}

// ---------------- masked softmax -> normalized P (bf16 hi/lo) ----------------
__device__ __forceinline__ float block_max256(float v) {
    __shared__ float red[8];
    int lane = threadIdx.x & 31, w = threadIdx.x >> 5;
    #pragma unroll
    for (int o = 16; o; o >>= 1) v = fmaxf(v, __shfl_xor_sync(0xffffffffu, v, o));
    if (lane == 0) red[w] = v;
    __syncthreads();
    if (w == 0) {
        float t = (lane < 8) ? red[lane] : -1e30f;
        #pragma unroll
        for (int o = 4; o; o >>= 1) t = fmaxf(t, __shfl_xor_sync(0xffffffffu, t, o));
        if (lane == 0) red[0] = t;
    }
    __syncthreads();
    float r = red[0];
    __syncthreads();
    return r;
}
__device__ __forceinline__ float block_sum256(float v) {
    __shared__ float red[8];
    int lane = threadIdx.x & 31, w = threadIdx.x >> 5;
    #pragma unroll
    for (int o = 16; o; o >>= 1) v += __shfl_xor_sync(0xffffffffu, v, o);
    if (lane == 0) red[w] = v;
    __syncthreads();
    if (w == 0) {
        float t = (lane < 8) ? red[lane] : 0.f;
        #pragma unroll
        for (int o = 4; o; o >>= 1) t += __shfl_xor_sync(0xffffffffu, t, o);
        if (lane == 0) red[0] = t;
    }
    __syncthreads();
    float r = red[0];
    __syncthreads();
    return r;
}
__global__ void __launch_bounds__(256) k_softmax_p(
        const float* __restrict__ S, const unsigned char* __restrict__ smask,
        bf16* __restrict__ PH, bf16* __restrict__ PL) {
    int row = blockIdx.x, bh = blockIdx.y, b = bh >> 3;
    int tid = threadIdx.x;
    __shared__ float buf[LTOT];
    const float* srow = S + ((size_t)bh*LTOT + row)*LPAD;
    const unsigned char* mrow = smask + ((size_t)b*LTOT + row)*LTOT;
    float mx = -1e30f;
    for (int j = tid; j < LTOT; j += 256) {
        float s = mrow[j] ? -1e30f : srow[j]*0.125f;
        buf[j] = s;
        mx = fmaxf(mx, s);
    }
    mx = block_max256(mx);
    float sum = 0.f;
    for (int j = tid; j < LTOT; j += 256) {
        float e = expf(buf[j] - mx);
        buf[j] = e; sum += e;
    }
    sum = block_sum256(sum);
    float inv = 1.f / sum;
    bf16* ph = PH + ((size_t)bh*LTOT + row)*LPAD;
    bf16* pl = PL + ((size_t)bh*LTOT + row)*LPAD;
    for (int j = tid; j < LPAD; j += 256) {
        float p = (j < LTOT) ? buf[j]*inv : 0.f;
        bf16 hh = __float2bfloat16(p);
        bf16 ll = __float2bfloat16(p - __bfloat162float(hh));
        ph[j] = hh; pl[j] = ll;
    }
}

// ---------------- conv weight re-layout ----------------
__global__ void k_convw(const float* __restrict__ w, float* __restrict__ wm) {
    int idx = blockIdx.x*blockDim.x + threadIdx.x;
    if (idx >= 3*2048*512) return;
    int l  = idx / (2048*512);
    int r  = idx - l*2048*512;
    int kk = r >> 9, co = r & 511;
    int t  = kk >> 9, ci = kk & 511;
    wm[idx] = w[(((size_t)(l*512 + co))*512 + ci)*4 + t];
}

// ---------------- concat + LN(1e-5) ----------------
__global__ void __launch_bounds__(256) k_concat_ln(
        const float* __restrict__ xe, const float* __restrict__ pyr,
        const float* __restrict__ g, const float* __restrict__ bt,
        float* __restrict__ out) {
    int row = blockIdx.x;
    int b = row / LTOT, i = row % LTOT;
    const float* src = (i < 1024) ? xe + ((size_t)(b*1024 + i))*512
                                  : pyr + ((size_t)(b*336 + (i - 1024)))*512;
    int t = threadIdx.x;
    float v0 = src[t], v1 = src[t + 256];
    float mu = block_sum256(v0 + v1) * (1.f/512.f);
    float d0 = v0 - mu, d1 = v1 - mu;
    float var = block_sum256(d0*d0 + d1*d1) * (1.f/512.f);
    float rs = rsqrtf(var + 1e-5f);
    float* o = out + (size_t)row*512;
    o[t]       = d0*rs*g[t]       + bt[t];
    o[t + 256] = d1*rs*g[t + 256] + bt[t + 256];
}

// ---------------- (a+res) -> LN ----------------
__global__ void __launch_bounds__(256) k_add_ln(
        const float* __restrict__ a, const float* __restrict__ res,
        const float* __restrict__ g, const float* __restrict__ bt,
        float* __restrict__ out, float eps) {
    int row = blockIdx.x, t = threadIdx.x;
    const float* pa = a + (size_t)row*512;
    const float* pr = res + (size_t)row*512;
    float v0 = pa[t] + pr[t], v1 = pa[t + 256] + pr[t + 256];
    float mu = block_sum256(v0 + v1) * (1.f/512.f);
    float d0 = v0 - mu, d1 = v1 - mu;
    float var = block_sum256(d0*d0 + d1*d1) * (1.f/512.f);
    float rs = rsqrtf(var + eps);
    float* o = out + (size_t)row*512;
    o[t]       = d0*rs*g[t]       + bt[t];
    o[t + 256] = d1*rs*g[t + 256] + bt[t + 256];
}

// two-branch add_ln
__global__ void __launch_bounds__(256) k_add_ln2(
        const float* __restrict__ at, const float* __restrict__ as_,
        const float* __restrict__ res,
        const float* __restrict__ g, const float* __restrict__ bt,
        size_t lo_t, size_t lo_s,
        float* __restrict__ ot, float* __restrict__ os_) {
    int s = blockIdx.y;
    const float* a = s ? as_ : at;
    const float* gg = g + (s ? lo_s : lo_t);
    const float* bb = bt + (s ? lo_s : lo_t);
    float* out = s ? os_ : ot;
    int row = blockIdx.x, t = threadIdx.x;
    const float* pa = a + (size_t)row*512;
    const float* pr = res + (size_t)row*512;
    float v0 = pa[t] + pr[t], v1 = pa[t + 256] + pr[t + 256];
    float mu = block_sum256(v0 + v1) * (1.f/512.f);
    float d0 = v0 - mu, d1 = v1 - mu;
    float var = block_sum256(d0*d0 + d1*d1) * (1.f/512.f);
    float rs = rsqrtf(var + 1e-6f);
    float* o = out + (size_t)row*512;
    o[t]       = d0*rs*gg[t]       + bb[t];
    o[t + 256] = d1*rs*gg[t + 256] + bb[t + 256];
}

// ---------------- row L2 normalize ----------------
__global__ void __launch_bounds__(256) k_rownorm(
        const float* __restrict__ x, float* __restrict__ xn) {
    int row = blockIdx.x, t = threadIdx.x;
    const float* p = x + (size_t)row*512;
    float v0 = p[t], v1 = p[t + 256];
    float ss = block_sum256(v0*v0 + v1*v1);
    float inv = 1.f / fmaxf(sqrtf(ss), 1e-8f);
    float* o = xn + (size_t)row*512;
    o[t] = v0*inv; o[t + 256] = v1*inv;
}

// ---------------- top-k select from precomputed sims ----------------
__global__ void __launch_bounds__(256) k_topksel(
        const float* __restrict__ xn, const float* __restrict__ simbuf,
        unsigned char* __restrict__ smask) {
    int i = blockIdx.x, b = blockIdx.y, tid = threadIdx.x;
    const int starts[4] = {0,1024,1280,1344};
    const int sizes[4]  = {1024,256,64,16};
    int lev = (i<1024)?0:(i<1280)?1:(i<1344)?2:3;
    int st = starts[lev], n = sizes[lev];
    int kk = n < 32 ? n : 32;
    __shared__ float sims[1024];
    __shared__ float qrow[512];
    __shared__ float wv[8]; __shared__ int wi[8];
    unsigned char* mrow = smask + ((size_t)b*LTOT + i)*LTOT + st;
    for (int j = tid; j < n; j += 256) mrow[j] = 0;
    if (lev <= 1) {
        size_t lvloff = (lev == 0) ? 0 : 1048576;
        const float* srow = simbuf + (size_t)b*SIMB + lvloff + (size_t)(i - st)*n;
        for (int j = tid; j < n; j += 256) sims[j] = srow[j];
        __syncthreads();
    } else {
        const float* xb = xn + (size_t)b*LTOT*512;
        for (int d = tid; d < 512; d += 256) qrow[d] = xb[(size_t)i*512 + d];
        __syncthreads();
        int w = tid >> 5, lane = tid & 31;
        for (int j = w; j < n; j += 8) {
            const float* rj = xb + (size_t)(st + j)*512;
            float p = 0.f;
            #pragma unroll 4
            for (int d = lane; d < 512; d += 32) p += qrow[d]*rj[d];
            #pragma unroll
            for (int o = 16; o; o >>= 1) p += __shfl_xor_sync(0xffffffffu, p, o);
            if (lane == 0) sims[j] = p;
        }
        __syncthreads();
    }
    int w = tid >> 5, lane = tid & 31;
    for (int it = 0; it < kk; it++) {
        float bv = -3.f; int bi = n;
        for (int j = tid; j < n; j += 256) {
            float v = sims[j];
            if (v > bv) { bv = v; bi = j; }
        }
        #pragma unroll
        for (int o = 16; o; o >>= 1) {
            float ov = __shfl_xor_sync(0xffffffffu, bv, o);
            int   oi = __shfl_xor_sync(0xffffffffu, bi, o);
            if (ov > bv || (ov == bv && oi < bi)) { bv = ov; bi = oi; }
        }
        if (lane == 0) { wv[w] = bv; wi[w] = bi; }
        __syncthreads();
        if (tid == 0) {
            float fv = wv[0]; int fi = wi[0];
            #pragma unroll
            for (int z = 1; z < 8; z++)
                if (wv[z] > fv || (wv[z] == fv && wi[z] < fi)) { fv = wv[z]; fi = wi[z]; }
            mrow[fi] = 1;
            sims[fi] = -3.f;
        }
        __syncthreads();
    }
}

// ---------------- SPARSE temporal attention ----------------
__global__ void __launch_bounds__(256) k_tattn(
        const float* __restrict__ Q, const float* __restrict__ K,
        const float* __restrict__ V, float* __restrict__ O) {
    int i = blockIdx.x, b = blockIdx.y;
    int h = threadIdx.x >> 5, lane = threadIdx.x & 31;
    const int starts[4] = {0,1024,1280,1344};
    const int sizes[4]  = {1024,256,64,16};
    int lev = (i<1024)?0:(i<1280)?1:(i<1344)?2:3;
    int st = starts[lev], n = sizes[lev];
    int nb[10]; int cnt = 0;
    int lo = (i-2 < st) ? st : i-2;
    int hi = (i+2 > st+n-1) ? st+n-1 : i+2;
    for (int j = lo; j <= hi; j++) nb[cnt++] = j;
    if (lev > 0) {
        int c0 = starts[lev-1] + (i - st)*4;
        nb[cnt++] = c0; nb[cnt++] = c0+1; nb[cnt++] = c0+2; nb[cnt++] = c0+3;
    }
    if (lev < 3) nb[cnt++] = starts[lev+1] + (i - st)/4;

    size_t rowb = (size_t)(b*LTOT);
    const float2 qv = *(const float2*)(Q + (rowb + i)*512 + h*64 + lane*2);
    float sc[10];
    #pragma unroll
    for (int t = 0; t < 10; t++) {
        if (t < cnt) {
            float2 kv = *(const float2*)(K + (rowb + nb[t])*512 + h*64 + lane*2);
            float p = qv.x*kv.x + qv.y*kv.y;
            #pragma unroll
            for (int o = 16; o; o >>= 1) p += __shfl_xor_sync(0xffffffffu, p, o);
            sc[t] = p * 0.125f;
        } else sc[t] = -1e30f;
    }
    float mx = -1e30f;
    #pragma unroll
    for (int t = 0; t < 10; t++) mx = fmaxf(mx, sc[t]);
    float ssum = 0.f;
    #pragma unroll
    for (int t = 0; t < 10; t++) {
        sc[t] = (t < cnt) ? expf(sc[t] - mx) : 0.f;
        ssum += sc[t];
    }
    float inv = 1.f / ssum;
    float ax = 0.f, ay = 0.f;
    #pragma unroll
    for (int t = 0; t < 10; t++) {
        if (t < cnt) {
            float2 vv = *(const float2*)(V + (rowb + nb[t])*512 + h*64 + lane*2);
            ax += sc[t]*vv.x; ay += sc[t]*vv.y;
        }
    }
    *(float2*)(O + (rowb + i)*512 + h*64 + lane*2) = make_float2(ax*inv, ay*inv);
}

// ---------------- pyramid concat + combine ----------------
__global__ void k_pyrcat(const float* __restrict__ c1, const float* __restrict__ c2,
                         const float* __restrict__ c3, float* __restrict__ out) {
    int idx = blockIdx.x*blockDim.x + threadIdx.x;
    if (idx >= BATCH*336*512) return;
    int d = idx & 511, r = idx >> 9;
    int b = r / 336, p = r % 336;
    float v;
    if (p < 256) v = c1[((size_t)(b*256 + p) << 9) | d];
    else if (p < 320) v = c2[((size_t)(b*64 + p - 256) << 9) | d];
    else v = c3[((size_t)(b*16 + p - 320) << 9) | d];
    out[idx] = v;
}

__global__ void k_comb(const float* __restrict__ t, const float* __restrict__ s,
                       float* __restrict__ x, int n) {
    int i = blockIdx.x*blockDim.x + threadIdx.x;
    if (i < n) x[i] = (t[i] + s[i] + x[i]) * (1.f/3.f);
}

// ---------------- orchestration ----------------
static bf16 *s_ahi, *s_alo, *s_bhi, *s_blo;

static void mgemm(const float* A, const float* B, float* C, const float* bias,
                  int M, int N, int K, int mode) {
    int n4 = M*K/4;
    k_cvtA<<<(n4 + 255)/256, 256>>>(A, s_ahi, s_alo, n4);
    k_cvtB<<<dim3(N/32, K/32), dim3(32, 8)>>>(B, s_bhi, s_blo, K, N);
    dim3 g(N/64, (M + 127)/128);
    k_mgemm<<<g, 256>>>(s_ahi, s_alo, s_bhi, s_blo, C, bias, M, N, K, mode);
}

extern "C" void kernel_launch(void* const* d_in, const int* in_sizes, int n_in,
                              void* d_out, int out_size) {
    const float* x_enc  = (const float*)d_in[0];
    const float* down_W = (const float*)d_in[1];
    const float* down_b = (const float*)d_in[2];
    const float* conv_W = (const float*)d_in[3];
    const float* conv_b = (const float*)d_in[4];
    const float* up_W   = (const float*)d_in[5];
    const float* up_b   = (const float*)d_in[6];
    const float* bc_g   = (const float*)d_in[7];
    const float* bc_b   = (const float*)d_in[8];
    const float* Wq     = (const float*)d_in[9];
    const float* Wk     = (const float*)d_in[10];
    const float* Wv     = (const float*)d_in[11];
    const float* fcW    = (const float*)d_in[12];
    const float* fcb    = (const float*)d_in[13];
    const float* aln_g  = (const float*)d_in[14];
    const float* aln_b  = (const float*)d_in[15];
    const float* W1     = (const float*)d_in[16];
    const float* b1     = (const float*)d_in[17];
    const float* W2     = (const float*)d_in[18];
    const float* b2     = (const float*)d_in[19];
    const float* fln_g  = (const float*)d_in[20];
    const float* fln_b  = (const float*)d_in[21];
    float* out = (float*)d_out;

    float *t0,*c1,*c2,*c3,*pc,*pyr,*x,*q,*k,*v,*q2,*k2,*v2,*o,*o2,*fc,*fc2,
          *tout,*sout,*xn,*h,*wc,*sim,*S;
    bf16 *QH,*QL,*KH,*KL,*VTH,*VTL,*PH,*PL;
    unsigned char *smk;
    cudaGetSymbolAddress((void**)&t0,  g_t0);
    cudaGetSymbolAddress((void**)&c1,  g_c1);
    cudaGetSymbolAddress((void**)&c2,  g_c2);
    cudaGetSymbolAddress((void**)&c3,  g_c3);
    cudaGetSymbolAddress((void**)&pc,  g_pc);
    cudaGetSymbolAddress((void**)&pyr, g_pyr);
    cudaGetSymbolAddress((void**)&x,   g_x);
    cudaGetSymbolAddress((void**)&q,   g_q);
    cudaGetSymbolAddress((void**)&k,   g_k);
    cudaGetSymbolAddress((void**)&v,   g_v);
    cudaGetSymbolAddress((void**)&q2,  g_q2);
    cudaGetSymbolAddress((void**)&k2,  g_k2);
    cudaGetSymbolAddress((void**)&v2,  g_v2);
    cudaGetSymbolAddress((void**)&o,   g_o);
    cudaGetSymbolAddress((void**)&o2,  g_o2);
    cudaGetSymbolAddress((void**)&fc,  g_fc);
    cudaGetSymbolAddress((void**)&fc2, g_fc2);
    cudaGetSymbolAddress((void**)&tout,g_tout);
    cudaGetSymbolAddress((void**)&sout,g_sout);
    cudaGetSymbolAddress((void**)&xn,  g_xn);
    cudaGetSymbolAddress((void**)&h,   g_h);
    cudaGetSymbolAddress((void**)&wc,  g_wc);
    cudaGetSymbolAddress((void**)&sim, g_sim);
    cudaGetSymbolAddress((void**)&S,   g_S);
    cudaGetSymbolAddress((void**)&QH,  g_QH);
    cudaGetSymbolAddress((void**)&QL,  g_QL);
    cudaGetSymbolAddress((void**)&KH,  g_KH);
    cudaGetSymbolAddress((void**)&KL,  g_KL);
    cudaGetSymbolAddress((void**)&VTH, g_VTH);
    cudaGetSymbolAddress((void**)&VTL, g_VTL);
    cudaGetSymbolAddress((void**)&PH,  g_PH);
    cudaGetSymbolAddress((void**)&PL,  g_PL);
    cudaGetSymbolAddress((void**)&smk, g_sm);
    cudaGetSymbolAddress((void**)&s_ahi, g_ahi);
    cudaGetSymbolAddress((void**)&s_alo, g_alo);
    cudaGetSymbolAddress((void**)&s_bhi, g_bhi);
    cudaGetSymbolAddress((void**)&s_blo, g_blo);

    k_convw<<<(3*2048*512 + 255)/256, 256>>>(conv_W, wc);

    // bottleneck
    mgemm(x_enc, down_W, t0, down_b, BATCH*1024, 512, 512, 0);
    mgemm(t0, wc,              c1, conv_b,        BATCH*256, 512, 2048, 2);
    mgemm(c1, wc + 2048*512,   c2, conv_b + 512,  BATCH*64,  512, 2048, 2);
    mgemm(c2, wc + 2*2048*512, c3, conv_b + 1024, BATCH*16,  512, 2048, 2);
    k_pyrcat<<<(BATCH*336*512 + 255)/256, 256>>>(c1, c2, c3, pc);
    mgemm(pc, up_W, pyr, up_b, BATCH*336, 512, 512, 0);
    k_concat_ln<<<NROWS, 256>>>(x_enc, pyr, bc_g, bc_b, x);

    for (int l = 0; l < 2; l++) {
        // ---- semantic mask via Gram GEMM + select ----
        k_rownorm<<<NROWS, 256>>>(x, xn);
        {
            int n4 = NROWS*512/4;
            k_cvtA<<<(n4 + 255)/256, 256>>>(xn, s_ahi, s_alo, n4);
            dim3 g0(1024/64, 1024/128, BATCH);
            k_mgemm_sim<<<g0, 256>>>(s_ahi, s_alo, 0,    1024, 0,       sim);
            dim3 g1(256/64, 256/128, BATCH);
            k_mgemm_sim<<<g1, 256>>>(s_ahi, s_alo, 1024, 256,  1048576, sim);
            dim3 tg(LTOT, BATCH);
            k_topksel<<<tg, 256>>>(xn, sim, smk);
        }

        size_t wo_t = ((size_t)l*2 + 0)*512*512, wo_s = ((size_t)l*2 + 1)*512*512;
        size_t lo_t = ((size_t)l*2 + 0)*512,     lo_s = ((size_t)l*2 + 1)*512;

        // QKV x6 fused
        {
            int n4 = NROWS*512/4;
            k_cvtA<<<(n4 + 255)/256, 256>>>(x, s_ahi, s_alo, n4);
            k_cvtB_qkv<<<dim3(16, 16, 6), dim3(32, 8)>>>(Wq, Wk, Wv, wo_t, wo_s,
                                                         s_bhi, s_blo);
            dim3 qg(8, (NROWS + 127)/128, 6);
            k_mgemm_qkv<<<qg, 256>>>(s_ahi, s_alo, s_bhi, s_blo,
                                     q, k, v, q2, k2, v2, NROWS, 512, 512);
        }
        // temporal branch (sparse, fp32)
        dim3 sg(LTOT, BATCH);
        k_tattn<<<sg, 256>>>(q, k, v, o);

        // semantic branch on tensor cores
        {
            long tot = (long)NBH*LPAD*64;
            k_cvt_qk<<<(unsigned)((tot + 255)/256), 256>>>(q2, k2, QH, QL, KH, KL);
            k_cvt_vt<<<dim3(LPAD/32, 2, NBH), dim3(32, 8)>>>(v2, VTH, VTL);
            dim3 gs(LPAD/64, (LTOT + 127)/128, NBH);
            k_mgemm_att_s<<<gs, 256>>>(QH, QL, KH, KL, S);
            dim3 gp(LTOT, NBH);
            k_softmax_p<<<gp, 256>>>(S, smk, PH, PL);
            dim3 gv(1, (LTOT + 127)/128, NBH);
            k_mgemm_att_pv<<<gv, 256>>>(PH, PL, VTH, VTL, o2);
        }

        // fc x2 fused
        {
            int n4 = NROWS*512/4;
            k_cvtA<<<(n4 + 255)/256, 256>>>(o,  s_ahi, s_alo, n4);
            k_cvtA<<<(n4 + 255)/256, 256>>>(o2, s_ahi + (size_t)NROWS*512,
                                                s_alo + (size_t)NROWS*512, n4);
            k_cvtB<<<dim3(16, 16), dim3(32, 8)>>>(fcW + wo_t, s_bhi, s_blo, 512, 512);
            k_cvtB<<<dim3(16, 16), dim3(32, 8)>>>(fcW + wo_s, s_bhi + (size_t)512*512,
                                                  s_blo + (size_t)512*512, 512, 512);
            dim3 fg(8, (NROWS + 127)/128, 2);
            k_mgemm_fc<<<fg, 256>>>(s_ahi, s_alo, s_bhi, s_blo,
                                    fcb, lo_t, lo_s, fc, fc2, NROWS, 512, 512);
        }
        dim3 lg(NROWS, 2);
        k_add_ln2<<<lg, 256>>>(fc, fc2, x, aln_g, aln_b, lo_t, lo_s, tout, sout);
        k_comb<<<(NROWS*512 + 255)/256, 256>>>(tout, sout, x, NROWS*512);

        size_t fo = (size_t)l*512*512, fb = (size_t)l*512;
        mgemm(x, W1 + fo, h, b1 + fb, NROWS, 512, 512, 1);
        mgemm(h, W2 + fo, fc, b2 + fb, NROWS, 512, 512, 0);
        k_add_ln<<<NROWS, 256>>>(fc, x, fln_g + fb, fln_b + fb,
                                 (l == 0) ? x : out, 1e-6f);
    }
}

// round 10
// speedup vs baseline: 3.9222x; 1.0716x over previous
#include <cuda_runtime.h>
#include <cuda_bf16.h>
#include <math.h>
#include <stdint.h>

#define LTOT   1360
#define BATCH  4
#define NROWS  (BATCH*LTOT)          // 5440
#define L2SZ   ((size_t)LTOT*LTOT)
#define SIMB   (1048576 + 65536)
#define LPAD   1408
#define NBH    (BATCH*8)

typedef __nv_bfloat16 bf16;
typedef unsigned int u32;

// ---------------- static device scratch ----------------
__device__ float g_t0[BATCH*1024*512];
__device__ float g_c1[BATCH*256*512];
__device__ float g_c2[BATCH*64*512];
__device__ float g_c3[BATCH*16*512];
__device__ float g_pc[BATCH*336*512];
__device__ float g_pyr[BATCH*336*512];
__device__ float g_x[NROWS*512];
__device__ float g_q[NROWS*512];
__device__ float g_k[NROWS*512];
__device__ float g_v[NROWS*512];
__device__ float g_q2[NROWS*512];
__device__ float g_k2[NROWS*512];
__device__ float g_v2[NROWS*512];
__device__ float g_o[NROWS*512];
__device__ float g_o2[NROWS*512];
__device__ float g_fc[NROWS*512];
__device__ float g_fc2[NROWS*512];
__device__ float g_xn[NROWS*512];
__device__ float g_h[NROWS*512];
__device__ float g_wc[3*2048*512];
__device__ bf16 g_ahi[2*NROWS*512];
__device__ bf16 g_alo[2*NROWS*512];
__device__ bf16 g_bhi[6*512*512];
__device__ bf16 g_blo[6*512*512];
__device__ float g_sim[(size_t)BATCH*SIMB];
__device__ unsigned char g_sm[(size_t)BATCH*LTOT*LTOT];
__device__ bf16 g_QH[(size_t)NBH*LPAD*64];
__device__ bf16 g_QL[(size_t)NBH*LPAD*64];
__device__ bf16 g_KH[(size_t)NBH*LPAD*64];
__device__ bf16 g_KL[(size_t)NBH*LPAD*64];
__device__ bf16 g_VTH[(size_t)NBH*64*LPAD];
__device__ bf16 g_VTL[(size_t)NBH*64*LPAD];
__device__ float g_S[(size_t)NBH*LTOT*LPAD];
__device__ bf16 g_PH[(size_t)NBH*LTOT*LPAD];
__device__ bf16 g_PL[(size_t)NBH*LTOT*LPAD];

// ---------------- fp32 -> bf16 hi/lo (flat) ----------------
__global__ void k_cvtA(const float* __restrict__ s, bf16* __restrict__ hi,
                       bf16* __restrict__ lo, int n4) {
    int i = blockIdx.x*blockDim.x + threadIdx.x;
    if (i >= n4) return;
    float4 v = ((const float4*)s)[i];
    bf16 h0=__float2bfloat16(v.x), h1=__float2bfloat16(v.y),
         h2=__float2bfloat16(v.z), h3=__float2bfloat16(v.w);
    bf16 l0=__float2bfloat16(v.x-__bfloat162float(h0)),
         l1=__float2bfloat16(v.y-__bfloat162float(h1)),
         l2=__float2bfloat16(v.z-__bfloat162float(h2)),
         l3=__float2bfloat16(v.w-__bfloat162float(h3));
    uint2 hp = make_uint2((u32)__bfloat16_as_ushort(h0) | ((u32)__bfloat16_as_ushort(h1)<<16),
                          (u32)__bfloat16_as_ushort(h2) | ((u32)__bfloat16_as_ushort(h3)<<16));
    uint2 lp = make_uint2((u32)__bfloat16_as_ushort(l0) | ((u32)__bfloat16_as_ushort(l1)<<16),
                          (u32)__bfloat16_as_ushort(l2) | ((u32)__bfloat16_as_ushort(l3)<<16));
    ((uint2*)hi)[i] = hp;
    ((uint2*)lo)[i] = lp;
}

// ---------------- fp32 [K][N] -> bf16 hi/lo transposed [N][K] ----------------
__device__ __forceinline__ void cvtB_body(const float* __restrict__ src,
        bf16* __restrict__ hi, bf16* __restrict__ lo, int K, int N) {
    __shared__ float t[32][33];
    int tx = threadIdx.x, ty = threadIdx.y;
    int n0 = blockIdx.x*32, k0 = blockIdx.y*32;
    #pragma unroll
    for (int i = 0; i < 4; i++)
        t[ty + i*8][tx] = src[(size_t)(k0 + ty + i*8)*N + n0 + tx];
    __syncthreads();
    #pragma unroll
    for (int i = 0; i < 4; i++) {
        float v = t[tx][ty + i*8];
        int n = n0 + ty + i*8, kk = k0 + tx;
        bf16 h = __float2bfloat16(v);
        bf16 l = __float2bfloat16(v - __bfloat162float(h));
        hi[(size_t)n*K + kk] = h;
        lo[(size_t)n*K + kk] = l;
    }
}
__global__ void k_cvtB(const float* __restrict__ src, bf16* hi, bf16* lo, int K, int N) {
    cvtB_body(src, hi, lo, K, N);
}
__global__ void k_cvtB_qkv(const float* __restrict__ Wq, const float* __restrict__ Wk,
                           const float* __restrict__ Wv, size_t wo_t, size_t wo_s,
                           bf16* hi, bf16* lo) {
    int z = blockIdx.z;
    const float* base = ((z%3 == 0) ? Wq : (z%3 == 1) ? Wk : Wv) + ((z/3) ? wo_s : wo_t);
    cvtB_body(base, hi + (size_t)z*512*512, lo + (size_t)z*512*512, 512, 512);
}

// ---------------- bf16x3 MMA GEMM with cp.async double-buffer ----------------
__device__ __forceinline__ void mma16816(float* d, const u32* a, const u32* b) {
    asm volatile(
        "mma.sync.aligned.m16n8k16.row.col.f32.bf16.bf16.f32 "
        "{%0,%1,%2,%3}, {%4,%5,%6,%7}, {%8,%9}, {%0,%1,%2,%3};"
        : "+f"(d[0]), "+f"(d[1]), "+f"(d[2]), "+f"(d[3])
        : "r"(a[0]), "r"(a[1]), "r"(a[2]), "r"(a[3]), "r"(b[0]), "r"(b[1]));
}
#define AP 40
#define ABUF (128*AP)
#define BBUF (64*AP)
#define BUFELEM (2*ABUF + 2*BBUF)
#define DSMEM (2*BUFELEM*2)          // 61440 bytes

__device__ __forceinline__ u32 sm32(const void* p) {
    return (u32)__cvta_generic_to_shared(p);
}
__device__ __forceinline__ void cp16(u32 dst, const void* src, int bytes) {
    asm volatile("cp.async.ca.shared.global [%0], [%1], 16, %2;"
                 :: "r"(dst), "l"(src), "r"(bytes));
}

// mode: 0 none, 1 relu, 2 scale+elu
__device__ void mg_body(const bf16* __restrict__ Ahi, const bf16* __restrict__ Alo,
                        const bf16* __restrict__ Bhi, const bf16* __restrict__ Blo,
                        float* __restrict__ C, const float* __restrict__ bias,
                        int M, int N, int K, int mode, int ldc) {
    extern __shared__ bf16 dsm[];
    int tid = threadIdx.x, wid = tid >> 5, lane = tid & 31;
    int wm = wid >> 1, wn = wid & 1, g = lane >> 2, qp = lane & 3;
    int row0 = blockIdx.y << 7, col0 = blockIdx.x << 6;

    auto loadc = [&](int kc, int b) {
        bf16* base = dsm + b*BUFELEM;
        #pragma unroll
        for (int s = 0; s < 2; s++) {
            int slot = s*256 + tid;
            int r = slot >> 2, k16 = (slot & 3) << 3;
            int gr = row0 + r;
            int ok = (gr < M) ? 16 : 0;
            size_t go = (size_t)(gr < M ? gr : 0)*K + kc + k16;
            cp16(sm32(base + r*AP + k16), Ahi + go, ok);
            cp16(sm32(base + ABUF + r*AP + k16), Alo + go, ok);
        }
        {
            int r = tid >> 2, k16 = (tid & 3) << 3;
            size_t go = (size_t)(col0 + r)*K + kc + k16;
            cp16(sm32(base + 2*ABUF + r*AP + k16), Bhi + go, 16);
            cp16(sm32(base + 2*ABUF + BBUF + r*AP + k16), Blo + go, 16);
        }
        asm volatile("cp.async.commit_group;" ::: "memory");
    };

    float acc[2][4][4] = {};
    loadc(0, 0);
    int buf = 0;
    for (int kc = 0; kc < K; kc += 32) {
        bool more = (kc + 32) < K;
        if (more) {
            loadc(kc + 32, buf ^ 1);
            asm volatile("cp.async.wait_group 1;" ::: "memory");
        } else {
            asm volatile("cp.async.wait_group 0;" ::: "memory");
        }
        __syncthreads();
        const bf16* As0 = dsm + buf*BUFELEM;
        const bf16* As1 = As0 + ABUF;
        const bf16* Bs0 = As0 + 2*ABUF;
        const bf16* Bs1 = Bs0 + BBUF;
        #pragma unroll
        for (int ks = 0; ks < 32; ks += 16) {
            u32 ah[2][4], al[2][4], bh[4][2], bl[4][2];
            #pragma unroll
            for (int mt = 0; mt < 2; mt++) {
                int ar = (wm*32 + mt*16 + g)*AP + ks + qp*2;
                int ar8 = ar + 8*AP;
                ah[mt][0] = *(const u32*)&As0[ar];     ah[mt][1] = *(const u32*)&As0[ar8];
                ah[mt][2] = *(const u32*)&As0[ar + 8]; ah[mt][3] = *(const u32*)&As0[ar8 + 8];
                al[mt][0] = *(const u32*)&As1[ar];     al[mt][1] = *(const u32*)&As1[ar8];
                al[mt][2] = *(const u32*)&As1[ar + 8]; al[mt][3] = *(const u32*)&As1[ar8 + 8];
            }
            #pragma unroll
            for (int nt = 0; nt < 4; nt++) {
                int br = (wn*32 + nt*8 + g)*AP + ks + qp*2;
                bh[nt][0] = *(const u32*)&Bs0[br]; bh[nt][1] = *(const u32*)&Bs0[br + 8];
                bl[nt][0] = *(const u32*)&Bs1[br]; bl[nt][1] = *(const u32*)&Bs1[br + 8];
            }
            #pragma unroll
            for (int mt = 0; mt < 2; mt++)
                #pragma unroll
                for (int nt = 0; nt < 4; nt++) {
                    mma16816(acc[mt][nt], ah[mt], bh[nt]);
                    mma16816(acc[mt][nt], ah[mt], bl[nt]);
                    mma16816(acc[mt][nt], al[mt], bh[nt]);
                }
        }
        __syncthreads();
        buf ^= 1;
    }
    #pragma unroll
    for (int mt = 0; mt < 2; mt++) {
        int r0 = row0 + wm*32 + mt*16 + g;
        #pragma unroll
        for (int half = 0; half < 2; half++) {
            int r = r0 + half*8;
            if (r >= M) continue;
            #pragma unroll
            for (int nt = 0; nt < 4; nt++) {
                int cl = col0 + wn*32 + nt*8 + qp*2;
                float v0 = acc[mt][nt][half*2 + 0], v1 = acc[mt][nt][half*2 + 1];
                if (bias) { v0 += bias[cl]; v1 += bias[cl + 1]; }
                if (mode == 1) { v0 = fmaxf(v0, 0.f); v1 = fmaxf(v1, 0.f); }
                else if (mode == 2) {
                    v0 *= 0.9999950000374997f; if (v0 <= 0.f) v0 = expm1f(v0);
                    v1 *= 0.9999950000374997f; if (v1 <= 0.f) v1 = expm1f(v1);
                }
                *(float2*)&C[(size_t)r*ldc + cl] = make_float2(v0, v1);
            }
        }
    }
}

__global__ void __launch_bounds__(256) k_mgemm(
        const bf16* Ahi, const bf16* Alo, const bf16* Bhi, const bf16* Blo,
        float* C, const float* bias, int M, int N, int K, int mode) {
    mg_body(Ahi, Alo, Bhi, Blo, C, bias, M, N, K, mode, N);
}
__global__ void __launch_bounds__(256) k_mgemm_qkv(
        const bf16* Ahi, const bf16* Alo, const bf16* Bhi, const bf16* Blo,
        float* q, float* k, float* v, float* q2, float* k2, float* v2,
        int M, int N, int K) {
    int z = blockIdx.z;
    size_t bo = (size_t)z*512*512;
    float* C = (z==0)?q:(z==1)?k:(z==2)?v:(z==3)?q2:(z==4)?k2:v2;
    mg_body(Ahi, Alo, Bhi + bo, Blo + bo, C, nullptr, M, N, K, 0, N);
}
__global__ void __launch_bounds__(256) k_mgemm_fc(
        const bf16* Ahi, const bf16* Alo, const bf16* Bhi, const bf16* Blo,
        const float* fcb, size_t lo_t, size_t lo_s,
        float* ft, float* fs, int M, int N, int K) {
    int z = blockIdx.z;
    size_t ao = (size_t)z*NROWS*512, bo = (size_t)z*512*512;
    mg_body(Ahi + ao, Alo + ao, Bhi + bo, Blo + bo, z ? fs : ft,
            fcb + (z ? lo_s : lo_t), M, N, K, 0, N);
}
__global__ void __launch_bounds__(256) k_mgemm_sim(
        const bf16* Ahi, const bf16* Alo, int startRow, int n, size_t lvloff,
        float* simbuf) {
    int b = blockIdx.z;
    size_t ao = ((size_t)(b*LTOT + startRow))*512;
    float* C = simbuf + (size_t)b*SIMB + lvloff;
    mg_body(Ahi + ao, Alo + ao, Ahi + ao, Alo + ao, C, nullptr, n, n, 512, 0, n);
}
__global__ void __launch_bounds__(256) k_mgemm_att_s(
        const bf16* QH, const bf16* QL, const bf16* KH, const bf16* KL, float* S) {
    int bh = blockIdx.z;
    size_t qo = (size_t)bh*LPAD*64;
    mg_body(QH + qo, QL + qo, KH + qo, KL + qo,
            S + (size_t)bh*LTOT*LPAD, nullptr, LTOT, LPAD, 64, 0, LPAD);
}
__global__ void __launch_bounds__(256) k_mgemm_att_pv(
        const bf16* PH, const bf16* PL, const bf16* VTH, const bf16* VTL, float* O) {
    int bh = blockIdx.z, b = bh >> 3, h = bh & 7;
    size_t po = (size_t)bh*LTOT*LPAD, vo = (size_t)bh*64*LPAD;
    mg_body(PH + po, PL + po, VTH + vo, VTL + vo,
            O + ((size_t)b*LTOT)*512 + h*64, nullptr, LTOT, 64, LPAD, 0, 512);
}

// ---------------- attention operand conversion ----------------
__global__ void k_cvt_qk(const float* __restrict__ q2, const float* __restrict__ k2,
                         bf16* QH, bf16* QL, bf16* KH, bf16* KL) {
    long idx = (long)blockIdx.x*256 + threadIdx.x;
    if (idx >= (long)NBH*LPAD*64) return;
    int d = idx & 63;
    long r_ = idx >> 6;
    int r = (int)(r_ % LPAD);
    int bh = (int)(r_ / LPAD);
    int b = bh >> 3, h = bh & 7;
    float qv = 0.f, kv = 0.f;
    if (r < LTOT) {
        size_t off = ((size_t)(b*LTOT + r))*512 + h*64 + d;
        qv = q2[off]; kv = k2[off];
    }
    bf16 qh = __float2bfloat16(qv);
    bf16 ql = __float2bfloat16(qv - __bfloat162float(qh));
    bf16 kh = __float2bfloat16(kv);
    bf16 kl = __float2bfloat16(kv - __bfloat162float(kh));
    QH[idx] = qh; QL[idx] = ql; KH[idx] = kh; KL[idx] = kl;
}
__global__ void k_cvt_vt(const float* __restrict__ v2, bf16* VTH, bf16* VTL) {
    __shared__ float t[32][33];
    int bh = blockIdx.z, b = bh >> 3, h = bh & 7;
    int j0 = blockIdx.x*32, d0 = blockIdx.y*32;
    int tx = threadIdx.x, ty = threadIdx.y;
    #pragma unroll
    for (int i = 0; i < 4; i++) {
        int j = j0 + ty + i*8;
        t[ty + i*8][tx] = (j < LTOT)
            ? v2[((size_t)(b*LTOT + j))*512 + h*64 + d0 + tx] : 0.f;
    }
    __syncthreads();
    #pragma unroll
    for (int i = 0; i < 4; i++) {
        int d = d0 + ty + i*8, j = j0 + tx;
        float v = t[tx][ty + i*8];
        bf16 hh = __float2bfloat16(v);
        bf16 ll = __float2bfloat16(v - __bfloat162float(hh));
        size_t off = ((size_t)bh*64 + d)*LPAD + j;
        VTH[off] = hh; VTL[off] = ll;
    }
}

// ---------------- reductions ----------------
__device__ __forceinline__ float block_max256(float v) {
    __shared__ float red[8];
    int lane = threadIdx.x & 31, w = threadIdx.x >> 5;
    #pragma unroll
    for (int o = 16; o; o >>= 1) v = fmaxf(v, __shfl_xor_sync(0xffffffffu, v, o));
    if (lane == 0) red[w] = v;
    __syncthreads();
    if (w == 0) {
        float t = (lane < 8) ? red[lane] : -1e30f;
        #pragma unroll
        for (int o = 4; o; o >>= 1) t = fmaxf(t, __shfl_xor_sync(0xffffffffu, t, o));
        if (lane == 0) red[0] = t;
    }
    __syncthreads();
    float r = red[0];
    __syncthreads();
    return r;
}
__device__ __forceinline__ float block_sum256(float v) {
    __shared__ float red[8];
    int lane = threadIdx.x & 31, w = threadIdx.x >> 5;
    #pragma unroll
    for (int o = 16; o; o >>= 1) v += __shfl_xor_sync(0xffffffffu, v, o);
    if (lane == 0) red[w] = v;
    __syncthreads();
    if (w == 0) {
        float t = (lane < 8) ? red[lane] : 0.f;
        #pragma unroll
        for (int o = 4; o; o >>= 1) t += __shfl_xor_sync(0xffffffffu, t, o);
        if (lane == 0) red[0] = t;
    }
    __syncthreads();
    float r = red[0];
    __syncthreads();
    return r;
}

__global__ void __launch_bounds__(256) k_softmax_p(
        const float* __restrict__ S, const unsigned char* __restrict__ smask,
        bf16* __restrict__ PH, bf16* __restrict__ PL) {
    int row = blockIdx.x, bh = blockIdx.y, b = bh >> 3;
    int tid = threadIdx.x;
    __shared__ float buf[LTOT];
    const float* srow = S + ((size_t)bh*LTOT + row)*LPAD;
    const unsigned char* mrow = smask + ((size_t)b*LTOT + row)*LTOT;
    float mx = -1e30f;
    for (int j = tid; j < LTOT; j += 256) {
        float s = mrow[j] ? -1e30f : srow[j]*0.125f;
        buf[j] = s;
        mx = fmaxf(mx, s);
    }
    mx = block_max256(mx);
    float sum = 0.f;
    for (int j = tid; j < LTOT; j += 256) {
        float e = expf(buf[j] - mx);
        buf[j] = e; sum += e;
    }
    sum = block_sum256(sum);
    float inv = 1.f / sum;
    bf16* ph = PH + ((size_t)bh*LTOT + row)*LPAD;
    bf16* pl = PL + ((size_t)bh*LTOT + row)*LPAD;
    for (int j = tid; j < LPAD; j += 256) {
        float p = (j < LTOT) ? buf[j]*inv : 0.f;
        bf16 hh = __float2bfloat16(p);
        bf16 ll = __float2bfloat16(p - __bfloat162float(hh));
        ph[j] = hh; pl[j] = ll;
    }
}

// ---------------- conv weight re-layout ----------------
__global__ void k_convw(const float* __restrict__ w, float* __restrict__ wm) {
    int idx = blockIdx.x*blockDim.x + threadIdx.x;
    if (idx >= 3*2048*512) return;
    int l  = idx / (2048*512);
    int r  = idx - l*2048*512;
    int kk = r >> 9, co = r & 511;
    int t  = kk >> 9, ci = kk & 511;
    wm[idx] = w[(((size_t)(l*512 + co))*512 + ci)*4 + t];
}

// ---------------- concat + LN(1e-5) ----------------
__global__ void __launch_bounds__(256) k_concat_ln(
        const float* __restrict__ xe, const float* __restrict__ pyr,
        const float* __restrict__ g, const float* __restrict__ bt,
        float* __restrict__ out) {
    int row = blockIdx.x;
    int b = row / LTOT, i = row % LTOT;
    const float* src = (i < 1024) ? xe + ((size_t)(b*1024 + i))*512
                                  : pyr + ((size_t)(b*336 + (i - 1024)))*512;
    int t = threadIdx.x;
    float v0 = src[t], v1 = src[t + 256];
    float mu = block_sum256(v0 + v1) * (1.f/512.f);
    float d0 = v0 - mu, d1 = v1 - mu;
    float var = block_sum256(d0*d0 + d1*d1) * (1.f/512.f);
    float rs = rsqrtf(var + 1e-5f);
    float* o = out + (size_t)row*512;
    o[t]       = d0*rs*g[t]       + bt[t];
    o[t + 256] = d1*rs*g[t + 256] + bt[t + 256];
}

// ---------------- (a+res) -> LN ----------------
__global__ void __launch_bounds__(256) k_add_ln(
        const float* __restrict__ a, const float* __restrict__ res,
        const float* __restrict__ g, const float* __restrict__ bt,
        float* __restrict__ out, float eps) {
    int row = blockIdx.x, t = threadIdx.x;
    const float* pa = a + (size_t)row*512;
    const float* pr = res + (size_t)row*512;
    float v0 = pa[t] + pr[t], v1 = pa[t + 256] + pr[t + 256];
    float mu = block_sum256(v0 + v1) * (1.f/512.f);
    float d0 = v0 - mu, d1 = v1 - mu;
    float var = block_sum256(d0*d0 + d1*d1) * (1.f/512.f);
    float rs = rsqrtf(var + eps);
    float* o = out + (size_t)row*512;
    o[t]       = d0*rs*g[t]       + bt[t];
    o[t + 256] = d1*rs*g[t + 256] + bt[t + 256];
}

// ---------------- fused: both branch LNs + (t+s+x)/3 combine ----------------
__global__ void __launch_bounds__(256) k_lncomb(
        const float* __restrict__ fc, const float* __restrict__ fc2,
        float* __restrict__ x,
        const float* __restrict__ g, const float* __restrict__ bt,
        size_t lo_t, size_t lo_s) {
    int row = blockIdx.x, t = threadIdx.x;
    const float* pa = fc + (size_t)row*512;
    const float* pb = fc2 + (size_t)row*512;
    float* px = x + (size_t)row*512;
    float x0 = px[t], x1 = px[t + 256];
    float a0 = pa[t] + x0, a1 = pa[t + 256] + x1;
    float b0 = pb[t] + x0, b1 = pb[t + 256] + x1;
    // t-branch LN
    float mu = block_sum256(a0 + a1) * (1.f/512.f);
    a0 -= mu; a1 -= mu;
    float var = block_sum256(a0*a0 + a1*a1) * (1.f/512.f);
    float rs = rsqrtf(var + 1e-6f);
    float t0 = a0*rs*g[lo_t + t]       + bt[lo_t + t];
    float t1 = a1*rs*g[lo_t + t + 256] + bt[lo_t + t + 256];
    // s-branch LN
    mu = block_sum256(b0 + b1) * (1.f/512.f);
    b0 -= mu; b1 -= mu;
    var = block_sum256(b0*b0 + b1*b1) * (1.f/512.f);
    rs = rsqrtf(var + 1e-6f);
    float s0 = b0*rs*g[lo_s + t]       + bt[lo_s + t];
    float s1 = b1*rs*g[lo_s + t + 256] + bt[lo_s + t + 256];
    px[t]       = (t0 + s0 + x0) * (1.f/3.f);
    px[t + 256] = (t1 + s1 + x1) * (1.f/3.f);
}

// ---------------- row L2 normalize ----------------
__global__ void __launch_bounds__(256) k_rownorm(
        const float* __restrict__ x, float* __restrict__ xn) {
    int row = blockIdx.x, t = threadIdx.x;
    const float* p = x + (size_t)row*512;
    float v0 = p[t], v1 = p[t + 256];
    float ss = block_sum256(v0*v0 + v1*v1);
    float inv = 1.f / fmaxf(sqrtf(ss), 1e-8f);
    float* o = xn + (size_t)row*512;
    o[t] = v0*inv; o[t + 256] = v1*inv;
}

// ---------------- top-k select ----------------
__global__ void __launch_bounds__(256) k_topksel(
        const float* __restrict__ xn, const float* __restrict__ simbuf,
        unsigned char* __restrict__ smask) {
    int i = blockIdx.x, b = blockIdx.y, tid = threadIdx.x;
    const int starts[4] = {0,1024,1280,1344};
    const int sizes[4]  = {1024,256,64,16};
    int lev = (i<1024)?0:(i<1280)?1:(i<1344)?2:3;
    int st = starts[lev], n = sizes[lev];
    int kk = n < 32 ? n : 32;
    __shared__ float sims[1024];
    __shared__ float qrow[512];
    __shared__ float wv[8]; __shared__ int wi[8];
    unsigned char* mrow = smask + ((size_t)b*LTOT + i)*LTOT + st;
    for (int j = tid; j < n; j += 256) mrow[j] = 0;
    if (lev <= 1) {
        size_t lvloff = (lev == 0) ? 0 : 1048576;
        const float* srow = simbuf + (size_t)b*SIMB + lvloff + (size_t)(i - st)*n;
        for (int j = tid; j < n; j += 256) sims[j] = srow[j];
        __syncthreads();
    } else {
        const float* xb = xn + (size_t)b*LTOT*512;
        for (int d = tid; d < 512; d += 256) qrow[d] = xb[(size_t)i*512 + d];
        __syncthreads();
        int w = tid >> 5, lane = tid & 31;
        for (int j = w; j < n; j += 8) {
            const float* rj = xb + (size_t)(st + j)*512;
            float p = 0.f;
            #pragma unroll 4
            for (int d = lane; d < 512; d += 32) p += qrow[d]*rj[d];
            #pragma unroll
            for (int o = 16; o; o >>= 1) p += __shfl_xor_sync(0xffffffffu, p, o);
            if (lane == 0) sims[j] = p;
        }
        __syncthreads();
    }
    int w = tid >> 5, lane = tid & 31;
    for (int it = 0; it < kk; it++) {
        float bv = -3.f; int bi = n;
        for (int j = tid; j < n; j += 256) {
            float v = sims[j];
            if (v > bv) { bv = v; bi = j; }
        }
        #pragma unroll
        for (int o = 16; o; o >>= 1) {
            float ov = __shfl_xor_sync(0xffffffffu, bv, o);
            int   oi = __shfl_xor_sync(0xffffffffu, bi, o);
            if (ov > bv || (ov == bv && oi < bi)) { bv = ov; bi = oi; }
        }
        if (lane == 0) { wv[w] = bv; wi[w] = bi; }
        __syncthreads();
        if (tid == 0) {
            float fv = wv[0]; int fi = wi[0];
            #pragma unroll
            for (int z = 1; z < 8; z++)
                if (wv[z] > fv || (wv[z] == fv && wi[z] < fi)) { fv = wv[z]; fi = wi[z]; }
            mrow[fi] = 1;
            sims[fi] = -3.f;
        }
        __syncthreads();
    }
}

// ---------------- SPARSE temporal attention ----------------
__global__ void __launch_bounds__(256) k_tattn(
        const float* __restrict__ Q, const float* __restrict__ K,
        const float* __restrict__ V, float* __restrict__ O) {
    int i = blockIdx.x, b = blockIdx.y;
    int h = threadIdx.x >> 5, lane = threadIdx.x & 31;
    const int starts[4] = {0,1024,1280,1344};
    const int sizes[4]  = {1024,256,64,16};
    int lev = (i<1024)?0:(i<1280)?1:(i<1344)?2:3;
    int st = starts[lev], n = sizes[lev];
    int nb[10]; int cnt = 0;
    int lo = (i-2 < st) ? st : i-2;
    int hi = (i+2 > st+n-1) ? st+n-1 : i+2;
    for (int j = lo; j <= hi; j++) nb[cnt++] = j;
    if (lev > 0) {
        int c0 = starts[lev-1] + (i - st)*4;
        nb[cnt++] = c0; nb[cnt++] = c0+1; nb[cnt++] = c0+2; nb[cnt++] = c0+3;
    }
    if (lev < 3) nb[cnt++] = starts[lev+1] + (i - st)/4;

    size_t rowb = (size_t)(b*LTOT);
    const float2 qv = *(const float2*)(Q + (rowb + i)*512 + h*64 + lane*2);
    float sc[10];
    #pragma unroll
    for (int t = 0; t < 10; t++) {
        if (t < cnt) {
            float2 kv = *(const float2*)(K + (rowb + nb[t])*512 + h*64 + lane*2);
            float p = qv.x*kv.x + qv.y*kv.y;
            #pragma unroll
            for (int o = 16; o; o >>= 1) p += __shfl_xor_sync(0xffffffffu, p, o);
            sc[t] = p * 0.125f;
        } else sc[t] = -1e30f;
    }
    float mx = -1e30f;
    #pragma unroll
    for (int t = 0; t < 10; t++) mx = fmaxf(mx, sc[t]);
    float ssum = 0.f;
    #pragma unroll
    for (int t = 0; t < 10; t++) {
        sc[t] = (t < cnt) ? expf(sc[t] - mx) : 0.f;
        ssum += sc[t];
    }
    float inv = 1.f / ssum;
    float ax = 0.f, ay = 0.f;
    #pragma unroll
    for (int t = 0; t < 10; t++) {
        if (t < cnt) {
            float2 vv = *(const float2*)(V + (rowb + nb[t])*512 + h*64 + lane*2);
            ax += sc[t]*vv.x; ay += sc[t]*vv.y;
        }
    }
    *(float2*)(O + (rowb + i)*512 + h*64 + lane*2) = make_float2(ax*inv, ay*inv);
}

// ---------------- pyramid concat ----------------
__global__ void k_pyrcat(const float* __restrict__ c1, const float* __restrict__ c2,
                         const float* __restrict__ c3, float* __restrict__ out) {
    int idx = blockIdx.x*blockDim.x + threadIdx.x;
    if (idx >= BATCH*336*512) return;
    int d = idx & 511, r = idx >> 9;
    int b = r / 336, p = r % 336;
    float v;
    if (p < 256) v = c1[((size_t)(b*256 + p) << 9) | d];
    else if (p < 320) v = c2[((size_t)(b*64 + p - 256) << 9) | d];
    else v = c3[((size_t)(b*16 + p - 320) << 9) | d];
    out[idx] = v;
}

// ---------------- orchestration ----------------
static bf16 *s_ahi, *s_alo, *s_bhi, *s_blo;

static void mgemm(const float* A, const float* B, float* C, const float* bias,
                  int M, int N, int K, int mode) {
    int n4 = M*K/4;
    k_cvtA<<<(n4 + 255)/256, 256>>>(A, s_ahi, s_alo, n4);
    k_cvtB<<<dim3(N/32, K/32), dim3(32, 8)>>>(B, s_bhi, s_blo, K, N);
    dim3 g(N/64, (M + 127)/128);
    k_mgemm<<<g, 256, DSMEM>>>(s_ahi, s_alo, s_bhi, s_blo, C, bias, M, N, K, mode);
}

extern "C" void kernel_launch(void* const* d_in, const int* in_sizes, int n_in,
                              void* d_out, int out_size) {
    const float* x_enc  = (const float*)d_in[0];
    const float* down_W = (const float*)d_in[1];
    const float* down_b = (const float*)d_in[2];
    const float* conv_W = (const float*)d_in[3];
    const float* conv_b = (const float*)d_in[4];
    const float* up_W   = (const float*)d_in[5];
    const float* up_b   = (const float*)d_in[6];
    const float* bc_g   = (const float*)d_in[7];
    const float* bc_b   = (const float*)d_in[8];
    const float* Wq     = (const float*)d_in[9];
    const float* Wk     = (const float*)d_in[10];
    const float* Wv     = (const float*)d_in[11];
    const float* fcW    = (const float*)d_in[12];
    const float* fcb    = (const float*)d_in[13];
    const float* aln_g  = (const float*)d_in[14];
    const float* aln_b  = (const float*)d_in[15];
    const float* W1     = (const float*)d_in[16];
    const float* b1     = (const float*)d_in[17];
    const float* W2     = (const float*)d_in[18];
    const float* b2     = (const float*)d_in[19];
    const float* fln_g  = (const float*)d_in[20];
    const float* fln_b  = (const float*)d_in[21];
    float* out = (float*)d_out;

    float *t0,*c1,*c2,*c3,*pc,*pyr,*x,*q,*k,*v,*q2,*k2,*v2,*o,*o2,*fc,*fc2,
          *xn,*h,*wc,*sim,*S;
    bf16 *QH,*QL,*KH,*KL,*VTH,*VTL,*PH,*PL;
    unsigned char *smk;
    cudaGetSymbolAddress((void**)&t0,  g_t0);
    cudaGetSymbolAddress((void**)&c1,  g_c1);
    cudaGetSymbolAddress((void**)&c2,  g_c2);
    cudaGetSymbolAddress((void**)&c3,  g_c3);
    cudaGetSymbolAddress((void**)&pc,  g_pc);
    cudaGetSymbolAddress((void**)&pyr, g_pyr);
    cudaGetSymbolAddress((void**)&x,   g_x);
    cudaGetSymbolAddress((void**)&q,   g_q);
    cudaGetSymbolAddress((void**)&k,   g_k);
    cudaGetSymbolAddress((void**)&v,   g_v);
    cudaGetSymbolAddress((void**)&q2,  g_q2);
    cudaGetSymbolAddress((void**)&k2,  g_k2);
    cudaGetSymbolAddress((void**)&v2,  g_v2);
    cudaGetSymbolAddress((void**)&o,   g_o);
    cudaGetSymbolAddress((void**)&o2,  g_o2);
    cudaGetSymbolAddress((void**)&fc,  g_fc);
    cudaGetSymbolAddress((void**)&fc2, g_fc2);
    cudaGetSymbolAddress((void**)&xn,  g_xn);
    cudaGetSymbolAddress((void**)&h,   g_h);
    cudaGetSymbolAddress((void**)&wc,  g_wc);
    cudaGetSymbolAddress((void**)&sim, g_sim);
    cudaGetSymbolAddress((void**)&S,   g_S);
    cudaGetSymbolAddress((void**)&QH,  g_QH);
    cudaGetSymbolAddress((void**)&QL,  g_QL);
    cudaGetSymbolAddress((void**)&KH,  g_KH);
    cudaGetSymbolAddress((void**)&KL,  g_KL);
    cudaGetSymbolAddress((void**)&VTH, g_VTH);
    cudaGetSymbolAddress((void**)&VTL, g_VTL);
    cudaGetSymbolAddress((void**)&PH,  g_PH);
    cudaGetSymbolAddress((void**)&PL,  g_PL);
    cudaGetSymbolAddress((void**)&smk, g_sm);
    cudaGetSymbolAddress((void**)&s_ahi, g_ahi);
    cudaGetSymbolAddress((void**)&s_alo, g_alo);
    cudaGetSymbolAddress((void**)&s_bhi, g_bhi);
    cudaGetSymbolAddress((void**)&s_blo, g_blo);

    cudaFuncSetAttribute(k_mgemm,        cudaFuncAttributeMaxDynamicSharedMemorySize, DSMEM);
    cudaFuncSetAttribute(k_mgemm_qkv,    cudaFuncAttributeMaxDynamicSharedMemorySize, DSMEM);
    cudaFuncSetAttribute(k_mgemm_fc,     cudaFuncAttributeMaxDynamicSharedMemorySize, DSMEM);
    cudaFuncSetAttribute(k_mgemm_sim,    cudaFuncAttributeMaxDynamicSharedMemorySize, DSMEM);
    cudaFuncSetAttribute(k_mgemm_att_s,  cudaFuncAttributeMaxDynamicSharedMemorySize, DSMEM);
    cudaFuncSetAttribute(k_mgemm_att_pv, cudaFuncAttributeMaxDynamicSharedMemorySize, DSMEM);

    k_convw<<<(3*2048*512 + 255)/256, 256>>>(conv_W, wc);

    // bottleneck
    mgemm(x_enc, down_W, t0, down_b, BATCH*1024, 512, 512, 0);
    mgemm(t0, wc,              c1, conv_b,        BATCH*256, 512, 2048, 2);
    mgemm(c1, wc + 2048*512,   c2, conv_b + 512,  BATCH*64,  512, 2048, 2);
    mgemm(c2, wc + 2*2048*512, c3, conv_b + 1024, BATCH*16,  512, 2048, 2);
    k_pyrcat<<<(BATCH*336*512 + 255)/256, 256>>>(c1, c2, c3, pc);
    mgemm(pc, up_W, pyr, up_b, BATCH*336, 512, 512, 0);
    k_concat_ln<<<NROWS, 256>>>(x_enc, pyr, bc_g, bc_b, x);

    for (int l = 0; l < 2; l++) {
        // ---- semantic mask via Gram GEMM + select ----
        k_rownorm<<<NROWS, 256>>>(x, xn);
        {
            int n4 = NROWS*512/4;
            k_cvtA<<<(n4 + 255)/256, 256>>>(xn, s_ahi, s_alo, n4);
            dim3 g0(1024/64, 1024/128, BATCH);
            k_mgemm_sim<<<g0, 256, DSMEM>>>(s_ahi, s_alo, 0,    1024, 0,       sim);
            dim3 g1(256/64, 256/128, BATCH);
            k_mgemm_sim<<<g1, 256, DSMEM>>>(s_ahi, s_alo, 1024, 256,  1048576, sim);
            dim3 tg(LTOT, BATCH);
            k_topksel<<<tg, 256>>>(xn, sim, smk);
        }

        size_t wo_t = ((size_t)l*2 + 0)*512*512, wo_s = ((size_t)l*2 + 1)*512*512;
        size_t lo_t = ((size_t)l*2 + 0)*512,     lo_s = ((size_t)l*2 + 1)*512;

        // QKV x6 fused
        {
            int n4 = NROWS*512/4;
            k_cvtA<<<(n4 + 255)/256, 256>>>(x, s_ahi, s_alo, n4);
            k_cvtB_qkv<<<dim3(16, 16, 6), dim3(32, 8)>>>(Wq, Wk, Wv, wo_t, wo_s,
                                                         s_bhi, s_blo);
            dim3 qg(8, (NROWS + 127)/128, 6);
            k_mgemm_qkv<<<qg, 256, DSMEM>>>(s_ahi, s_alo, s_bhi, s_blo,
                                            q, k, v, q2, k2, v2, NROWS, 512, 512);
        }
        // temporal branch (sparse, fp32)
        dim3 sg(LTOT, BATCH);
        k_tattn<<<sg, 256>>>(q, k, v, o);

        // semantic branch on tensor cores
        {
            long tot = (long)NBH*LPAD*64;
            k_cvt_qk<<<(unsigned)((tot + 255)/256), 256>>>(q2, k2, QH, QL, KH, KL);
            k_cvt_vt<<<dim3(LPAD/32, 2, NBH), dim3(32, 8)>>>(v2, VTH, VTL);
            dim3 gs(LPAD/64, (LTOT + 127)/128, NBH);
            k_mgemm_att_s<<<gs, 256, DSMEM>>>(QH, QL, KH, KL, S);
            dim3 gp(LTOT, NBH);
            k_softmax_p<<<gp, 256>>>(S, smk, PH, PL);
            dim3 gv(1, (LTOT + 127)/128, NBH);
            k_mgemm_att_pv<<<gv, 256, DSMEM>>>(PH, PL, VTH, VTL, o2);
        }

        // fc x2 fused
        {
            int n4 = NROWS*512/4;
            k_cvtA<<<(n4 + 255)/256, 256>>>(o,  s_ahi, s_alo, n4);
            k_cvtA<<<(n4 + 255)/256, 256>>>(o2, s_ahi + (size_t)NROWS*512,
                                                s_alo + (size_t)NROWS*512, n4);
            k_cvtB<<<dim3(16, 16), dim3(32, 8)>>>(fcW + wo_t, s_bhi, s_blo, 512, 512);
            k_cvtB<<<dim3(16, 16), dim3(32, 8)>>>(fcW + wo_s, s_bhi + (size_t)512*512,
                                                  s_blo + (size_t)512*512, 512, 512);
            dim3 fg(8, (NROWS + 127)/128, 2);
            k_mgemm_fc<<<fg, 256, DSMEM>>>(s_ahi, s_alo, s_bhi, s_blo,
                                           fcb, lo_t, lo_s, fc, fc2, NROWS, 512, 512);
        }
        // fused dual-LN + combine (writes x in place)
        k_lncomb<<<NROWS, 256>>>(fc, fc2, x, aln_g, aln_b, lo_t, lo_s);

        size_t fo = (size_t)l*512*512, fb = (size_t)l*512;
        mgemm(x, W1 + fo, h, b1 + fb, NROWS, 512, 512, 1);
        mgemm(h, W2 + fo, fc, b2 + fb, NROWS, 512, 512, 0);
        k_add_ln<<<NROWS, 256>>>(fc, x, fln_g + fb, fln_b + fb,
                                 (l == 0) ? x : out, 1e-6f);
    }
}

// round 11
// speedup vs baseline: 3.9563x; 1.0087x over previous
#include <cuda_runtime.h>
#include <cuda_bf16.h>
#include <math.h>
#include <stdint.h>

#define LTOT   1360
#define BATCH  4
#define NROWS  (BATCH*LTOT)          // 5440
#define L2SZ   ((size_t)LTOT*LTOT)
#define SIMB   (1048576 + 65536)
#define LPAD   1408
#define NBH    (BATCH*8)

// weight arena element offsets
#define WOFF_DOWN 0
#define WOFF_UP   262144
#define WOFF_CONV 524288
#define WOFF_QKV  3670016
#define WOFF_FC   6815744
#define WOFF_FFN1 7864320
#define WOFF_FFN2 8388608
#define WTOT      8912896

typedef __nv_bfloat16 bf16;
typedef unsigned int u32;

// ---------------- static device scratch ----------------
__device__ float g_c1[BATCH*256*512];
__device__ float g_c2[BATCH*64*512];
__device__ float g_c3[BATCH*16*512];
__device__ float g_pyr[BATCH*336*512];
__device__ float g_x[NROWS*512];
__device__ float g_q[NROWS*512];
__device__ float g_k[NROWS*512];
__device__ float g_v[NROWS*512];
__device__ float g_q2[NROWS*512];
__device__ float g_k2[NROWS*512];
__device__ float g_v2[NROWS*512];
__device__ float g_fc[NROWS*512];
__device__ float g_fc2[NROWS*512];
__device__ float g_xn[NROWS*512];
__device__ float g_wc[3*2048*512];
__device__ float g_sim[(size_t)BATCH*SIMB];
__device__ unsigned char g_sm[(size_t)BATCH*LTOT*LTOT];
// bf16 hi/lo operand buffers
__device__ bf16 g_wHI[WTOT];
__device__ bf16 g_wLO[WTOT];
__device__ bf16 g_xhi[NROWS*512];
__device__ bf16 g_xlo[NROWS*512];
__device__ bf16 g_xnhi[NROWS*512];
__device__ bf16 g_xnlo[NROWS*512];
__device__ bf16 g_oohi[2*NROWS*512];
__device__ bf16 g_oolo[2*NROWS*512];
__device__ bf16 g_hhi[NROWS*512];
__device__ bf16 g_hlo[NROWS*512];
// attention buffers
__device__ bf16 g_QH[(size_t)NBH*LPAD*64];
__device__ bf16 g_QL[(size_t)NBH*LPAD*64];
__device__ bf16 g_KH[(size_t)NBH*LPAD*64];
__device__ bf16 g_KL[(size_t)NBH*LPAD*64];
__device__ bf16 g_VTH[(size_t)NBH*64*LPAD];
__device__ bf16 g_VTL[(size_t)NBH*64*LPAD];
__device__ float g_S[(size_t)NBH*LTOT*LPAD];
__device__ bf16 g_PH[(size_t)NBH*LTOT*LPAD];
__device__ bf16 g_PL[(size_t)NBH*LTOT*LPAD];

__device__ __forceinline__ void wr_hl(bf16* hi, bf16* lo, size_t idx, float v) {
    bf16 h = __float2bfloat16(v);
    hi[idx] = h;
    lo[idx] = __float2bfloat16(v - __bfloat162float(h));
}

// ---------------- fp32 -> bf16 hi/lo (flat) ----------------
__global__ void k_cvtA(const float* __restrict__ s, bf16* __restrict__ hi,
                       bf16* __restrict__ lo, int n4) {
    int i = blockIdx.x*blockDim.x + threadIdx.x;
    if (i >= n4) return;
    float4 v = ((const float4*)s)[i];
    bf16 h0=__float2bfloat16(v.x), h1=__float2bfloat16(v.y),
         h2=__float2bfloat16(v.z), h3=__float2bfloat16(v.w);
    bf16 l0=__float2bfloat16(v.x-__bfloat162float(h0)),
         l1=__float2bfloat16(v.y-__bfloat162float(h1)),
         l2=__float2bfloat16(v.z-__bfloat162float(h2)),
         l3=__float2bfloat16(v.w-__bfloat162float(h3));
    uint2 hp = make_uint2((u32)__bfloat16_as_ushort(h0) | ((u32)__bfloat16_as_ushort(h1)<<16),
                          (u32)__bfloat16_as_ushort(h2) | ((u32)__bfloat16_as_ushort(h3)<<16));
    uint2 lp = make_uint2((u32)__bfloat16_as_ushort(l0) | ((u32)__bfloat16_as_ushort(l1)<<16),
                          (u32)__bfloat16_as_ushort(l2) | ((u32)__bfloat16_as_ushort(l3)<<16));
    ((uint2*)hi)[i] = hp;
    ((uint2*)lo)[i] = lp;
}

// ---------------- fp32 [K][N] -> bf16 hi/lo transposed [N][K] ----------------
__device__ __forceinline__ void cvtB_body(const float* __restrict__ src,
        bf16* __restrict__ hi, bf16* __restrict__ lo, int K, int N) {
    __shared__ float t[32][33];
    int tx = threadIdx.x, ty = threadIdx.y;
    int n0 = blockIdx.x*32, k0 = blockIdx.y*32;
    #pragma unroll
    for (int i = 0; i < 4; i++)
        t[ty + i*8][tx] = src[(size_t)(k0 + ty + i*8)*N + n0 + tx];
    __syncthreads();
    #pragma unroll
    for (int i = 0; i < 4; i++) {
        float v = t[tx][ty + i*8];
        int n = n0 + ty + i*8, kk = k0 + tx;
        wr_hl(hi, lo, (size_t)n*K + kk, v);
    }
}
__global__ void k_cvtB(const float* __restrict__ src, bf16* hi, bf16* lo, int K, int N) {
    cvtB_body(src, hi, lo, K, N);
}
__global__ void k_cvtB_multi(const float* __restrict__ src, bf16* hi, bf16* lo,
                             int K, int N) {
    size_t off = (size_t)blockIdx.z*K*N;
    cvtB_body(src + off, hi + off, lo + off, K, N);
}
__global__ void k_cvtW_qkv12(const float* __restrict__ Wq, const float* __restrict__ Wk,
                             const float* __restrict__ Wv, bf16* hi, bf16* lo) {
    int z = blockIdx.z;
    int l = z/6, rem = z%6, s = rem/3, c = rem%3;
    const float* base = ((c==0)?Wq:(c==1)?Wk:Wv) + ((size_t)(l*2+s))*262144;
    cvtB_body(base, hi + (size_t)z*262144, lo + (size_t)z*262144, 512, 512);
}

// ---------------- bf16x3 MMA GEMM with cp.async double-buffer ----------------
__device__ __forceinline__ void mma16816(float* d, const u32* a, const u32* b) {
    asm volatile(
        "mma.sync.aligned.m16n8k16.row.col.f32.bf16.bf16.f32 "
        "{%0,%1,%2,%3}, {%4,%5,%6,%7}, {%8,%9}, {%0,%1,%2,%3};"
        : "+f"(d[0]), "+f"(d[1]), "+f"(d[2]), "+f"(d[3])
        : "r"(a[0]), "r"(a[1]), "r"(a[2]), "r"(a[3]), "r"(b[0]), "r"(b[1]));
}
#define AP 40
#define ABUF (128*AP)
#define BBUF (64*AP)
#define BUFELEM (2*ABUF + 2*BBUF)
#define DSMEM (2*BUFELEM*2)

__device__ __forceinline__ u32 sm32(const void* p) {
    return (u32)__cvta_generic_to_shared(p);
}
__device__ __forceinline__ void cp16(u32 dst, const void* src, int bytes) {
    asm volatile("cp.async.ca.shared.global [%0], [%1], 16, %2;"
                 :: "r"(dst), "l"(src), "r"(bytes));
}

// mode: 0 none, 1 relu, 2 scale+elu. C and/or Chi may be null.
__device__ void mg_body(const bf16* __restrict__ Ahi, const bf16* __restrict__ Alo,
                        const bf16* __restrict__ Bhi, const bf16* __restrict__ Blo,
                        float* __restrict__ C, bf16* __restrict__ Chi,
                        bf16* __restrict__ Clo, const float* __restrict__ bias,
                        int M, int N, int K, int mode, int ldc) {
    extern __shared__ bf16 dsm[];
    int tid = threadIdx.x, wid = tid >> 5, lane = tid & 31;
    int wm = wid >> 1, wn = wid & 1, g = lane >> 2, qp = lane & 3;
    int row0 = blockIdx.y << 7, col0 = blockIdx.x << 6;

    auto loadc = [&](int kc, int b) {
        bf16* base = dsm + b*BUFELEM;
        #pragma unroll
        for (int s = 0; s < 2; s++) {
            int slot = s*256 + tid;
            int r = slot >> 2, k16 = (slot & 3) << 3;
            int gr = row0 + r;
            int ok = (gr < M) ? 16 : 0;
            size_t go = (size_t)(gr < M ? gr : 0)*K + kc + k16;
            cp16(sm32(base + r*AP + k16), Ahi + go, ok);
            cp16(sm32(base + ABUF + r*AP + k16), Alo + go, ok);
        }
        {
            int r = tid >> 2, k16 = (tid & 3) << 3;
            size_t go = (size_t)(col0 + r)*K + kc + k16;
            cp16(sm32(base + 2*ABUF + r*AP + k16), Bhi + go, 16);
            cp16(sm32(base + 2*ABUF + BBUF + r*AP + k16), Blo + go, 16);
        }
        asm volatile("cp.async.commit_group;" ::: "memory");
    };

    float acc[2][4][4] = {};
    loadc(0, 0);
    int buf = 0;
    for (int kc = 0; kc < K; kc += 32) {
        bool more = (kc + 32) < K;
        if (more) {
            loadc(kc + 32, buf ^ 1);
            asm volatile("cp.async.wait_group 1;" ::: "memory");
        } else {
            asm volatile("cp.async.wait_group 0;" ::: "memory");
        }
        __syncthreads();
        const bf16* As0 = dsm + buf*BUFELEM;
        const bf16* As1 = As0 + ABUF;
        const bf16* Bs0 = As0 + 2*ABUF;
        const bf16* Bs1 = Bs0 + BBUF;
        #pragma unroll
        for (int ks = 0; ks < 32; ks += 16) {
            u32 ah[2][4], al[2][4], bh[4][2], bl[4][2];
            #pragma unroll
            for (int mt = 0; mt < 2; mt++) {
                int ar = (wm*32 + mt*16 + g)*AP + ks + qp*2;
                int ar8 = ar + 8*AP;
                ah[mt][0] = *(const u32*)&As0[ar];     ah[mt][1] = *(const u32*)&As0[ar8];
                ah[mt][2] = *(const u32*)&As0[ar + 8]; ah[mt][3] = *(const u32*)&As0[ar8 + 8];
                al[mt][0] = *(const u32*)&As1[ar];     al[mt][1] = *(const u32*)&As1[ar8];
                al[mt][2] = *(const u32*)&As1[ar + 8]; al[mt][3] = *(const u32*)&As1[ar8 + 8];
            }
            #pragma unroll
            for (int nt = 0; nt < 4; nt++) {
                int br = (wn*32 + nt*8 + g)*AP + ks + qp*2;
                bh[nt][0] = *(const u32*)&Bs0[br]; bh[nt][1] = *(const u32*)&Bs0[br + 8];
                bl[nt][0] = *(const u32*)&Bs1[br]; bl[nt][1] = *(const u32*)&Bs1[br + 8];
            }
            #pragma unroll
            for (int mt = 0; mt < 2; mt++)
                #pragma unroll
                for (int nt = 0; nt < 4; nt++) {
                    mma16816(acc[mt][nt], ah[mt], bh[nt]);
                    mma16816(acc[mt][nt], ah[mt], bl[nt]);
                    mma16816(acc[mt][nt], al[mt], bh[nt]);
                }
        }
        __syncthreads();
        buf ^= 1;
    }
    #pragma unroll
    for (int mt = 0; mt < 2; mt++) {
        int r0 = row0 + wm*32 + mt*16 + g;
        #pragma unroll
        for (int half = 0; half < 2; half++) {
            int r = r0 + half*8;
            if (r >= M) continue;
            #pragma unroll
            for (int nt = 0; nt < 4; nt++) {
                int cl = col0 + wn*32 + nt*8 + qp*2;
                float v0 = acc[mt][nt][half*2 + 0], v1 = acc[mt][nt][half*2 + 1];
                if (bias) { v0 += bias[cl]; v1 += bias[cl + 1]; }
                if (mode == 1) { v0 = fmaxf(v0, 0.f); v1 = fmaxf(v1, 0.f); }
                else if (mode == 2) {
                    v0 *= 0.9999950000374997f; if (v0 <= 0.f) v0 = expm1f(v0);
                    v1 *= 0.9999950000374997f; if (v1 <= 0.f) v1 = expm1f(v1);
                }
                size_t ci = (size_t)r*ldc + cl;
                if (C) *(float2*)&C[ci] = make_float2(v0, v1);
                if (Chi) {
                    bf16 h0 = __float2bfloat16(v0), h1 = __float2bfloat16(v1);
                    bf16 l0 = __float2bfloat16(v0 - __bfloat162float(h0));
                    bf16 l1 = __float2bfloat16(v1 - __bfloat162float(h1));
                    *(u32*)&Chi[ci] = (u32)__bfloat16_as_ushort(h0) |
                                      ((u32)__bfloat16_as_ushort(h1) << 16);
                    *(u32*)&Clo[ci] = (u32)__bfloat16_as_ushort(l0) |
                                      ((u32)__bfloat16_as_ushort(l1) << 16);
                }
            }
        }
    }
}

__global__ void __launch_bounds__(256) k_mgemm(
        const bf16* Ahi, const bf16* Alo, const bf16* Bhi, const bf16* Blo,
        float* C, bf16* Chi, bf16* Clo, const float* bias,
        int M, int N, int K, int mode) {
    mg_body(Ahi, Alo, Bhi, Blo, C, Chi, Clo, bias, M, N, K, mode, N);
}
__global__ void __launch_bounds__(256) k_mgemm_qkv(
        const bf16* Ahi, const bf16* Alo, const bf16* Bhi, const bf16* Blo,
        float* q, float* k, float* v, float* q2, float* k2, float* v2,
        int M, int N, int K) {
    int z = blockIdx.z;
    size_t bo = (size_t)z*262144;
    float* C = (z==0)?q:(z==1)?k:(z==2)?v:(z==3)?q2:(z==4)?k2:v2;
    mg_body(Ahi, Alo, Bhi + bo, Blo + bo, C, nullptr, nullptr, nullptr, M, N, K, 0, N);
}
__global__ void __launch_bounds__(256) k_mgemm_fc(
        const bf16* Ahi, const bf16* Alo, const bf16* Bhi, const bf16* Blo,
        const float* fcb, size_t lo_t, size_t lo_s,
        float* ft, float* fs, int M, int N, int K) {
    int z = blockIdx.z;
    size_t ao = (size_t)z*NROWS*512, bo = (size_t)z*262144;
    mg_body(Ahi + ao, Alo + ao, Bhi + bo, Blo + bo, z ? fs : ft, nullptr, nullptr,
            fcb + (z ? lo_s : lo_t), M, N, K, 0, N);
}
__global__ void __launch_bounds__(256) k_mgemm_sim(
        const bf16* Ahi, const bf16* Alo, int startRow, int n, size_t lvloff,
        float* simbuf) {
    int b = blockIdx.z;
    size_t ao = ((size_t)(b*LTOT + startRow))*512;
    float* C = simbuf + (size_t)b*SIMB + lvloff;
    mg_body(Ahi + ao, Alo + ao, Ahi + ao, Alo + ao, C, nullptr, nullptr, nullptr,
            n, n, 512, 0, n);
}
__global__ void __launch_bounds__(256) k_mgemm_att_s(
        const bf16* QH, const bf16* QL, const bf16* KH, const bf16* KL, float* S) {
    int bh = blockIdx.z;
    size_t qo = (size_t)bh*LPAD*64;
    mg_body(QH + qo, QL + qo, KH + qo, KL + qo,
            S + (size_t)bh*LTOT*LPAD, nullptr, nullptr, nullptr, LTOT, LPAD, 64, 0, LPAD);
}
__global__ void __launch_bounds__(256) k_mgemm_att_pv(
        const bf16* PH, const bf16* PL, const bf16* VTH, const bf16* VTL,
        bf16* Ohi, bf16* Olo) {
    int bh = blockIdx.z, b = bh >> 3, h = bh & 7;
    size_t po = (size_t)bh*LTOT*LPAD, vo = (size_t)bh*64*LPAD;
    size_t co = ((size_t)b*LTOT)*512 + h*64;
    mg_body(PH + po, PL + po, VTH + vo, VTL + vo,
            nullptr, Ohi + co, Olo + co, nullptr, LTOT, 64, LPAD, 0, 512);
}

// ---------------- attention operand conversion ----------------
__global__ void k_cvt_qk(const float* __restrict__ q2, const float* __restrict__ k2,
                         bf16* QH, bf16* QL, bf16* KH, bf16* KL) {
    long idx = (long)blockIdx.x*256 + threadIdx.x;
    if (idx >= (long)NBH*LPAD*64) return;
    int d = idx & 63;
    long r_ = idx >> 6;
    int r = (int)(r_ % LPAD);
    int bh = (int)(r_ / LPAD);
    int b = bh >> 3, h = bh & 7;
    float qv = 0.f, kv = 0.f;
    if (r < LTOT) {
        size_t off = ((size_t)(b*LTOT + r))*512 + h*64 + d;
        qv = q2[off]; kv = k2[off];
    }
    wr_hl(QH, QL, idx, qv);
    wr_hl(KH, KL, idx, kv);
}
__global__ void k_cvt_vt(const float* __restrict__ v2, bf16* VTH, bf16* VTL) {
    __shared__ float t[32][33];
    int bh = blockIdx.z, b = bh >> 3, h = bh & 7;
    int j0 = blockIdx.x*32, d0 = blockIdx.y*32;
    int tx = threadIdx.x, ty = threadIdx.y;
    #pragma unroll
    for (int i = 0; i < 4; i++) {
        int j = j0 + ty + i*8;
        t[ty + i*8][tx] = (j < LTOT)
            ? v2[((size_t)(b*LTOT + j))*512 + h*64 + d0 + tx] : 0.f;
    }
    __syncthreads();
    #pragma unroll
    for (int i = 0; i < 4; i++) {
        int d = d0 + ty + i*8, j = j0 + tx;
        wr_hl(VTH, VTL, ((size_t)bh*64 + d)*LPAD + j, t[tx][ty + i*8]);
    }
}

// ---------------- reductions ----------------
__device__ __forceinline__ float block_max256(float v) {
    __shared__ float red[8];
    int lane = threadIdx.x & 31, w = threadIdx.x >> 5;
    #pragma unroll
    for (int o = 16; o; o >>= 1) v = fmaxf(v, __shfl_xor_sync(0xffffffffu, v, o));
    if (lane == 0) red[w] = v;
    __syncthreads();
    if (w == 0) {
        float t = (lane < 8) ? red[lane] : -1e30f;
        #pragma unroll
        for (int o = 4; o; o >>= 1) t = fmaxf(t, __shfl_xor_sync(0xffffffffu, t, o));
        if (lane == 0) red[0] = t;
    }
    __syncthreads();
    float r = red[0];
    __syncthreads();
    return r;
}
__device__ __forceinline__ float block_sum256(float v) {
    __shared__ float red[8];
    int lane = threadIdx.x & 31, w = threadIdx.x >> 5;
    #pragma unroll
    for (int o = 16; o; o >>= 1) v += __shfl_xor_sync(0xffffffffu, v, o);
    if (lane == 0) red[w] = v;
    __syncthreads();
    if (w == 0) {
        float t = (lane < 8) ? red[lane] : 0.f;
        #pragma unroll
        for (int o = 4; o; o >>= 1) t += __shfl_xor_sync(0xffffffffu, t, o);
        if (lane == 0) red[0] = t;
    }
    __syncthreads();
    float r = red[0];
    __syncthreads();
    return r;
}

__global__ void __launch_bounds__(256) k_softmax_p(
        const float* __restrict__ S, const unsigned char* __restrict__ smask,
        bf16* __restrict__ PH, bf16* __restrict__ PL) {
    int row = blockIdx.x, bh = blockIdx.y, b = bh >> 3;
    int tid = threadIdx.x;
    __shared__ float buf[LTOT];
    const float* srow = S + ((size_t)bh*LTOT + row)*LPAD;
    const unsigned char* mrow = smask + ((size_t)b*LTOT + row)*LTOT;
    float mx = -1e30f;
    for (int j = tid; j < LTOT; j += 256) {
        float s = mrow[j] ? -1e30f : srow[j]*0.125f;
        buf[j] = s;
        mx = fmaxf(mx, s);
    }
    mx = block_max256(mx);
    float sum = 0.f;
    for (int j = tid; j < LTOT; j += 256) {
        float e = expf(buf[j] - mx);
        buf[j] = e; sum += e;
    }
    sum = block_sum256(sum);
    float inv = 1.f / sum;
    bf16* ph = PH + ((size_t)bh*LTOT + row)*LPAD;
    bf16* pl = PL + ((size_t)bh*LTOT + row)*LPAD;
    for (int j = tid; j < LPAD; j += 256) {
        float p = (j < LTOT) ? buf[j]*inv : 0.f;
        wr_hl(ph, pl, j, p);
    }
}

// ---------------- conv weight re-layout ----------------
__global__ void k_convw(const float* __restrict__ w, float* __restrict__ wm) {
    int idx = blockIdx.x*blockDim.x + threadIdx.x;
    if (idx >= 3*2048*512) return;
    int l  = idx / (2048*512);
    int r  = idx - l*2048*512;
    int kk = r >> 9, co = r & 511;
    int t  = kk >> 9, ci = kk & 511;
    wm[idx] = w[(((size_t)(l*512 + co))*512 + ci)*4 + t];
}

// ---------------- concat + LN(1e-5), emits hi/lo ----------------
__global__ void __launch_bounds__(256) k_concat_ln(
        const float* __restrict__ xe, const float* __restrict__ pyr,
        const float* __restrict__ g, const float* __restrict__ bt,
        float* __restrict__ out, bf16* ohi, bf16* olo) {
    int row = blockIdx.x;
    int b = row / LTOT, i = row % LTOT;
    const float* src = (i < 1024) ? xe + ((size_t)(b*1024 + i))*512
                                  : pyr + ((size_t)(b*336 + (i - 1024)))*512;
    int t = threadIdx.x;
    float v0 = src[t], v1 = src[t + 256];
    float mu = block_sum256(v0 + v1) * (1.f/512.f);
    float d0 = v0 - mu, d1 = v1 - mu;
    float var = block_sum256(d0*d0 + d1*d1) * (1.f/512.f);
    float rs = rsqrtf(var + 1e-5f);
    float r0 = d0*rs*g[t]       + bt[t];
    float r1 = d1*rs*g[t + 256] + bt[t + 256];
    size_t base = (size_t)row*512;
    out[base + t] = r0; out[base + t + 256] = r1;
    wr_hl(ohi, olo, base + t, r0);
    wr_hl(ohi, olo, base + t + 256, r1);
}

// ---------------- (a+res) -> LN, optional hi/lo ----------------
__global__ void __launch_bounds__(256) k_add_ln(
        const float* __restrict__ a, const float* __restrict__ res,
        const float* __restrict__ g, const float* __restrict__ bt,
        float* __restrict__ out, bf16* ohi, bf16* olo, float eps) {
    int row = blockIdx.x, t = threadIdx.x;
    const float* pa = a + (size_t)row*512;
    const float* pr = res + (size_t)row*512;
    float v0 = pa[t] + pr[t], v1 = pa[t + 256] + pr[t + 256];
    float mu = block_sum256(v0 + v1) * (1.f/512.f);
    float d0 = v0 - mu, d1 = v1 - mu;
    float var = block_sum256(d0*d0 + d1*d1) * (1.f/512.f);
    float rs = rsqrtf(var + eps);
    float r0 = d0*rs*g[t]       + bt[t];
    float r1 = d1*rs*g[t + 256] + bt[t + 256];
    size_t base = (size_t)row*512;
    out[base + t] = r0; out[base + t + 256] = r1;
    if (ohi) {
        wr_hl(ohi, olo, base + t, r0);
        wr_hl(ohi, olo, base + t + 256, r1);
    }
}

// ---------------- fused dual-LN + combine, emits hi/lo ----------------
__global__ void __launch_bounds__(256) k_lncomb(
        const float* __restrict__ fc, const float* __restrict__ fc2,
        float* __restrict__ x, bf16* xhi, bf16* xlo,
        const float* __restrict__ g, const float* __restrict__ bt,
        size_t lo_t, size_t lo_s) {
    int row = blockIdx.x, t = threadIdx.x;
    const float* pa = fc + (size_t)row*512;
    const float* pb = fc2 + (size_t)row*512;
    float* px = x + (size_t)row*512;
    float x0 = px[t], x1 = px[t + 256];
    float a0 = pa[t] + x0, a1 = pa[t + 256] + x1;
    float b0 = pb[t] + x0, b1 = pb[t + 256] + x1;
    float mu = block_sum256(a0 + a1) * (1.f/512.f);
    a0 -= mu; a1 -= mu;
    float var = block_sum256(a0*a0 + a1*a1) * (1.f/512.f);
    float rs = rsqrtf(var + 1e-6f);
    float t0 = a0*rs*g[lo_t + t]       + bt[lo_t + t];
    float t1 = a1*rs*g[lo_t + t + 256] + bt[lo_t + t + 256];
    mu = block_sum256(b0 + b1) * (1.f/512.f);
    b0 -= mu; b1 -= mu;
    var = block_sum256(b0*b0 + b1*b1) * (1.f/512.f);
    rs = rsqrtf(var + 1e-6f);
    float s0 = b0*rs*g[lo_s + t]       + bt[lo_s + t];
    float s1 = b1*rs*g[lo_s + t + 256] + bt[lo_s + t + 256];
    float r0 = (t0 + s0 + x0) * (1.f/3.f);
    float r1 = (t1 + s1 + x1) * (1.f/3.f);
    px[t] = r0; px[t + 256] = r1;
    size_t base = (size_t)row*512;
    wr_hl(xhi, xlo, base + t, r0);
    wr_hl(xhi, xlo, base + t + 256, r1);
}

// ---------------- row L2 normalize, emits hi/lo ----------------
__global__ void __launch_bounds__(256) k_rownorm(
        const float* __restrict__ x, float* __restrict__ xn,
        bf16* nhi, bf16* nlo) {
    int row = blockIdx.x, t = threadIdx.x;
    const float* p = x + (size_t)row*512;
    float v0 = p[t], v1 = p[t + 256];
    float ss = block_sum256(v0*v0 + v1*v1);
    float inv = 1.f / fmaxf(sqrtf(ss), 1e-8f);
    float r0 = v0*inv, r1 = v1*inv;
    size_t base = (size_t)row*512;
    xn[base + t] = r0; xn[base + t + 256] = r1;
    wr_hl(nhi, nlo, base + t, r0);
    wr_hl(nhi, nlo, base + t + 256, r1);
}

// ---------------- top-k select ----------------
__global__ void __launch_bounds__(256) k_topksel(
        const float* __restrict__ xn, const float* __restrict__ simbuf,
        unsigned char* __restrict__ smask) {
    int i = blockIdx.x, b = blockIdx.y, tid = threadIdx.x;
    const int starts[4] = {0,1024,1280,1344};
    const int sizes[4]  = {1024,256,64,16};
    int lev = (i<1024)?0:(i<1280)?1:(i<1344)?2:3;
    int st = starts[lev], n = sizes[lev];
    int kk = n < 32 ? n : 32;
    __shared__ float sims[1024];
    __shared__ float qrow[512];
    __shared__ float wv[8]; __shared__ int wi[8];
    unsigned char* mrow = smask + ((size_t)b*LTOT + i)*LTOT + st;
    for (int j = tid; j < n; j += 256) mrow[j] = 0;
    if (lev <= 1) {
        size_t lvloff = (lev == 0) ? 0 : 1048576;
        const float* srow = simbuf + (size_t)b*SIMB + lvloff + (size_t)(i - st)*n;
        for (int j = tid; j < n; j += 256) sims[j] = srow[j];
        __syncthreads();
    } else {
        const float* xb = xn + (size_t)b*LTOT*512;
        for (int d = tid; d < 512; d += 256) qrow[d] = xb[(size_t)i*512 + d];
        __syncthreads();
        int w = tid >> 5, lane = tid & 31;
        for (int j = w; j < n; j += 8) {
            const float* rj = xb + (size_t)(st + j)*512;
            float p = 0.f;
            #pragma unroll 4
            for (int d = lane; d < 512; d += 32) p += qrow[d]*rj[d];
            #pragma unroll
            for (int o = 16; o; o >>= 1) p += __shfl_xor_sync(0xffffffffu, p, o);
            if (lane == 0) sims[j] = p;
        }
        __syncthreads();
    }
    int w = tid >> 5, lane = tid & 31;
    for (int it = 0; it < kk; it++) {
        float bv = -3.f; int bi = n;
        for (int j = tid; j < n; j += 256) {
            float v = sims[j];
            if (v > bv) { bv = v; bi = j; }
        }
        #pragma unroll
        for (int o = 16; o; o >>= 1) {
            float ov = __shfl_xor_sync(0xffffffffu, bv, o);
            int   oi = __shfl_xor_sync(0xffffffffu, bi, o);
            if (ov > bv || (ov == bv && oi < bi)) { bv = ov; bi = oi; }
        }
        if (lane == 0) { wv[w] = bv; wi[w] = bi; }
        __syncthreads();
        if (tid == 0) {
            float fv = wv[0]; int fi = wi[0];
            #pragma unroll
            for (int z = 1; z < 8; z++)
                if (wv[z] > fv || (wv[z] == fv && wi[z] < fi)) { fv = wv[z]; fi = wi[z]; }
            mrow[fi] = 1;
            sims[fi] = -3.f;
        }
        __syncthreads();
    }
}

// ---------------- SPARSE temporal attention, emits hi/lo ----------------
__global__ void __launch_bounds__(256) k_tattn(
        const float* __restrict__ Q, const float* __restrict__ K,
        const float* __restrict__ V, bf16* __restrict__ Ohi, bf16* __restrict__ Olo) {
    int i = blockIdx.x, b = blockIdx.y;
    int h = threadIdx.x >> 5, lane = threadIdx.x & 31;
    const int starts[4] = {0,1024,1280,1344};
    const int sizes[4]  = {1024,256,64,16};
    int lev = (i<1024)?0:(i<1280)?1:(i<1344)?2:3;
    int st = starts[lev], n = sizes[lev];
    int nb[10]; int cnt = 0;
    int lo = (i-2 < st) ? st : i-2;
    int hi = (i+2 > st+n-1) ? st+n-1 : i+2;
    for (int j = lo; j <= hi; j++) nb[cnt++] = j;
    if (lev > 0) {
        int c0 = starts[lev-1] + (i - st)*4;
        nb[cnt++] = c0; nb[cnt++] = c0+1; nb[cnt++] = c0+2; nb[cnt++] = c0+3;
    }
    if (lev < 3) nb[cnt++] = starts[lev+1] + (i - st)/4;

    size_t rowb = (size_t)(b*LTOT);
    const float2 qv = *(const float2*)(Q + (rowb + i)*512 + h*64 + lane*2);
    float sc[10];
    #pragma unroll
    for (int t = 0; t < 10; t++) {
        if (t < cnt) {
            float2 kv = *(const float2*)(K + (rowb + nb[t])*512 + h*64 + lane*2);
            float p = qv.x*kv.x + qv.y*kv.y;
            #pragma unroll
            for (int o = 16; o; o >>= 1) p += __shfl_xor_sync(0xffffffffu, p, o);
            sc[t] = p * 0.125f;
        } else sc[t] = -1e30f;
    }
    float mx = -1e30f;
    #pragma unroll
    for (int t = 0; t < 10; t++) mx = fmaxf(mx, sc[t]);
    float ssum = 0.f;
    #pragma unroll
    for (int t = 0; t < 10; t++) {
        sc[t] = (t < cnt) ? expf(sc[t] - mx) : 0.f;
        ssum += sc[t];
    }
    float inv = 1.f / ssum;
    float ax = 0.f, ay = 0.f;
    #pragma unroll
    for (int t = 0; t < 10; t++) {
        if (t < cnt) {
            float2 vv = *(const float2*)(V + (rowb + nb[t])*512 + h*64 + lane*2);
            ax += sc[t]*vv.x; ay += sc[t]*vv.y;
        }
    }
    float vx = ax*inv, vy = ay*inv;
    size_t idx = (rowb + i)*512 + h*64 + lane*2;
    bf16 hx = __float2bfloat16(vx), hy = __float2bfloat16(vy);
    bf16 lx = __float2bfloat16(vx - __bfloat162float(hx));
    bf16 ly = __float2bfloat16(vy - __bfloat162float(hy));
    *(u32*)&Ohi[idx] = (u32)__bfloat16_as_ushort(hx) | ((u32)__bfloat16_as_ushort(hy) << 16);
    *(u32*)&Olo[idx] = (u32)__bfloat16_as_ushort(lx) | ((u32)__bfloat16_as_ushort(ly) << 16);
}

// ---------------- pyramid concat, emits hi/lo ----------------
__global__ void k_pyrcat(const float* __restrict__ c1, const float* __restrict__ c2,
                         const float* __restrict__ c3, bf16* hi, bf16* lo) {
    int idx = blockIdx.x*blockDim.x + threadIdx.x;
    if (idx >= BATCH*336*512) return;
    int d = idx & 511, r = idx >> 9;
    int b = r / 336, p = r % 336;
    float v;
    if (p < 256) v = c1[((size_t)(b*256 + p) << 9) | d];
    else if (p < 320) v = c2[((size_t)(b*64 + p - 256) << 9) | d];
    else v = c3[((size_t)(b*16 + p - 320) << 9) | d];
    wr_hl(hi, lo, idx, v);
}

// ---------------- orchestration ----------------
extern "C" void kernel_launch(void* const* d_in, const int* in_sizes, int n_in,
                              void* d_out, int out_size) {
    const float* x_enc  = (const float*)d_in[0];
    const float* down_W = (const float*)d_in[1];
    const float* down_b = (const float*)d_in[2];
    const float* conv_W = (const float*)d_in[3];
    const float* conv_b = (const float*)d_in[4];
    const float* up_W   = (const float*)d_in[5];
    const float* up_b   = (const float*)d_in[6];
    const float* bc_g   = (const float*)d_in[7];
    const float* bc_b   = (const float*)d_in[8];
    const float* Wq     = (const float*)d_in[9];
    const float* Wk     = (const float*)d_in[10];
    const float* Wv     = (const float*)d_in[11];
    const float* fcW    = (const float*)d_in[12];
    const float* fcb    = (const float*)d_in[13];
    const float* aln_g  = (const float*)d_in[14];
    const float* aln_b  = (const float*)d_in[15];
    const float* W1     = (const float*)d_in[16];
    const float* b1     = (const float*)d_in[17];
    const float* W2     = (const float*)d_in[18];
    const float* b2     = (const float*)d_in[19];
    const float* fln_g  = (const float*)d_in[20];
    const float* fln_b  = (const float*)d_in[21];
    float* out = (float*)d_out;

    float *c1,*c2,*c3,*pyr,*x,*q,*k,*v,*q2,*k2,*v2,*fc,*fc2,*xn,*wc,*sim,*S;
    bf16 *wHI,*wLO,*xhi,*xlo,*xnhi,*xnlo,*oohi,*oolo,*hhi,*hlo;
    bf16 *QH,*QL,*KH,*KL,*VTH,*VTL,*PH,*PL;
    unsigned char *smk;
    cudaGetSymbolAddress((void**)&c1,  g_c1);
    cudaGetSymbolAddress((void**)&c2,  g_c2);
    cudaGetSymbolAddress((void**)&c3,  g_c3);
    cudaGetSymbolAddress((void**)&pyr, g_pyr);
    cudaGetSymbolAddress((void**)&x,   g_x);
    cudaGetSymbolAddress((void**)&q,   g_q);
    cudaGetSymbolAddress((void**)&k,   g_k);
    cudaGetSymbolAddress((void**)&v,   g_v);
    cudaGetSymbolAddress((void**)&q2,  g_q2);
    cudaGetSymbolAddress((void**)&k2,  g_k2);
    cudaGetSymbolAddress((void**)&v2,  g_v2);
    cudaGetSymbolAddress((void**)&fc,  g_fc);
    cudaGetSymbolAddress((void**)&fc2, g_fc2);
    cudaGetSymbolAddress((void**)&xn,  g_xn);
    cudaGetSymbolAddress((void**)&wc,  g_wc);
    cudaGetSymbolAddress((void**)&sim, g_sim);
    cudaGetSymbolAddress((void**)&S,   g_S);
    cudaGetSymbolAddress((void**)&wHI, g_wHI);
    cudaGetSymbolAddress((void**)&wLO, g_wLO);
    cudaGetSymbolAddress((void**)&xhi, g_xhi);
    cudaGetSymbolAddress((void**)&xlo, g_xlo);
    cudaGetSymbolAddress((void**)&xnhi,g_xnhi);
    cudaGetSymbolAddress((void**)&xnlo,g_xnlo);
    cudaGetSymbolAddress((void**)&oohi,g_oohi);
    cudaGetSymbolAddress((void**)&oolo,g_oolo);
    cudaGetSymbolAddress((void**)&hhi, g_hhi);
    cudaGetSymbolAddress((void**)&hlo, g_hlo);
    cudaGetSymbolAddress((void**)&QH,  g_QH);
    cudaGetSymbolAddress((void**)&QL,  g_QL);
    cudaGetSymbolAddress((void**)&KH,  g_KH);
    cudaGetSymbolAddress((void**)&KL,  g_KL);
    cudaGetSymbolAddress((void**)&VTH, g_VTH);
    cudaGetSymbolAddress((void**)&VTL, g_VTL);
    cudaGetSymbolAddress((void**)&PH,  g_PH);
    cudaGetSymbolAddress((void**)&PL,  g_PL);
    cudaGetSymbolAddress((void**)&smk, g_sm);

    cudaFuncSetAttribute(k_mgemm,        cudaFuncAttributeMaxDynamicSharedMemorySize, DSMEM);
    cudaFuncSetAttribute(k_mgemm_qkv,    cudaFuncAttributeMaxDynamicSharedMemorySize, DSMEM);
    cudaFuncSetAttribute(k_mgemm_fc,     cudaFuncAttributeMaxDynamicSharedMemorySize, DSMEM);
    cudaFuncSetAttribute(k_mgemm_sim,    cudaFuncAttributeMaxDynamicSharedMemorySize, DSMEM);
    cudaFuncSetAttribute(k_mgemm_att_s,  cudaFuncAttributeMaxDynamicSharedMemorySize, DSMEM);
    cudaFuncSetAttribute(k_mgemm_att_pv, cudaFuncAttributeMaxDynamicSharedMemorySize, DSMEM);

    // ---- upfront weight conversions ----
    k_convw<<<(3*2048*512 + 255)/256, 256>>>(conv_W, wc);
    k_cvtB<<<dim3(16,16), dim3(32,8)>>>(down_W, wHI + WOFF_DOWN, wLO + WOFF_DOWN, 512, 512);
    k_cvtB<<<dim3(16,16), dim3(32,8)>>>(up_W,   wHI + WOFF_UP,   wLO + WOFF_UP,   512, 512);
    k_cvtB_multi<<<dim3(16,64,3), dim3(32,8)>>>(wc, wHI + WOFF_CONV, wLO + WOFF_CONV, 2048, 512);
    k_cvtW_qkv12<<<dim3(16,16,12), dim3(32,8)>>>(Wq, Wk, Wv, wHI + WOFF_QKV, wLO + WOFF_QKV);
    k_cvtB_multi<<<dim3(16,16,4), dim3(32,8)>>>(fcW, wHI + WOFF_FC,   wLO + WOFF_FC,   512, 512);
    k_cvtB_multi<<<dim3(16,16,2), dim3(32,8)>>>(W1,  wHI + WOFF_FFN1, wLO + WOFF_FFN1, 512, 512);
    k_cvtB_multi<<<dim3(16,16,2), dim3(32,8)>>>(W2,  wHI + WOFF_FFN2, wLO + WOFF_FFN2, 512, 512);
    k_cvtA<<<(BATCH*1024*512/4 + 255)/256, 256>>>(x_enc, xhi, xlo, BATCH*1024*512/4);

    // ---- bottleneck ----
    k_mgemm<<<dim3(8,32), 256, DSMEM>>>(xhi, xlo, wHI+WOFF_DOWN, wLO+WOFF_DOWN,
            nullptr, oohi, oolo, down_b, BATCH*1024, 512, 512, 0);
    k_mgemm<<<dim3(8,8), 256, DSMEM>>>(oohi, oolo, wHI+WOFF_CONV, wLO+WOFF_CONV,
            c1, xnhi, xnlo, conv_b, BATCH*256, 512, 2048, 2);
    k_mgemm<<<dim3(8,2), 256, DSMEM>>>(xnhi, xnlo, wHI+WOFF_CONV+1048576, wLO+WOFF_CONV+1048576,
            c2, hhi, hlo, conv_b + 512, BATCH*64, 512, 2048, 2);
    k_mgemm<<<dim3(8,1), 256, DSMEM>>>(hhi, hlo, wHI+WOFF_CONV+2097152, wLO+WOFF_CONV+2097152,
            c3, nullptr, nullptr, conv_b + 1024, BATCH*16, 512, 2048, 2);
    k_pyrcat<<<(BATCH*336*512 + 255)/256, 256>>>(c1, c2, c3, xhi, xlo);
    k_mgemm<<<dim3(8,(BATCH*336 + 127)/128), 256, DSMEM>>>(xhi, xlo, wHI+WOFF_UP, wLO+WOFF_UP,
            pyr, nullptr, nullptr, up_b, BATCH*336, 512, 512, 0);
    k_concat_ln<<<NROWS, 256>>>(x_enc, pyr, bc_g, bc_b, x, xhi, xlo);

    for (int l = 0; l < 2; l++) {
        size_t lo_t = ((size_t)l*2 + 0)*512, lo_s = ((size_t)l*2 + 1)*512;

        // semantic mask
        k_rownorm<<<NROWS, 256>>>(x, xn, xnhi, xnlo);
        k_mgemm_sim<<<dim3(16,8,BATCH), 256, DSMEM>>>(xnhi, xnlo, 0,    1024, 0,       sim);
        k_mgemm_sim<<<dim3(4,2,BATCH),  256, DSMEM>>>(xnhi, xnlo, 1024, 256,  1048576, sim);
        dim3 tg(LTOT, BATCH);
        k_topksel<<<tg, 256>>>(xn, sim, smk);

        // QKV x6 fused (weights pre-converted)
        dim3 qg(8, (NROWS + 127)/128, 6);
        k_mgemm_qkv<<<qg, 256, DSMEM>>>(xhi, xlo,
                wHI + WOFF_QKV + (size_t)l*6*262144, wLO + WOFF_QKV + (size_t)l*6*262144,
                q, k, v, q2, k2, v2, NROWS, 512, 512);

        // temporal branch -> hi/lo directly
        dim3 sg(LTOT, BATCH);
        k_tattn<<<sg, 256>>>(q, k, v, oohi, oolo);

        // semantic branch on tensor cores
        {
            long tot = (long)NBH*LPAD*64;
            k_cvt_qk<<<(unsigned)((tot + 255)/256), 256>>>(q2, k2, QH, QL, KH, KL);
            k_cvt_vt<<<dim3(LPAD/32, 2, NBH), dim3(32, 8)>>>(v2, VTH, VTL);
            dim3 gs(LPAD/64, (LTOT + 127)/128, NBH);
            k_mgemm_att_s<<<gs, 256, DSMEM>>>(QH, QL, KH, KL, S);
            dim3 gp(LTOT, NBH);
            k_softmax_p<<<gp, 256>>>(S, smk, PH, PL);
            dim3 gv(1, (LTOT + 127)/128, NBH);
            k_mgemm_att_pv<<<gv, 256, DSMEM>>>(PH, PL, VTH, VTL,
                    oohi + (size_t)NROWS*512, oolo + (size_t)NROWS*512);
        }

        // fc x2 fused (A operands already hi/lo)
        dim3 fg(8, (NROWS + 127)/128, 2);
        k_mgemm_fc<<<fg, 256, DSMEM>>>(oohi, oolo,
                wHI + WOFF_FC + (size_t)l*2*262144, wLO + WOFF_FC + (size_t)l*2*262144,
                fcb, lo_t, lo_s, fc, fc2, NROWS, 512, 512);

        k_lncomb<<<NROWS, 256>>>(fc, fc2, x, xhi, xlo, aln_g, aln_b, lo_t, lo_s);

        // FFN
        size_t fb = (size_t)l*512;
        dim3 ng(8, (NROWS + 127)/128);
        k_mgemm<<<ng, 256, DSMEM>>>(xhi, xlo,
                wHI + WOFF_FFN1 + (size_t)l*262144, wLO + WOFF_FFN1 + (size_t)l*262144,
                nullptr, hhi, hlo, b1 + fb, NROWS, 512, 512, 1);
        k_mgemm<<<ng, 256, DSMEM>>>(hhi, hlo,
                wHI + WOFF_FFN2 + (size_t)l*262144, wLO + WOFF_FFN2 + (size_t)l*262144,
                fc, nullptr, nullptr, b2 + fb, NROWS, 512, 512, 0);
        if (l == 0)
            k_add_ln<<<NROWS, 256>>>(fc, x, fln_g + fb, fln_b + fb, x, xhi, xlo, 1e-6f);
        else
            k_add_ln<<<NROWS, 256>>>(fc, x, fln_g + fb, fln_b + fb, out, nullptr, nullptr, 1e-6f);
    }
}

// round 12
// speedup vs baseline: 4.4538x; 1.1257x over previous
#include <cuda_runtime.h>
#include <cuda_bf16.h>
#include <math.h>
#include <stdint.h>

#define LTOT   1360
#define BATCH  4
#define NROWS  (BATCH*LTOT)          // 5440
#define L2SZ   ((size_t)LTOT*LTOT)
#define SIMB   (1048576 + 65536)
#define LPAD   1408
#define NBH    (BATCH*8)
#define NJT    22                    // LPAD/64 key tiles

// weight arena element offsets
#define WOFF_DOWN 0
#define WOFF_UP   262144
#define WOFF_CONV 524288
#define WOFF_QKV  3670016
#define WOFF_FC   6815744
#define WOFF_FFN1 7864320
#define WOFF_FFN2 8388608
#define WTOT      8912896

typedef __nv_bfloat16 bf16;
typedef unsigned int u32;

// ---------------- static device scratch ----------------
__device__ float g_c1[BATCH*256*512];
__device__ float g_c2[BATCH*64*512];
__device__ float g_c3[BATCH*16*512];
__device__ float g_pyr[BATCH*336*512];
__device__ float g_x[NROWS*512];
__device__ float g_q[NROWS*512];
__device__ float g_k[NROWS*512];
__device__ float g_v[NROWS*512];
__device__ float g_q2[NROWS*512];
__device__ float g_k2[NROWS*512];
__device__ float g_v2[NROWS*512];
__device__ float g_fc[NROWS*512];
__device__ float g_fc2[NROWS*512];
__device__ float g_xn[NROWS*512];
__device__ float g_wc[3*2048*512];
__device__ float g_sim[(size_t)BATCH*SIMB];
__device__ unsigned char g_sm[(size_t)BATCH*LTOT*LTOT];
// bf16 hi/lo operand buffers
__device__ bf16 g_wHI[WTOT];
__device__ bf16 g_wLO[WTOT];
__device__ bf16 g_xhi[NROWS*512];
__device__ bf16 g_xlo[NROWS*512];
__device__ bf16 g_xnhi[NROWS*512];
__device__ bf16 g_xnlo[NROWS*512];
__device__ bf16 g_oohi[2*NROWS*512];
__device__ bf16 g_oolo[2*NROWS*512];
__device__ bf16 g_hhi[NROWS*512];
__device__ bf16 g_hlo[NROWS*512];
// attention buffers
__device__ bf16 g_QH[(size_t)NBH*LPAD*64];
__device__ bf16 g_QL[(size_t)NBH*LPAD*64];
__device__ bf16 g_KH[(size_t)NBH*LPAD*64];
__device__ bf16 g_KL[(size_t)NBH*LPAD*64];
__device__ bf16 g_VTH[(size_t)NBH*64*LPAD];
__device__ bf16 g_VTL[(size_t)NBH*64*LPAD];
__device__ bf16 g_PH[(size_t)NBH*LTOT*LPAD];
__device__ bf16 g_PL[(size_t)NBH*LTOT*LPAD];
__device__ float g_psum[(size_t)NBH*LTOT*NJT];
__device__ float g_rsum[(size_t)NBH*LTOT];

__device__ __forceinline__ void wr_hl(bf16* hi, bf16* lo, size_t idx, float v) {
    bf16 h = __float2bfloat16(v);
    hi[idx] = h;
    lo[idx] = __float2bfloat16(v - __bfloat162float(h));
}

// ---------------- fp32 -> bf16 hi/lo (flat) ----------------
__global__ void k_cvtA(const float* __restrict__ s, bf16* __restrict__ hi,
                       bf16* __restrict__ lo, int n4) {
    int i = blockIdx.x*blockDim.x + threadIdx.x;
    if (i >= n4) return;
    float4 v = ((const float4*)s)[i];
    bf16 h0=__float2bfloat16(v.x), h1=__float2bfloat16(v.y),
         h2=__float2bfloat16(v.z), h3=__float2bfloat16(v.w);
    bf16 l0=__float2bfloat16(v.x-__bfloat162float(h0)),
         l1=__float2bfloat16(v.y-__bfloat162float(h1)),
         l2=__float2bfloat16(v.z-__bfloat162float(h2)),
         l3=__float2bfloat16(v.w-__bfloat162float(h3));
    uint2 hp = make_uint2((u32)__bfloat16_as_ushort(h0) | ((u32)__bfloat16_as_ushort(h1)<<16),
                          (u32)__bfloat16_as_ushort(h2) | ((u32)__bfloat16_as_ushort(h3)<<16));
    uint2 lp = make_uint2((u32)__bfloat16_as_ushort(l0) | ((u32)__bfloat16_as_ushort(l1)<<16),
                          (u32)__bfloat16_as_ushort(l2) | ((u32)__bfloat16_as_ushort(l3)<<16));
    ((uint2*)hi)[i] = hp;
    ((uint2*)lo)[i] = lp;
}

// ---------------- fp32 [K][N] -> bf16 hi/lo transposed [N][K] ----------------
__device__ __forceinline__ void cvtB_body(const float* __restrict__ src,
        bf16* __restrict__ hi, bf16* __restrict__ lo, int K, int N) {
    __shared__ float t[32][33];
    int tx = threadIdx.x, ty = threadIdx.y;
    int n0 = blockIdx.x*32, k0 = blockIdx.y*32;
    #pragma unroll
    for (int i = 0; i < 4; i++)
        t[ty + i*8][tx] = src[(size_t)(k0 + ty + i*8)*N + n0 + tx];
    __syncthreads();
    #pragma unroll
    for (int i = 0; i < 4; i++) {
        float v = t[tx][ty + i*8];
        int n = n0 + ty + i*8, kk = k0 + tx;
        wr_hl(hi, lo, (size_t)n*K + kk, v);
    }
}
__global__ void k_cvtB(const float* __restrict__ src, bf16* hi, bf16* lo, int K, int N) {
    cvtB_body(src, hi, lo, K, N);
}
__global__ void k_cvtB_multi(const float* __restrict__ src, bf16* hi, bf16* lo,
                             int K, int N) {
    size_t off = (size_t)blockIdx.z*K*N;
    cvtB_body(src + off, hi + off, lo + off, K, N);
}
__global__ void k_cvtW_qkv12(const float* __restrict__ Wq, const float* __restrict__ Wk,
                             const float* __restrict__ Wv, bf16* hi, bf16* lo) {
    int z = blockIdx.z;
    int l = z/6, rem = z%6, s = rem/3, c = rem%3;
    const float* base = ((c==0)?Wq:(c==1)?Wk:Wv) + ((size_t)(l*2+s))*262144;
    cvtB_body(base, hi + (size_t)z*262144, lo + (size_t)z*262144, 512, 512);
}

// ---------------- bf16x3 MMA GEMM with cp.async double-buffer ----------------
__device__ __forceinline__ void mma16816(float* d, const u32* a, const u32* b) {
    asm volatile(
        "mma.sync.aligned.m16n8k16.row.col.f32.bf16.bf16.f32 "
        "{%0,%1,%2,%3}, {%4,%5,%6,%7}, {%8,%9}, {%0,%1,%2,%3};"
        : "+f"(d[0]), "+f"(d[1]), "+f"(d[2]), "+f"(d[3])
        : "r"(a[0]), "r"(a[1]), "r"(a[2]), "r"(a[3]), "r"(b[0]), "r"(b[1]));
}
#define AP 40
#define ABUF (128*AP)
#define BBUF (64*AP)
#define BUFELEM (2*ABUF + 2*BBUF)
#define DSMEM (2*BUFELEM*2)

__device__ __forceinline__ u32 sm32(const void* p) {
    return (u32)__cvta_generic_to_shared(p);
}
__device__ __forceinline__ void cp16(u32 dst, const void* src, int bytes) {
    asm volatile("cp.async.ca.shared.global [%0], [%1], 16, %2;"
                 :: "r"(dst), "l"(src), "r"(bytes));
}

#define MG_LOADC(kc, bsel)                                                     \
    {                                                                          \
        bf16* base = dsm + (bsel)*BUFELEM;                                     \
        _Pragma("unroll")                                                      \
        for (int s = 0; s < 2; s++) {                                          \
            int slot = s*256 + tid;                                            \
            int r = slot >> 2, k16 = (slot & 3) << 3;                          \
            int gr = row0 + r;                                                 \
            int ok = (gr < M) ? 16 : 0;                                        \
            size_t go = (size_t)(gr < M ? gr : 0)*K + (kc) + k16;              \
            cp16(sm32(base + r*AP + k16), Ahi + go, ok);                       \
            cp16(sm32(base + ABUF + r*AP + k16), Alo + go, ok);                \
        }                                                                      \
        {                                                                      \
            int r = tid >> 2, k16 = (tid & 3) << 3;                            \
            size_t go = (size_t)(col0 + r)*K + (kc) + k16;                     \
            cp16(sm32(base + 2*ABUF + r*AP + k16), Bhi + go, 16);              \
            cp16(sm32(base + 2*ABUF + BBUF + r*AP + k16), Blo + go, 16);       \
        }                                                                      \
        asm volatile("cp.async.commit_group;" ::: "memory");                   \
    }

#define MG_MAINLOOP()                                                          \
    MG_LOADC(0, 0);                                                            \
    int buf = 0;                                                               \
    for (int kc = 0; kc < K; kc += 32) {                                       \
        bool more = (kc + 32) < K;                                             \
        if (more) {                                                            \
            MG_LOADC(kc + 32, buf ^ 1);                                        \
            asm volatile("cp.async.wait_group 1;" ::: "memory");               \
        } else {                                                               \
            asm volatile("cp.async.wait_group 0;" ::: "memory");               \
        }                                                                      \
        __syncthreads();                                                       \
        const bf16* As0 = dsm + buf*BUFELEM;                                   \
        const bf16* As1 = As0 + ABUF;                                          \
        const bf16* Bs0 = As0 + 2*ABUF;                                        \
        const bf16* Bs1 = Bs0 + BBUF;                                          \
        _Pragma("unroll")                                                      \
        for (int ks = 0; ks < 32; ks += 16) {                                  \
            u32 ah[2][4], al[2][4], bh[4][2], bl[4][2];                        \
            _Pragma("unroll")                                                  \
            for (int mt = 0; mt < 2; mt++) {                                   \
                int ar = (wm*32 + mt*16 + g)*AP + ks + qp*2;                   \
                int ar8 = ar + 8*AP;                                           \
                ah[mt][0] = *(const u32*)&As0[ar];                             \
                ah[mt][1] = *(const u32*)&As0[ar8];                            \
                ah[mt][2] = *(const u32*)&As0[ar + 8];                         \
                ah[mt][3] = *(const u32*)&As0[ar8 + 8];                        \
                al[mt][0] = *(const u32*)&As1[ar];                             \
                al[mt][1] = *(const u32*)&As1[ar8];                            \
                al[mt][2] = *(const u32*)&As1[ar + 8];                         \
                al[mt][3] = *(const u32*)&As1[ar8 + 8];                        \
            }                                                                  \
            _Pragma("unroll")                                                  \
            for (int nt = 0; nt < 4; nt++) {                                   \
                int br = (wn*32 + nt*8 + g)*AP + ks + qp*2;                    \
                bh[nt][0] = *(const u32*)&Bs0[br];                             \
                bh[nt][1] = *(const u32*)&Bs0[br + 8];                         \
                bl[nt][0] = *(const u32*)&Bs1[br];                             \
                bl[nt][1] = *(const u32*)&Bs1[br + 8];                         \
            }                                                                  \
            _Pragma("unroll")                                                  \
            for (int mt = 0; mt < 2; mt++)                                     \
                _Pragma("unroll")                                              \
                for (int nt = 0; nt < 4; nt++) {                               \
                    mma16816(acc[mt][nt], ah[mt], bh[nt]);                     \
                    mma16816(acc[mt][nt], ah[mt], bl[nt]);                     \
                    mma16816(acc[mt][nt], al[mt], bh[nt]);                     \
                }                                                              \
        }                                                                      \
        __syncthreads();                                                       \
        buf ^= 1;                                                              \
    }

// mode: 0 none, 1 relu, 2 scale+elu. C/Chi may be null; rmul scales rows.
__device__ void mg_body(const bf16* __restrict__ Ahi, const bf16* __restrict__ Alo,
                        const bf16* __restrict__ Bhi, const bf16* __restrict__ Blo,
                        float* __restrict__ C, bf16* __restrict__ Chi,
                        bf16* __restrict__ Clo, const float* __restrict__ bias,
                        const float* __restrict__ rmul,
                        int M, int N, int K, int mode, int ldc) {
    extern __shared__ bf16 dsm[];
    int tid = threadIdx.x, wid = tid >> 5, lane = tid & 31;
    int wm = wid >> 1, wn = wid & 1, g = lane >> 2, qp = lane & 3;
    int row0 = blockIdx.y << 7, col0 = blockIdx.x << 6;
    float acc[2][4][4] = {};
    MG_MAINLOOP();
    #pragma unroll
    for (int mt = 0; mt < 2; mt++) {
        #pragma unroll
        for (int half = 0; half < 2; half++) {
            int r = row0 + wm*32 + mt*16 + g + half*8;
            if (r >= M) continue;
            float rmv = rmul ? rmul[r] : 1.f;
            #pragma unroll
            for (int nt = 0; nt < 4; nt++) {
                int cl = col0 + wn*32 + nt*8 + qp*2;
                float v0 = acc[mt][nt][half*2 + 0], v1 = acc[mt][nt][half*2 + 1];
                if (rmul) { v0 *= rmv; v1 *= rmv; }
                if (bias) { v0 += bias[cl]; v1 += bias[cl + 1]; }
                if (mode == 1) { v0 = fmaxf(v0, 0.f); v1 = fmaxf(v1, 0.f); }
                else if (mode == 2) {
                    v0 *= 0.9999950000374997f; if (v0 <= 0.f) v0 = expm1f(v0);
                    v1 *= 0.9999950000374997f; if (v1 <= 0.f) v1 = expm1f(v1);
                }
                size_t ci = (size_t)r*ldc + cl;
                if (C) *(float2*)&C[ci] = make_float2(v0, v1);
                if (Chi) {
                    bf16 h0 = __float2bfloat16(v0), h1 = __float2bfloat16(v1);
                    bf16 l0 = __float2bfloat16(v0 - __bfloat162float(h0));
                    bf16 l1 = __float2bfloat16(v1 - __bfloat162float(h1));
                    *(u32*)&Chi[ci] = (u32)__bfloat16_as_ushort(h0) |
                                      ((u32)__bfloat16_as_ushort(h1) << 16);
                    *(u32*)&Clo[ci] = (u32)__bfloat16_as_ushort(l0) |
                                      ((u32)__bfloat16_as_ushort(l1) << 16);
                }
            }
        }
    }
}

__global__ void __launch_bounds__(256) k_mgemm(
        const bf16* Ahi, const bf16* Alo, const bf16* Bhi, const bf16* Blo,
        float* C, bf16* Chi, bf16* Clo, const float* bias,
        int M, int N, int K, int mode) {
    mg_body(Ahi, Alo, Bhi, Blo, C, Chi, Clo, bias, nullptr, M, N, K, mode, N);
}
__global__ void __launch_bounds__(256) k_mgemm_qkv(
        const bf16* Ahi, const bf16* Alo, const bf16* Bhi, const bf16* Blo,
        float* q, float* k, float* v, float* q2, float* k2, float* v2,
        int M, int N, int K) {
    int z = blockIdx.z;
    size_t bo = (size_t)z*262144;
    float* C = (z==0)?q:(z==1)?k:(z==2)?v:(z==3)?q2:(z==4)?k2:v2;
    mg_body(Ahi, Alo, Bhi + bo, Blo + bo, C, nullptr, nullptr, nullptr, nullptr,
            M, N, K, 0, N);
}
__global__ void __launch_bounds__(256) k_mgemm_fc(
        const bf16* Ahi, const bf16* Alo, const bf16* Bhi, const bf16* Blo,
        const float* fcb, size_t lo_t, size_t lo_s,
        float* ft, float* fs, int M, int N, int K) {
    int z = blockIdx.z;
    size_t ao = (size_t)z*NROWS*512, bo = (size_t)z*262144;
    mg_body(Ahi + ao, Alo + ao, Bhi + bo, Blo + bo, z ? fs : ft, nullptr, nullptr,
            fcb + (z ? lo_s : lo_t), nullptr, M, N, K, 0, N);
}
__global__ void __launch_bounds__(256) k_mgemm_sim(
        const bf16* Ahi, const bf16* Alo, int startRow, int n, size_t lvloff,
        float* simbuf) {
    int b = blockIdx.z;
    size_t ao = ((size_t)(b*LTOT + startRow))*512;
    float* C = simbuf + (size_t)b*SIMB + lvloff;
    mg_body(Ahi + ao, Alo + ao, Ahi + ao, Alo + ao, C, nullptr, nullptr, nullptr,
            nullptr, n, n, 512, 0, n);
}
__global__ void __launch_bounds__(256) k_mgemm_att_pv(
        const bf16* PH, const bf16* PL, const bf16* VTH, const bf16* VTL,
        const float* rsum, bf16* Ohi, bf16* Olo) {
    int bh = blockIdx.z, b = bh >> 3, h = bh & 7;
    size_t po = (size_t)bh*LTOT*LPAD, vo = (size_t)bh*64*LPAD;
    size_t co = ((size_t)b*LTOT)*512 + h*64;
    mg_body(PH + po, PL + po, VTH + vo, VTL + vo,
            nullptr, Ohi + co, Olo + co, nullptr, rsum + (size_t)bh*LTOT,
            LTOT, 64, LPAD, 0, 512);
}

// ---- fused S = QK^T with mask+exp epilogue + deterministic row partials ----
__global__ void __launch_bounds__(256) k_att_s(
        const bf16* __restrict__ QHg, const bf16* __restrict__ QLg,
        const bf16* __restrict__ KHg, const bf16* __restrict__ KLg,
        const unsigned char* __restrict__ smask,
        bf16* __restrict__ PH, bf16* __restrict__ PL,
        float* __restrict__ psum) {
    extern __shared__ bf16 dsm[];
    __shared__ float psm[128][2];
    int bh = blockIdx.z, b = bh >> 3;
    const bf16* Ahi = QHg + (size_t)bh*LPAD*64;
    const bf16* Alo = QLg + (size_t)bh*LPAD*64;
    const bf16* Bhi = KHg + (size_t)bh*LPAD*64;
    const bf16* Blo = KLg + (size_t)bh*LPAD*64;
    int tid = threadIdx.x, wid = tid >> 5, lane = tid & 31;
    int wm = wid >> 1, wn = wid & 1, g = lane >> 2, qp = lane & 3;
    int row0 = blockIdx.y << 7, col0 = blockIdx.x << 6;
    const int M = LTOT, K = 64;
    float acc[2][4][4] = {};
    MG_MAINLOOP();
    float rp[2][2];
    #pragma unroll
    for (int mt = 0; mt < 2; mt++) {
        #pragma unroll
        for (int half = 0; half < 2; half++) {
            int r = row0 + wm*32 + mt*16 + g + half*8;
            bool rok = (r < M);
            const unsigned char* mrow = smask + ((size_t)b*LTOT + (rok ? r : 0))*LTOT;
            float rs = 0.f;
            #pragma unroll
            for (int nt = 0; nt < 4; nt++) {
                int cl = col0 + wn*32 + nt*8 + qp*2;
                float e0 = 0.f, e1 = 0.f;
                if (rok) {
                    if (cl < LTOT && !mrow[cl])
                        e0 = expf(acc[mt][nt][half*2 + 0]*0.125f);
                    if (cl + 1 < LTOT && !mrow[cl + 1])
                        e1 = expf(acc[mt][nt][half*2 + 1]*0.125f);
                    size_t ci = ((size_t)bh*LTOT + r)*LPAD + cl;
                    bf16 h0 = __float2bfloat16(e0), h1 = __float2bfloat16(e1);
                    bf16 l0 = __float2bfloat16(e0 - __bfloat162float(h0));
                    bf16 l1 = __float2bfloat16(e1 - __bfloat162float(h1));
                    *(u32*)&PH[ci] = (u32)__bfloat16_as_ushort(h0) |
                                     ((u32)__bfloat16_as_ushort(h1) << 16);
                    *(u32*)&PL[ci] = (u32)__bfloat16_as_ushort(l0) |
                                     ((u32)__bfloat16_as_ushort(l1) << 16);
                }
                rs += e0 + e1;
            }
            rp[mt][half] = rs;
        }
    }
    // quad reduce (lanes qp 0..3 share a row), then cross-warp (wn) via smem
    #pragma unroll
    for (int mt = 0; mt < 2; mt++)
        #pragma unroll
        for (int half = 0; half < 2; half++) {
            float v = rp[mt][half];
            v += __shfl_xor_sync(0xffffffffu, v, 1);
            v += __shfl_xor_sync(0xffffffffu, v, 2);
            if (qp == 0) psm[wm*32 + mt*16 + half*8 + g][wn] = v;
        }
    __syncthreads();
    if (tid < 128) {
        int r = row0 + tid;
        if (r < M)
            psum[((size_t)bh*LTOT + r)*NJT + blockIdx.x] = psm[tid][0] + psm[tid][1];
    }
}

__global__ void k_rsumfin(const float* __restrict__ psum, float* __restrict__ rsum) {
    int i = blockIdx.x*256 + threadIdx.x;
    if (i >= NBH*LTOT) return;
    const float* p = psum + (size_t)i*NJT;
    float s = 0.f;
    #pragma unroll
    for (int j = 0; j < NJT; j++) s += p[j];
    rsum[i] = 1.f / s;
}

// ---------------- attention operand conversion ----------------
__global__ void k_cvt_qk(const float* __restrict__ q2, const float* __restrict__ k2,
                         bf16* QH, bf16* QL, bf16* KH, bf16* KL) {
    long idx = (long)blockIdx.x*256 + threadIdx.x;
    if (idx >= (long)NBH*LPAD*64) return;
    int d = idx & 63;
    long r_ = idx >> 6;
    int r = (int)(r_ % LPAD);
    int bh = (int)(r_ / LPAD);
    int b = bh >> 3, h = bh & 7;
    float qv = 0.f, kv = 0.f;
    if (r < LTOT) {
        size_t off = ((size_t)(b*LTOT + r))*512 + h*64 + d;
        qv = q2[off]; kv = k2[off];
    }
    wr_hl(QH, QL, idx, qv);
    wr_hl(KH, KL, idx, kv);
}
__global__ void k_cvt_vt(const float* __restrict__ v2, bf16* VTH, bf16* VTL) {
    __shared__ float t[32][33];
    int bh = blockIdx.z, b = bh >> 3, h = bh & 7;
    int j0 = blockIdx.x*32, d0 = blockIdx.y*32;
    int tx = threadIdx.x, ty = threadIdx.y;
    #pragma unroll
    for (int i = 0; i < 4; i++) {
        int j = j0 + ty + i*8;
        t[ty + i*8][tx] = (j < LTOT)
            ? v2[((size_t)(b*LTOT + j))*512 + h*64 + d0 + tx] : 0.f;
    }
    __syncthreads();
    #pragma unroll
    for (int i = 0; i < 4; i++) {
        int d = d0 + ty + i*8, j = j0 + tx;
        wr_hl(VTH, VTL, ((size_t)bh*64 + d)*LPAD + j, t[tx][ty + i*8]);
    }
}

// ---------------- reductions ----------------
__device__ __forceinline__ float block_sum256(float v) {
    __shared__ float red[8];
    int lane = threadIdx.x & 31, w = threadIdx.x >> 5;
    #pragma unroll
    for (int o = 16; o; o >>= 1) v += __shfl_xor_sync(0xffffffffu, v, o);
    if (lane == 0) red[w] = v;
    __syncthreads();
    if (w == 0) {
        float t = (lane < 8) ? red[lane] : 0.f;
        #pragma unroll
        for (int o = 4; o; o >>= 1) t += __shfl_xor_sync(0xffffffffu, t, o);
        if (lane == 0) red[0] = t;
    }
    __syncthreads();
    float r = red[0];
    __syncthreads();
    return r;
}

// ---------------- conv weight re-layout ----------------
__global__ void k_convw(const float* __restrict__ w, float* __restrict__ wm) {
    int idx = blockIdx.x*blockDim.x + threadIdx.x;
    if (idx >= 3*2048*512) return;
    int l  = idx / (2048*512);
    int r  = idx - l*2048*512;
    int kk = r >> 9, co = r & 511;
    int t  = kk >> 9, ci = kk & 511;
    wm[idx] = w[(((size_t)(l*512 + co))*512 + ci)*4 + t];
}

// ---------------- concat + LN(1e-5), emits hi/lo ----------------
__global__ void __launch_bounds__(256) k_concat_ln(
        const float* __restrict__ xe, const float* __restrict__ pyr,
        const float* __restrict__ g, const float* __restrict__ bt,
        float* __restrict__ out, bf16* ohi, bf16* olo) {
    int row = blockIdx.x;
    int b = row / LTOT, i = row % LTOT;
    const float* src = (i < 1024) ? xe + ((size_t)(b*1024 + i))*512
                                  : pyr + ((size_t)(b*336 + (i - 1024)))*512;
    int t = threadIdx.x;
    float v0 = src[t], v1 = src[t + 256];
    float mu = block_sum256(v0 + v1) * (1.f/512.f);
    float d0 = v0 - mu, d1 = v1 - mu;
    float var = block_sum256(d0*d0 + d1*d1) * (1.f/512.f);
    float rs = rsqrtf(var + 1e-5f);
    float r0 = d0*rs*g[t]       + bt[t];
    float r1 = d1*rs*g[t + 256] + bt[t + 256];
    size_t base = (size_t)row*512;
    out[base + t] = r0; out[base + t + 256] = r1;
    wr_hl(ohi, olo, base + t, r0);
    wr_hl(ohi, olo, base + t + 256, r1);
}

// ---------------- (a+res) -> LN, optional hi/lo ----------------
__global__ void __launch_bounds__(256) k_add_ln(
        const float* __restrict__ a, const float* __restrict__ res,
        const float* __restrict__ g, const float* __restrict__ bt,
        float* __restrict__ out, bf16* ohi, bf16* olo, float eps) {
    int row = blockIdx.x, t = threadIdx.x;
    const float* pa = a + (size_t)row*512;
    const float* pr = res + (size_t)row*512;
    float v0 = pa[t] + pr[t], v1 = pa[t + 256] + pr[t + 256];
    float mu = block_sum256(v0 + v1) * (1.f/512.f);
    float d0 = v0 - mu, d1 = v1 - mu;
    float var = block_sum256(d0*d0 + d1*d1) * (1.f/512.f);
    float rs = rsqrtf(var + eps);
    float r0 = d0*rs*g[t]       + bt[t];
    float r1 = d1*rs*g[t + 256] + bt[t + 256];
    size_t base = (size_t)row*512;
    out[base + t] = r0; out[base + t + 256] = r1;
    if (ohi) {
        wr_hl(ohi, olo, base + t, r0);
        wr_hl(ohi, olo, base + t + 256, r1);
    }
}

// ---------------- fused dual-LN + combine, emits hi/lo ----------------
__global__ void __launch_bounds__(256) k_lncomb(
        const float* __restrict__ fc, const float* __restrict__ fc2,
        float* __restrict__ x, bf16* xhi, bf16* xlo,
        const float* __restrict__ g, const float* __restrict__ bt,
        size_t lo_t, size_t lo_s) {
    int row = blockIdx.x, t = threadIdx.x;
    const float* pa = fc + (size_t)row*512;
    const float* pb = fc2 + (size_t)row*512;
    float* px = x + (size_t)row*512;
    float x0 = px[t], x1 = px[t + 256];
    float a0 = pa[t] + x0, a1 = pa[t + 256] + x1;
    float b0 = pb[t] + x0, b1 = pb[t + 256] + x1;
    float mu = block_sum256(a0 + a1) * (1.f/512.f);
    a0 -= mu; a1 -= mu;
    float var = block_sum256(a0*a0 + a1*a1) * (1.f/512.f);
    float rs = rsqrtf(var + 1e-6f);
    float t0 = a0*rs*g[lo_t + t]       + bt[lo_t + t];
    float t1 = a1*rs*g[lo_t + t + 256] + bt[lo_t + t + 256];
    mu = block_sum256(b0 + b1) * (1.f/512.f);
    b0 -= mu; b1 -= mu;
    var = block_sum256(b0*b0 + b1*b1) * (1.f/512.f);
    rs = rsqrtf(var + 1e-6f);
    float s0 = b0*rs*g[lo_s + t]       + bt[lo_s + t];
    float s1 = b1*rs*g[lo_s + t + 256] + bt[lo_s + t + 256];
    float r0 = (t0 + s0 + x0) * (1.f/3.f);
    float r1 = (t1 + s1 + x1) * (1.f/3.f);
    px[t] = r0; px[t + 256] = r1;
    size_t base = (size_t)row*512;
    wr_hl(xhi, xlo, base + t, r0);
    wr_hl(xhi, xlo, base + t + 256, r1);
}

// ---------------- row L2 normalize, emits hi/lo ----------------
__global__ void __launch_bounds__(256) k_rownorm(
        const float* __restrict__ x, float* __restrict__ xn,
        bf16* nhi, bf16* nlo) {
    int row = blockIdx.x, t = threadIdx.x;
    const float* p = x + (size_t)row*512;
    float v0 = p[t], v1 = p[t + 256];
    float ss = block_sum256(v0*v0 + v1*v1);
    float inv = 1.f / fmaxf(sqrtf(ss), 1e-8f);
    float r0 = v0*inv, r1 = v1*inv;
    size_t base = (size_t)row*512;
    xn[base + t] = r0; xn[base + t + 256] = r1;
    wr_hl(nhi, nlo, base + t, r0);
    wr_hl(nhi, nlo, base + t + 256, r1);
}

// ---------------- top-k select ----------------
__global__ void __launch_bounds__(256) k_topksel(
        const float* __restrict__ xn, const float* __restrict__ simbuf,
        unsigned char* __restrict__ smask) {
    int i = blockIdx.x, b = blockIdx.y, tid = threadIdx.x;
    const int starts[4] = {0,1024,1280,1344};
    const int sizes[4]  = {1024,256,64,16};
    int lev = (i<1024)?0:(i<1280)?1:(i<1344)?2:3;
    int st = starts[lev], n = sizes[lev];
    int kk = n < 32 ? n : 32;
    __shared__ float sims[1024];
    __shared__ float qrow[512];
    __shared__ float wv[8]; __shared__ int wi[8];
    unsigned char* mrow = smask + ((size_t)b*LTOT + i)*LTOT + st;
    for (int j = tid; j < n; j += 256) mrow[j] = 0;
    if (lev <= 1) {
        size_t lvloff = (lev == 0) ? 0 : 1048576;
        const float* srow = simbuf + (size_t)b*SIMB + lvloff + (size_t)(i - st)*n;
        for (int j = tid; j < n; j += 256) sims[j] = srow[j];
        __syncthreads();
    } else {
        const float* xb = xn + (size_t)b*LTOT*512;
        for (int d = tid; d < 512; d += 256) qrow[d] = xb[(size_t)i*512 + d];
        __syncthreads();
        int w = tid >> 5, lane = tid & 31;
        for (int j = w; j < n; j += 8) {
            const float* rj = xb + (size_t)(st + j)*512;
            float p = 0.f;
            #pragma unroll 4
            for (int d = lane; d < 512; d += 32) p += qrow[d]*rj[d];
            #pragma unroll
            for (int o = 16; o; o >>= 1) p += __shfl_xor_sync(0xffffffffu, p, o);
            if (lane == 0) sims[j] = p;
        }
        __syncthreads();
    }
    int w = tid >> 5, lane = tid & 31;
    for (int it = 0; it < kk; it++) {
        float bv = -3.f; int bi = n;
        for (int j = tid; j < n; j += 256) {
            float v = sims[j];
            if (v > bv) { bv = v; bi = j; }
        }
        #pragma unroll
        for (int o = 16; o; o >>= 1) {
            float ov = __shfl_xor_sync(0xffffffffu, bv, o);
            int   oi = __shfl_xor_sync(0xffffffffu, bi, o);
            if (ov > bv || (ov == bv && oi < bi)) { bv = ov; bi = oi; }
        }
        if (lane == 0) { wv[w] = bv; wi[w] = bi; }
        __syncthreads();
        if (tid == 0) {
            float fv = wv[0]; int fi = wi[0];
            #pragma unroll
            for (int z = 1; z < 8; z++)
                if (wv[z] > fv || (wv[z] == fv && wi[z] < fi)) { fv = wv[z]; fi = wi[z]; }
            mrow[fi] = 1;
            sims[fi] = -3.f;
        }
        __syncthreads();
    }
}

// ---------------- SPARSE temporal attention, emits hi/lo ----------------
__global__ void __launch_bounds__(256) k_tattn(
        const float* __restrict__ Q, const float* __restrict__ K,
        const float* __restrict__ V, bf16* __restrict__ Ohi, bf16* __restrict__ Olo) {
    int i = blockIdx.x, b = blockIdx.y;
    int h = threadIdx.x >> 5, lane = threadIdx.x & 31;
    const int starts[4] = {0,1024,1280,1344};
    const int sizes[4]  = {1024,256,64,16};
    int lev = (i<1024)?0:(i<1280)?1:(i<1344)?2:3;
    int st = starts[lev], n = sizes[lev];
    int nb[10]; int cnt = 0;
    int lo = (i-2 < st) ? st : i-2;
    int hi = (i+2 > st+n-1) ? st+n-1 : i+2;
    for (int j = lo; j <= hi; j++) nb[cnt++] = j;
    if (lev > 0) {
        int c0 = starts[lev-1] + (i - st)*4;
        nb[cnt++] = c0; nb[cnt++] = c0+1; nb[cnt++] = c0+2; nb[cnt++] = c0+3;
    }
    if (lev < 3) nb[cnt++] = starts[lev+1] + (i - st)/4;

    size_t rowb = (size_t)(b*LTOT);
    const float2 qv = *(const float2*)(Q + (rowb + i)*512 + h*64 + lane*2);
    float sc[10];
    #pragma unroll
    for (int t = 0; t < 10; t++) {
        if (t < cnt) {
            float2 kv = *(const float2*)(K + (rowb + nb[t])*512 + h*64 + lane*2);
            float p = qv.x*kv.x + qv.y*kv.y;
            #pragma unroll
            for (int o = 16; o; o >>= 1) p += __shfl_xor_sync(0xffffffffu, p, o);
            sc[t] = p * 0.125f;
        } else sc[t] = -1e30f;
    }
    float mx = -1e30f;
    #pragma unroll
    for (int t = 0; t < 10; t++) mx = fmaxf(mx, sc[t]);
    float ssum = 0.f;
    #pragma unroll
    for (int t = 0; t < 10; t++) {
        sc[t] = (t < cnt) ? expf(sc[t] - mx) : 0.f;
        ssum += sc[t];
    }
    float inv = 1.f / ssum;
    float ax = 0.f, ay = 0.f;
    #pragma unroll
    for (int t = 0; t < 10; t++) {
        if (t < cnt) {
            float2 vv = *(const float2*)(V + (rowb + nb[t])*512 + h*64 + lane*2);
            ax += sc[t]*vv.x; ay += sc[t]*vv.y;
        }
    }
    float vx = ax*inv, vy = ay*inv;
    size_t idx = (rowb + i)*512 + h*64 + lane*2;
    bf16 hx = __float2bfloat16(vx), hy = __float2bfloat16(vy);
    bf16 lx = __float2bfloat16(vx - __bfloat162float(hx));
    bf16 ly = __float2bfloat16(vy - __bfloat162float(hy));
    *(u32*)&Ohi[idx] = (u32)__bfloat16_as_ushort(hx) | ((u32)__bfloat16_as_ushort(hy) << 16);
    *(u32*)&Olo[idx] = (u32)__bfloat16_as_ushort(lx) | ((u32)__bfloat16_as_ushort(ly) << 16);
}

// ---------------- pyramid concat, emits hi/lo ----------------
__global__ void k_pyrcat(const float* __restrict__ c1, const float* __restrict__ c2,
                         const float* __restrict__ c3, bf16* hi, bf16* lo) {
    int idx = blockIdx.x*blockDim.x + threadIdx.x;
    if (idx >= BATCH*336*512) return;
    int d = idx & 511, r = idx >> 9;
    int b = r / 336, p = r % 336;
    float v;
    if (p < 256) v = c1[((size_t)(b*256 + p) << 9) | d];
    else if (p < 320) v = c2[((size_t)(b*64 + p - 256) << 9) | d];
    else v = c3[((size_t)(b*16 + p - 320) << 9) | d];
    wr_hl(hi, lo, idx, v);
}

// ---------------- orchestration ----------------
extern "C" void kernel_launch(void* const* d_in, const int* in_sizes, int n_in,
                              void* d_out, int out_size) {
    const float* x_enc  = (const float*)d_in[0];
    const float* down_W = (const float*)d_in[1];
    const float* down_b = (const float*)d_in[2];
    const float* conv_W = (const float*)d_in[3];
    const float* conv_b = (const float*)d_in[4];
    const float* up_W   = (const float*)d_in[5];
    const float* up_b   = (const float*)d_in[6];
    const float* bc_g   = (const float*)d_in[7];
    const float* bc_b   = (const float*)d_in[8];
    const float* Wq     = (const float*)d_in[9];
    const float* Wk     = (const float*)d_in[10];
    const float* Wv     = (const float*)d_in[11];
    const float* fcW    = (const float*)d_in[12];
    const float* fcb    = (const float*)d_in[13];
    const float* aln_g  = (const float*)d_in[14];
    const float* aln_b  = (const float*)d_in[15];
    const float* W1     = (const float*)d_in[16];
    const float* b1     = (const float*)d_in[17];
    const float* W2     = (const float*)d_in[18];
    const float* b2     = (const float*)d_in[19];
    const float* fln_g  = (const float*)d_in[20];
    const float* fln_b  = (const float*)d_in[21];
    float* out = (float*)d_out;

    float *c1,*c2,*c3,*pyr,*x,*q,*k,*v,*q2,*k2,*v2,*fc,*fc2,*xn,*wc,*sim,*psum,*rsum;
    bf16 *wHI,*wLO,*xhi,*xlo,*xnhi,*xnlo,*oohi,*oolo,*hhi,*hlo;
    bf16 *QH,*QL,*KH,*KL,*VTH,*VTL,*PH,*PL;
    unsigned char *smk;
    cudaGetSymbolAddress((void**)&c1,  g_c1);
    cudaGetSymbolAddress((void**)&c2,  g_c2);
    cudaGetSymbolAddress((void**)&c3,  g_c3);
    cudaGetSymbolAddress((void**)&pyr, g_pyr);
    cudaGetSymbolAddress((void**)&x,   g_x);
    cudaGetSymbolAddress((void**)&q,   g_q);
    cudaGetSymbolAddress((void**)&k,   g_k);
    cudaGetSymbolAddress((void**)&v,   g_v);
    cudaGetSymbolAddress((void**)&q2,  g_q2);
    cudaGetSymbolAddress((void**)&k2,  g_k2);
    cudaGetSymbolAddress((void**)&v2,  g_v2);
    cudaGetSymbolAddress((void**)&fc,  g_fc);
    cudaGetSymbolAddress((void**)&fc2, g_fc2);
    cudaGetSymbolAddress((void**)&xn,  g_xn);
    cudaGetSymbolAddress((void**)&wc,  g_wc);
    cudaGetSymbolAddress((void**)&sim, g_sim);
    cudaGetSymbolAddress((void**)&psum,g_psum);
    cudaGetSymbolAddress((void**)&rsum,g_rsum);
    cudaGetSymbolAddress((void**)&wHI, g_wHI);
    cudaGetSymbolAddress((void**)&wLO, g_wLO);
    cudaGetSymbolAddress((void**)&xhi, g_xhi);
    cudaGetSymbolAddress((void**)&xlo, g_xlo);
    cudaGetSymbolAddress((void**)&xnhi,g_xnhi);
    cudaGetSymbolAddress((void**)&xnlo,g_xnlo);
    cudaGetSymbolAddress((void**)&oohi,g_oohi);
    cudaGetSymbolAddress((void**)&oolo,g_oolo);
    cudaGetSymbolAddress((void**)&hhi, g_hhi);
    cudaGetSymbolAddress((void**)&hlo, g_hlo);
    cudaGetSymbolAddress((void**)&QH,  g_QH);
    cudaGetSymbolAddress((void**)&QL,  g_QL);
    cudaGetSymbolAddress((void**)&KH,  g_KH);
    cudaGetSymbolAddress((void**)&KL,  g_KL);
    cudaGetSymbolAddress((void**)&VTH, g_VTH);
    cudaGetSymbolAddress((void**)&VTL, g_VTL);
    cudaGetSymbolAddress((void**)&PH,  g_PH);
    cudaGetSymbolAddress((void**)&PL,  g_PL);
    cudaGetSymbolAddress((void**)&smk, g_sm);

    cudaFuncSetAttribute(k_mgemm,        cudaFuncAttributeMaxDynamicSharedMemorySize, DSMEM);
    cudaFuncSetAttribute(k_mgemm_qkv,    cudaFuncAttributeMaxDynamicSharedMemorySize, DSMEM);
    cudaFuncSetAttribute(k_mgemm_fc,     cudaFuncAttributeMaxDynamicSharedMemorySize, DSMEM);
    cudaFuncSetAttribute(k_mgemm_sim,    cudaFuncAttributeMaxDynamicSharedMemorySize, DSMEM);
    cudaFuncSetAttribute(k_att_s,        cudaFuncAttributeMaxDynamicSharedMemorySize, DSMEM);
    cudaFuncSetAttribute(k_mgemm_att_pv, cudaFuncAttributeMaxDynamicSharedMemorySize, DSMEM);

    // ---- upfront weight conversions ----
    k_convw<<<(3*2048*512 + 255)/256, 256>>>(conv_W, wc);
    k_cvtB<<<dim3(16,16), dim3(32,8)>>>(down_W, wHI + WOFF_DOWN, wLO + WOFF_DOWN, 512, 512);
    k_cvtB<<<dim3(16,16), dim3(32,8)>>>(up_W,   wHI + WOFF_UP,   wLO + WOFF_UP,   512, 512);
    k_cvtB_multi<<<dim3(16,64,3), dim3(32,8)>>>(wc, wHI + WOFF_CONV, wLO + WOFF_CONV, 2048, 512);
    k_cvtW_qkv12<<<dim3(16,16,12), dim3(32,8)>>>(Wq, Wk, Wv, wHI + WOFF_QKV, wLO + WOFF_QKV);
    k_cvtB_multi<<<dim3(16,16,4), dim3(32,8)>>>(fcW, wHI + WOFF_FC,   wLO + WOFF_FC,   512, 512);
    k_cvtB_multi<<<dim3(16,16,2), dim3(32,8)>>>(W1,  wHI + WOFF_FFN1, wLO + WOFF_FFN1, 512, 512);
    k_cvtB_multi<<<dim3(16,16,2), dim3(32,8)>>>(W2,  wHI + WOFF_FFN2, wLO + WOFF_FFN2, 512, 512);
    k_cvtA<<<(BATCH*1024*512/4 + 255)/256, 256>>>(x_enc, xhi, xlo, BATCH*1024*512/4);

    // ---- bottleneck ----
    k_mgemm<<<dim3(8,32), 256, DSMEM>>>(xhi, xlo, wHI+WOFF_DOWN, wLO+WOFF_DOWN,
            nullptr, oohi, oolo, down_b, BATCH*1024, 512, 512, 0);
    k_mgemm<<<dim3(8,8), 256, DSMEM>>>(oohi, oolo, wHI+WOFF_CONV, wLO+WOFF_CONV,
            c1, xnhi, xnlo, conv_b, BATCH*256, 512, 2048, 2);
    k_mgemm<<<dim3(8,2), 256, DSMEM>>>(xnhi, xnlo, wHI+WOFF_CONV+1048576, wLO+WOFF_CONV+1048576,
            c2, hhi, hlo, conv_b + 512, BATCH*64, 512, 2048, 2);
    k_mgemm<<<dim3(8,1), 256, DSMEM>>>(hhi, hlo, wHI+WOFF_CONV+2097152, wLO+WOFF_CONV+2097152,
            c3, nullptr, nullptr, conv_b + 1024, BATCH*16, 512, 2048, 2);
    k_pyrcat<<<(BATCH*336*512 + 255)/256, 256>>>(c1, c2, c3, xhi, xlo);
    k_mgemm<<<dim3(8,(BATCH*336 + 127)/128), 256, DSMEM>>>(xhi, xlo, wHI+WOFF_UP, wLO+WOFF_UP,
            pyr, nullptr, nullptr, up_b, BATCH*336, 512, 512, 0);
    k_concat_ln<<<NROWS, 256>>>(x_enc, pyr, bc_g, bc_b, x, xhi, xlo);

    for (int l = 0; l < 2; l++) {
        size_t lo_t = ((size_t)l*2 + 0)*512, lo_s = ((size_t)l*2 + 1)*512;

        // semantic mask
        k_rownorm<<<NROWS, 256>>>(x, xn, xnhi, xnlo);
        k_mgemm_sim<<<dim3(16,8,BATCH), 256, DSMEM>>>(xnhi, xnlo, 0,    1024, 0,       sim);
        k_mgemm_sim<<<dim3(4,2,BATCH),  256, DSMEM>>>(xnhi, xnlo, 1024, 256,  1048576, sim);
        dim3 tg(LTOT, BATCH);
        k_topksel<<<tg, 256>>>(xn, sim, smk);

        // QKV x6 fused
        dim3 qg(8, (NROWS + 127)/128, 6);
        k_mgemm_qkv<<<qg, 256, DSMEM>>>(xhi, xlo,
                wHI + WOFF_QKV + (size_t)l*6*262144, wLO + WOFF_QKV + (size_t)l*6*262144,
                q, k, v, q2, k2, v2, NROWS, 512, 512);

        // temporal branch -> hi/lo directly
        dim3 sg(LTOT, BATCH);
        k_tattn<<<sg, 256>>>(q, k, v, oohi, oolo);

        // semantic branch: fused exp-S + rowsum + PV
        {
            long tot = (long)NBH*LPAD*64;
            k_cvt_qk<<<(unsigned)((tot + 255)/256), 256>>>(q2, k2, QH, QL, KH, KL);
            k_cvt_vt<<<dim3(LPAD/32, 2, NBH), dim3(32, 8)>>>(v2, VTH, VTL);
            dim3 gs(NJT, (LTOT + 127)/128, NBH);
            k_att_s<<<gs, 256, DSMEM>>>(QH, QL, KH, KL, smk, PH, PL, psum);
            k_rsumfin<<<(NBH*LTOT + 255)/256, 256>>>(psum, rsum);
            dim3 gv(1, (LTOT + 127)/128, NBH);
            k_mgemm_att_pv<<<gv, 256, DSMEM>>>(PH, PL, VTH, VTL, rsum,
                    oohi + (size_t)NROWS*512, oolo + (size_t)NROWS*512);
        }

        // fc x2 fused
        dim3 fg(8, (NROWS + 127)/128, 2);
        k_mgemm_fc<<<fg, 256, DSMEM>>>(oohi, oolo,
                wHI + WOFF_FC + (size_t)l*2*262144, wLO + WOFF_FC + (size_t)l*2*262144,
                fcb, lo_t, lo_s, fc, fc2, NROWS, 512, 512);

        k_lncomb<<<NROWS, 256>>>(fc, fc2, x, xhi, xlo, aln_g, aln_b, lo_t, lo_s);

        // FFN
        size_t fb = (size_t)l*512;
        dim3 ng(8, (NROWS + 127)/128);
        k_mgemm<<<ng, 256, DSMEM>>>(xhi, xlo,
                wHI + WOFF_FFN1 + (size_t)l*262144, wLO + WOFF_FFN1 + (size_t)l*262144,
                nullptr, hhi, hlo, b1 + fb, NROWS, 512, 512, 1);
        k_mgemm<<<ng, 256, DSMEM>>>(hhi, hlo,
                wHI + WOFF_FFN2 + (size_t)l*262144, wLO + WOFF_FFN2 + (size_t)l*262144,
                fc, nullptr, nullptr, b2 + fb, NROWS, 512, 512, 0);
        if (l == 0)
            k_add_ln<<<NROWS, 256>>>(fc, x, fln_g + fb, fln_b + fb, x, xhi, xlo, 1e-6f);
        else
            k_add_ln<<<NROWS, 256>>>(fc, x, fln_g + fb, fln_b + fb, out, nullptr, nullptr, 1e-6f);
    }
}